// round 1
// baseline (speedup 1.0000x reference)
#include <cuda_runtime.h>
#include <math.h>
#include <stdint.h>

// ---------------- problem constants ----------------
#define BB    512
#define TT    96
#define DIN   64
#define HH    256
#define LL    4
#define EE    768
#define NCC   100
#define TP    48          // T / patch
#define FF    25          // rfft(48) -> 25 freqs
#define NF2   13          // rfft(25) -> 13 freqs
#define DHH   96          // E / heads
#define NHEADS 8

#define N_BT  ((size_t)BB * TT)   // 49152
#define N_BF  ((size_t)BB * FF)   // 12800

// ---------------- scratch buffers (device globals; no allocation) ----------------
__device__ float g_h1 [N_BT * HH];
__device__ float g_hpe[N_BT * HH];
__device__ float g_sf [N_BT * HH];
__device__ float g_h2 [N_BT * HH];
__device__ float g_hp [(size_t)BB * TP * HH];
__device__ float g_fr [N_BF * HH];
__device__ float g_C48[FF * TP];
__device__ float g_wc [1024 * EE];
__device__ float g_cb [EE];
__device__ float g_col[N_BF * 2304];
__device__ float g_wc2[2304 * EE];
__device__ float g_h  [N_BF * EE];
__device__ float g_y  [N_BF * EE];
__device__ float g_qkv[N_BF * 3 * EE];
__device__ float g_att[N_BF * EE];
__device__ float g_mid[N_BF * 4 * EE];
__device__ float g_s  [N_BF * EE];
__device__ float g_hm [(size_t)BB * EE];

// ---------------- SGEMM 128x128x8, 8x8 per-thread, fused epilogue ----------------
// C[M,N] = act( A[M,K] @ B[K,N] + bias + res )
// Requires K % 8 == 0 and N % 4 == 0 (true for all calls here).
__global__ void __launch_bounds__(256, 2)
sgemm_kernel(const float* __restrict__ A, const float* __restrict__ B,
             float* __restrict__ C, int M, int N, int K,
             const float* __restrict__ bias, const float* __restrict__ res, int act)
{
    __shared__ float As[8][128];
    __shared__ float Bs[8][128];

    const int tid  = threadIdx.x;
    const int row0 = blockIdx.y * 128;
    const int col0 = blockIdx.x * 128;

    const int tx = tid & 15;        // 0..15 -> 8 cols each
    const int ty = tid >> 4;        // 0..15 -> 8 rows each

    const int arow = tid >> 1;      // 0..127
    const int acol = (tid & 1) * 4; // 0 or 4
    const int brow = tid >> 5;      // 0..7
    const int bcol = (tid & 31) * 4;

    float acc[8][8];
#pragma unroll
    for (int i = 0; i < 8; i++)
#pragma unroll
        for (int j = 0; j < 8; j++) acc[i][j] = 0.f;

    const int gar = row0 + arow;
    const int gbc = col0 + bcol;
    const bool aok = (gar < M);
    const bool bok = (gbc < N);   // N % 4 == 0 so float4 never straddles the edge

    for (int k0 = 0; k0 < K; k0 += 8) {
        float4 av = make_float4(0.f, 0.f, 0.f, 0.f);
        if (aok) av = *reinterpret_cast<const float4*>(&A[(size_t)gar * K + k0 + acol]);
        As[acol + 0][arow] = av.x;
        As[acol + 1][arow] = av.y;
        As[acol + 2][arow] = av.z;
        As[acol + 3][arow] = av.w;

        float4 bv = make_float4(0.f, 0.f, 0.f, 0.f);
        if (bok) bv = *reinterpret_cast<const float4*>(&B[(size_t)(k0 + brow) * N + gbc]);
        *reinterpret_cast<float4*>(&Bs[brow][bcol]) = bv;

        __syncthreads();

#pragma unroll
        for (int kk = 0; kk < 8; kk++) {
            float4 ra0 = *reinterpret_cast<const float4*>(&As[kk][ty * 8 + 0]);
            float4 ra1 = *reinterpret_cast<const float4*>(&As[kk][ty * 8 + 4]);
            float4 rb0 = *reinterpret_cast<const float4*>(&Bs[kk][tx * 8 + 0]);
            float4 rb1 = *reinterpret_cast<const float4*>(&Bs[kk][tx * 8 + 4]);
            float ra[8] = {ra0.x, ra0.y, ra0.z, ra0.w, ra1.x, ra1.y, ra1.z, ra1.w};
            float rb[8] = {rb0.x, rb0.y, rb0.z, rb0.w, rb1.x, rb1.y, rb1.z, rb1.w};
#pragma unroll
            for (int i = 0; i < 8; i++)
#pragma unroll
                for (int j = 0; j < 8; j++)
                    acc[i][j] = fmaf(ra[i], rb[j], acc[i][j]);
        }
        __syncthreads();
    }

#pragma unroll
    for (int i = 0; i < 8; i++) {
        const int r = row0 + ty * 8 + i;
        if (r >= M) continue;
#pragma unroll
        for (int j = 0; j < 8; j++) {
            const int c = col0 + tx * 8 + j;
            if (c >= N) continue;
            float v = acc[i][j];
            if (bias) v += bias[c];
            if (res)  v += res[(size_t)r * N + c];
            if (act)  v = 0.5f * v * (1.0f + erff(v * 0.70710678118654752f));
            C[(size_t)r * N + c] = v;
        }
    }
}

// ---------------- small kernels ----------------
__global__ void init_c48_kernel(float* __restrict__ C48) {
    for (int i = threadIdx.x; i < FF * TP; i += blockDim.x) {
        int k = i / TP, t = i % TP;
        int m = (k * t) % TP;
        C48[i] = cospif(2.0f * (float)m / (float)TP);
    }
}

// h1 -> hpe = h1 + pe[t], sf = diff(hpe, prepend first)
__global__ void pe_diff_kernel(const float* __restrict__ h1, const float* __restrict__ pe,
                               float* __restrict__ hpe, float* __restrict__ sf)
{
    size_t idx = (size_t)blockIdx.x * blockDim.x + threadIdx.x;
    const size_t total = N_BT * HH;
    if (idx >= total) return;
    int c = (int)(idx % HH);
    size_t r = idx / HH;
    int t = (int)(r % TT);
    float cur = h1[idx] + pe[(size_t)t * HH + c];
    hpe[idx] = cur;
    float prev = (t == 0) ? cur : (h1[idx - HH] + pe[(size_t)(t - 1) * HH + c]);
    sf[idx] = cur - prev;
}

// real part of rfft over T=48 : f[b,k,c] = sum_t hp[b,t,c]*cos(2*pi*k*t/48)
__global__ void __launch_bounds__(256) dft48_kernel(const float* __restrict__ hp,
                                                    float* __restrict__ out,
                                                    const float* __restrict__ C48)
{
    __shared__ float sC[FF * TP];
    int b = blockIdx.x;
    for (int i = threadIdx.x; i < FF * TP; i += 256) sC[i] = C48[i];
    float r[TP];
    const float* base = hp + (size_t)b * TP * HH + threadIdx.x;
#pragma unroll
    for (int t = 0; t < TP; t++) r[t] = base[(size_t)t * HH];
    __syncthreads();
    float* ob = out + (size_t)b * FF * HH + threadIdx.x;
    for (int k = 0; k < FF; k++) {
        float acc = 0.f;
#pragma unroll
        for (int t = 0; t < TP; t++) acc = fmaf(r[t], sC[k * TP + t], acc);
        ob[(size_t)k * HH] = acc;
    }
}

// assemble multiscale-conv weights into [1024, 768] (rows: dpos*256+i, dpos: offset -1,0,1,2)
__global__ void assemble_conv_w(const float* __restrict__ w1, const float* __restrict__ w2,
                                const float* __restrict__ w4, const float* __restrict__ b1,
                                const float* __restrict__ b2, const float* __restrict__ b4,
                                float* __restrict__ wc, float* __restrict__ cb)
{
    int idx = blockIdx.x * blockDim.x + threadIdx.x;
    if (idx < EE) cb[idx] = (idx < 256) ? b1[idx] : (idx < 512 ? b2[idx - 256] : b4[idx - 512]);
    if (idx >= 1024 * EE) return;
    int o = idx % EE;
    int k = idx / EE;
    int i = k % 256, d = k / 256;     // d: 0->delta -1, 1->0, 2->+1, 3->+2
    float v = 0.f;
    if (o < 256)      { if (d == 1) v = w1[o * 256 + i]; }
    else if (o < 512) { int oo = o - 256; int j = d - 1; if (j == 0 || j == 1) v = w2[oo * 512 + i * 2 + j]; }
    else              { int oo = o - 512; v = w4[oo * 1024 + i * 4 + d]; }
    wc[idx] = v;
}

__global__ void im2col_conv(const float* __restrict__ f, float* __restrict__ col) {
    size_t idx = (size_t)blockIdx.x * blockDim.x + threadIdx.x;
    const size_t total = N_BF * 1024;
    if (idx >= total) return;
    int kk = (int)(idx % 1024);
    size_t row = idx / 1024;
    int i = kk % 256, d = kk / 256;
    int fq = (int)(row % FF);
    size_t b = row / FF;
    int src = fq + d - 1;
    col[idx] = (src >= 0 && src < FF) ? f[((size_t)b * FF + src) * HH + i] : 0.f;
}

__global__ void assemble_ssm_w(const float* __restrict__ w, float* __restrict__ wc) {
    int idx = blockIdx.x * blockDim.x + threadIdx.x;
    if (idx >= 2304 * EE) return;
    int o = idx % EE;
    int k = idx / EE;
    int i = k % EE, j = k / EE;   // j in 0..2
    wc[idx] = w[(size_t)o * (EE * 3) + i * 3 + j];
}

__global__ void im2col_ssm(const float* __restrict__ h, float* __restrict__ col) {
    size_t idx = (size_t)blockIdx.x * blockDim.x + threadIdx.x;
    const size_t total = N_BF * 2304;
    if (idx >= total) return;
    int kk = (int)(idx % 2304);
    size_t row = idx / 2304;
    int i = kk % EE, j = kk / EE;
    int fq = (int)(row % FF);
    size_t b = row / FF;
    int src = fq + j - 1;
    col[idx] = (src >= 0 && src < FF) ? h[((size_t)b * FF + src) * EE + i] : 0.f;
}

// layernorm over C: y = (x[+add] - mean) * rsqrt(var+eps) * g + b   (in-place safe)
__global__ void __launch_bounds__(256) ln_kernel(const float* __restrict__ x,
                                                 const float* __restrict__ add,
                                                 const float* __restrict__ g,
                                                 const float* __restrict__ bta,
                                                 float* __restrict__ y, int C)
{
    int row = blockIdx.x;
    const float* xr = x + (size_t)row * C;
    const float* ar = add ? add + (size_t)row * C : nullptr;
    float s = 0.f, q = 0.f;
    for (int c = threadIdx.x; c < C; c += 256) {
        float v = xr[c] + (ar ? ar[c] : 0.f);
        s += v; q += v * v;
    }
#pragma unroll
    for (int o = 16; o; o >>= 1) {
        s += __shfl_xor_sync(~0u, s, o);
        q += __shfl_xor_sync(~0u, q, o);
    }
    __shared__ float ss[8], sq[8];
    int w = threadIdx.x >> 5, l = threadIdx.x & 31;
    if (l == 0) { ss[w] = s; sq[w] = q; }
    __syncthreads();
    if (threadIdx.x == 0) {
        float ts = 0.f, tq = 0.f;
        for (int i = 0; i < 8; i++) { ts += ss[i]; tq += sq[i]; }
        ss[0] = ts; sq[0] = tq;
    }
    __syncthreads();
    float mean = ss[0] / C;
    float var  = sq[0] / C - mean * mean;
    float inv  = rsqrtf(var + 1e-5f);
    for (int c = threadIdx.x; c < C; c += 256) {
        float v = xr[c] + (ar ? ar[c] : 0.f);
        y[(size_t)row * C + c] = (v - mean) * inv * g[c] + bta[c];
    }
}

// fourier attention: one block per (batch, head)
// attn[f] = sum_{t,s} G[t,s] cos(w f (t-s)) / sqrt(dh);   softmax over 13 freqs;
// out = circulant(k_time) @ v  with k_time = irfft(attn, n=25)
__global__ void __launch_bounds__(256) attn_kernel(const float* __restrict__ qkv,
                                                   float* __restrict__ out)
{
    __shared__ float sq_[FF][DHH], sk_[FF][DHH], sv_[FF][DHH];
    __shared__ float G[FF][FF];
    __shared__ float ctab[FF];
    __shared__ float sa[NF2];
    __shared__ float kt[FF];

    int bh = blockIdx.x;
    int b = bh >> 3, hh = bh & 7;
    int tid = threadIdx.x;
    const float* base = qkv + ((size_t)b * FF) * (3 * EE) + hh * DHH;

    for (int idx = tid; idx < FF * DHH; idx += 256) {
        int t = idx / DHH, d = idx % DHH;
        size_t off = (size_t)t * (3 * EE) + d;
        sq_[t][d] = base[off];
        sk_[t][d] = base[off + EE];
        sv_[t][d] = base[off + 2 * EE];
    }
    if (tid < FF) ctab[tid] = cospif(2.0f * (float)tid / 25.0f);
    __syncthreads();

    for (int e = tid; e < FF * FF; e += 256) {
        int t = e / FF, s2 = e % FF;
        float acc = 0.f;
#pragma unroll 8
        for (int d = 0; d < DHH; d++) acc = fmaf(sq_[t][d], sk_[s2][d], acc);
        G[t][s2] = acc;
    }
    __syncthreads();

    if (tid < NF2) {
        float acc = 0.f;
        for (int t = 0; t < FF; t++)
            for (int s2 = 0; s2 < FF; s2++)
                acc = fmaf(G[t][s2], ctab[(tid * (t - s2 + FF)) % FF], acc);
        sa[tid] = acc * 0.10206207261596575f;  // 1/sqrt(96)
    }
    __syncthreads();

    if (tid == 0) {
        float mx = sa[0];
        for (int f = 1; f < NF2; f++) mx = fmaxf(mx, sa[f]);
        float e_[NF2], sum = 0.f;
        for (int f = 0; f < NF2; f++) { e_[f] = expf(sa[f] - mx); sum += e_[f]; }
        float inv = 1.0f / sum;
        for (int f = 0; f < NF2; f++) sa[f] = e_[f] * inv;
    }
    __syncthreads();

    if (tid < FF) {
        float acc = sa[0];
        for (int f = 1; f < NF2; f++) acc = fmaf(2.0f * sa[f], ctab[(f * tid) % FF], acc);
        kt[tid] = acc * 0.04f;  // 1/25
    }
    __syncthreads();

    float* obase = out + ((size_t)b * FF) * EE + hh * DHH;
    for (int idx = tid; idx < FF * DHH; idx += 256) {
        int t = idx / DHH, d = idx % DHH;
        float acc = 0.f;
#pragma unroll
        for (int s2 = 0; s2 < FF; s2++)
            acc = fmaf(kt[(t - s2 + FF) % FF], sv_[s2][d], acc);
        obase[(size_t)t * EE + d] = acc;
    }
}

__global__ void mean_kernel(const float* __restrict__ h, float* __restrict__ hm) {
    int b = blockIdx.x;
    int c = threadIdx.x;  // 768 threads
    float acc = 0.f;
#pragma unroll
    for (int f = 0; f < FF; f++) acc += h[((size_t)b * FF + f) * EE + c];
    hm[(size_t)b * EE + c] = acc * 0.04f;
}

// ---------------- launch ----------------
static inline void gemm_launch(const float* A, const float* B, float* C,
                               int M, int N, int K,
                               const float* bias, const float* res, int act)
{
    dim3 grid((N + 127) / 128, (M + 127) / 128);
    sgemm_kernel<<<grid, 256>>>(A, B, C, M, N, K, bias, res, act);
}

extern "C" void kernel_launch(void* const* d_in, const int* in_sizes, int n_in,
                              void* d_out, int out_size)
{
    const float* x       = (const float*)d_in[0];
    const float* W_in    = (const float*)d_in[1];
    const float* b_in    = (const float*)d_in[2];
    const float* pe      = (const float*)d_in[3];
    const float* W_shape = (const float*)d_in[4];
    const float* b_shape = (const float*)d_in[5];
    const float* W_patch = (const float*)d_in[6];
    const float* b_patch = (const float*)d_in[7];
    const float* cw1     = (const float*)d_in[8];
    const float* cb1     = (const float*)d_in[9];
    const float* cw2     = (const float*)d_in[10];
    const float* cb2     = (const float*)d_in[11];
    const float* cw4     = (const float*)d_in[12];
    const float* cb4     = (const float*)d_in[13];
    const float* ln1g    = (const float*)d_in[14];
    const float* ln1b    = (const float*)d_in[15];
    const float* Wqkv    = (const float*)d_in[16];
    const float* Wo      = (const float*)d_in[17];
    const float* bo      = (const float*)d_in[18];
    const float* ln2g    = (const float*)d_in[19];
    const float* ln2b    = (const float*)d_in[20];
    const float* Wf1     = (const float*)d_in[21];
    const float* bf1     = (const float*)d_in[22];
    const float* Wf2     = (const float*)d_in[23];
    const float* bf2     = (const float*)d_in[24];
    const float* ssmw    = (const float*)d_in[25];
    const float* ssmb    = (const float*)d_in[26];
    const float* ssmg    = (const float*)d_in[27];
    const float* ssmbn   = (const float*)d_in[28];
    const float* W_out   = (const float*)d_in[29];
    const float* b_out   = (const float*)d_in[30];
    float* out = (float*)d_out;

    float *h1, *hpe, *sf, *h2, *hp, *fr, *C48, *wc, *cb, *col, *wc2;
    float *h, *y, *qkv, *att, *mid, *s, *hm;
    cudaGetSymbolAddress((void**)&h1,  g_h1);
    cudaGetSymbolAddress((void**)&hpe, g_hpe);
    cudaGetSymbolAddress((void**)&sf,  g_sf);
    cudaGetSymbolAddress((void**)&h2,  g_h2);
    cudaGetSymbolAddress((void**)&hp,  g_hp);
    cudaGetSymbolAddress((void**)&fr,  g_fr);
    cudaGetSymbolAddress((void**)&C48, g_C48);
    cudaGetSymbolAddress((void**)&wc,  g_wc);
    cudaGetSymbolAddress((void**)&cb,  g_cb);
    cudaGetSymbolAddress((void**)&col, g_col);
    cudaGetSymbolAddress((void**)&wc2, g_wc2);
    cudaGetSymbolAddress((void**)&h,   g_h);
    cudaGetSymbolAddress((void**)&y,   g_y);
    cudaGetSymbolAddress((void**)&qkv, g_qkv);
    cudaGetSymbolAddress((void**)&att, g_att);
    cudaGetSymbolAddress((void**)&mid, g_mid);
    cudaGetSymbolAddress((void**)&s,   g_s);
    cudaGetSymbolAddress((void**)&hm,  g_hm);

    // tables
    init_c48_kernel<<<1, 256>>>(C48);

    // input embedding + positional + shape-aware embedding
    gemm_launch(x, W_in, h1, BB * TT, HH, DIN, b_in, nullptr, 0);
    {
        size_t tot = N_BT * HH;
        pe_diff_kernel<<<(unsigned)((tot + 255) / 256), 256>>>(h1, pe, hpe, sf);
    }
    gemm_launch(sf, W_shape, h2, BB * TT, HH, HH, b_shape, hpe, 0);

    // patch embedding: view h2 as [B*48, 512]
    gemm_launch(h2, W_patch, hp, BB * TP, HH, 2 * HH, b_patch, nullptr, 0);

    // rfft real over T=48
    dft48_kernel<<<BB, 256>>>(hp, fr, C48);

    // multiscale conv via im2col + GEMM
    assemble_conv_w<<<(1024 * EE + 255) / 256, 256>>>(cw1, cw2, cw4, cb1, cb2, cb4, wc, cb);
    {
        size_t tot = N_BF * 1024;
        im2col_conv<<<(unsigned)((tot + 255) / 256), 256>>>(fr, col);
    }
    gemm_launch(col, wc, h, (int)N_BF, EE, 1024, cb, nullptr, 0);

    // transformer layers
    for (int i = 0; i < LL; i++) {
        ln_kernel<<<(unsigned)N_BF, 256>>>(h, nullptr, ln1g + (size_t)i * EE, ln1b + (size_t)i * EE, y, EE);
        gemm_launch(y, Wqkv + (size_t)i * EE * 3 * EE, qkv, (int)N_BF, 3 * EE, EE, nullptr, nullptr, 0);
        attn_kernel<<<BB * NHEADS, 256>>>(qkv, att);
        gemm_launch(att, Wo + (size_t)i * EE * EE, h, (int)N_BF, EE, EE, bo + (size_t)i * EE, h, 0);
        ln_kernel<<<(unsigned)N_BF, 256>>>(h, nullptr, ln2g + (size_t)i * EE, ln2b + (size_t)i * EE, y, EE);
        gemm_launch(y, Wf1 + (size_t)i * EE * 4 * EE, mid, (int)N_BF, 4 * EE, EE, bf1 + (size_t)i * 4 * EE, nullptr, 1);
        gemm_launch(mid, Wf2 + (size_t)i * 4 * EE * EE, h, (int)N_BF, EE, 4 * EE, bf2 + (size_t)i * EE, h, 0);
    }

    // SSM conv (k=3, full) via im2col + GEMM, then LN(h + s)
    assemble_ssm_w<<<(2304 * EE + 255) / 256, 256>>>(ssmw, wc2);
    {
        size_t tot = N_BF * 2304;
        im2col_ssm<<<(unsigned)((tot + 255) / 256), 256>>>(h, col);
    }
    gemm_launch(col, wc2, s, (int)N_BF, EE, 3 * EE, ssmb, nullptr, 0);
    ln_kernel<<<(unsigned)N_BF, 256>>>(h, s, ssmg, ssmbn, h, EE);

    // mean over time + classifier
    mean_kernel<<<BB, EE>>>(h, hm);
    gemm_launch(hm, W_out, out, BB, NCC, EE, b_out, nullptr, 0);
}

// round 4
// speedup vs baseline: 1.6028x; 1.6028x over previous
#include <cuda_runtime.h>
#include <cuda_bf16.h>
#include <math.h>
#include <stdint.h>

// ---------------- problem constants ----------------
#define BB    512
#define TT    96
#define DIN   64
#define HH    256
#define LL    4
#define EE    768
#define NCC   100
#define TP    48
#define FF    25
#define NF2   13
#define DHH   96
#define NHEADS 8

#define N_BT  ((size_t)BB * TT)   // 49152
#define N_BF  ((size_t)BB * FF)   // 12800

typedef __nv_bfloat16 bf16;

// ---------------- scratch buffers ----------------
__device__ __align__(16) float g_h1 [N_BT * HH];
__device__ __align__(16) float g_hpe[N_BT * HH];
__device__ __align__(16) float g_sf [N_BT * HH];
__device__ __align__(16) float g_h2 [N_BT * HH];
__device__ __align__(16) float g_hp [(size_t)BB * TP * HH];
__device__ __align__(16) float g_fr [N_BF * HH];
__device__ __align__(16) float g_C48[FF * TP];
__device__ __align__(16) float g_cb [EE];
__device__ __align__(16) float g_col[N_BF * 2304];
__device__ __align__(16) float g_h  [N_BF * EE];
__device__ __align__(16) float g_y  [N_BF * EE];
__device__ __align__(16) float g_qkv[N_BF * 3 * EE];
__device__ __align__(16) float g_att[N_BF * EE];
__device__ __align__(16) float g_mid[N_BF * 4 * EE];
__device__ __align__(16) float g_s  [N_BF * EE];
__device__ __align__(16) float g_hm [(size_t)BB * EE];

// transposed + split weights: [N][K] bf16 hi/lo
__device__ __align__(16) bf16 g_tWin_h [256 * 64],       g_tWin_l [256 * 64];
__device__ __align__(16) bf16 g_tWsh_h [256 * 256],      g_tWsh_l [256 * 256];
__device__ __align__(16) bf16 g_tWpa_h [256 * 512],      g_tWpa_l [256 * 512];
__device__ __align__(16) bf16 g_tWc_h  [768 * 1024],     g_tWc_l  [768 * 1024];
__device__ __align__(16) bf16 g_tWqkv_h[LL * 2304 * 768],g_tWqkv_l[LL * 2304 * 768];
__device__ __align__(16) bf16 g_tWo_h  [LL * 768 * 768], g_tWo_l  [LL * 768 * 768];
__device__ __align__(16) bf16 g_tWf1_h [LL * 3072 * 768],g_tWf1_l [LL * 3072 * 768];
__device__ __align__(16) bf16 g_tWf2_h [LL * 768 * 3072],g_tWf2_l [LL * 768 * 3072];
__device__ __align__(16) bf16 g_tWc2_h [768 * 2304],     g_tWc2_l [768 * 2304];

// ---------------- helpers ----------------
__device__ __forceinline__ uint32_t smem_u32(const void* p) {
    uint32_t a;
    asm("{ .reg .u64 t; cvta.to.shared.u64 t, %1; cvt.u32.u64 %0, t; }" : "=r"(a) : "l"(p));
    return a;
}
__device__ __forceinline__ uint32_t bfpack(bf16 a, bf16 b) {
    __nv_bfloat162 t; t.x = a; t.y = b;
    return *reinterpret_cast<uint32_t*>(&t);
}

// swizzle: 64B rows, xor 16B-chunk bits [4:5] with row low bits (addr bits [6:7])
#define ASWZ(x) ((x) ^ (((x) >> 2) & 0x30))

#define LDMX4(r, a) \
    asm volatile("ldmatrix.sync.aligned.m8n8.x4.shared.b16 {%0,%1,%2,%3}, [%4];" \
        : "=r"((r)[0]), "=r"((r)[1]), "=r"((r)[2]), "=r"((r)[3]) : "r"(a))
#define LDMX2(r, a) \
    asm volatile("ldmatrix.sync.aligned.m8n8.x2.shared.b16 {%0,%1}, [%2];" \
        : "=r"((r)[0]), "=r"((r)[1]) : "r"(a))
#define MMA16816(d, A, Bf) \
    asm volatile("mma.sync.aligned.m16n8k16.row.col.f32.bf16.bf16.f32 " \
        "{%0,%1,%2,%3}, {%4,%5,%6,%7}, {%8,%9}, {%0,%1,%2,%3};" \
        : "+f"((d)[0]), "+f"((d)[1]), "+f"((d)[2]), "+f"((d)[3]) \
        : "r"((A)[0]), "r"((A)[1]), "r"((A)[2]), "r"((A)[3]), "r"((Bf)[0]), "r"((Bf)[1]))

// ---------------- HMMA GEMM: C[M,N] = act(A f32 @ B^T(split bf16) + bias + res)
// M%128==0, N%128==0, K%32==0
#define GSM_BUF   32768
#define GSM_AHI   0
#define GSM_ALO   8192
#define GSM_BHI   16384
#define GSM_BLO   24576
#define GSM_TOTAL 69632

__global__ void __launch_bounds__(256, 1)
gemm_mma_kernel(const float* __restrict__ A,
                const bf16* __restrict__ Bhi, const bf16* __restrict__ Blo,
                float* __restrict__ C, int M, int N, int K,
                const float* __restrict__ bias, const float* __restrict__ res, int act)
{
    extern __shared__ char smem[];
    const uint32_t sb = smem_u32(smem);
    const int tid  = threadIdx.x;
    const int lane = tid & 31;
    const int wid  = tid >> 5;
    const int wm   = wid & 1;       // 2 warp-rows  (64 rows each)
    const int wn   = wid >> 1;      // 4 warp-cols  (32 cols each)
    const int m0 = blockIdx.y * 128;
    const int n0 = blockIdx.x * 128;

    const int aRow  = tid >> 1;            // 0..127
    const int aQ0   = (tid & 1) * 4;       // quad base
    const int bRow  = tid >> 1;            // 0..127 (n)
    const int bC0   = (tid & 1) * 2;       // 16B-chunk base

    float acc[4][4][4];
#pragma unroll
    for (int i = 0; i < 4; i++)
#pragma unroll
        for (int j = 0; j < 4; j++)
#pragma unroll
            for (int e = 0; e < 4; e++) acc[i][j][e] = 0.f;

    const int nk = K >> 5;

    // UNswizzled per-lane fragment byte bases (swizzle applied per-use, AFTER adding kb)
    const uint32_t aBase = (uint32_t)(wm * 64 + (lane & 15)) * 64u + (uint32_t)(lane >> 4) * 16u;
    const uint32_t bBase = (uint32_t)(wn * 32 + (lane & 7)) * 64u + (uint32_t)((lane >> 3) & 1) * 16u;

    float4 av[4];
    uint4 bhv[2], blv[2];

    // prologue: load chunk 0
    {
        const float* Ab = A + (size_t)(m0 + aRow) * K;
#pragma unroll
        for (int p = 0; p < 4; p++)
            av[p] = *reinterpret_cast<const float4*>(Ab + (aQ0 + p) * 4);
        const bf16* Bh = Bhi + (size_t)(n0 + bRow) * K;
        const bf16* Bl = Blo + (size_t)(n0 + bRow) * K;
#pragma unroll
        for (int p = 0; p < 2; p++) {
            bhv[p] = *reinterpret_cast<const uint4*>(Bh + (bC0 + p) * 8);
            blv[p] = *reinterpret_cast<const uint4*>(Bl + (bC0 + p) * 8);
        }
    }
    // STS chunk 0 into buf 0
    {
        char* bufc = smem;
#pragma unroll
        for (int p = 0; p < 4; p++) {
            uint32_t off = ASWZ((uint32_t)aRow * 64u + (uint32_t)(aQ0 + p) * 8u);
            float4 v = av[p];
            bf16 h0 = __float2bfloat16(v.x), h1 = __float2bfloat16(v.y);
            bf16 h2 = __float2bfloat16(v.z), h3 = __float2bfloat16(v.w);
            bf16 l0 = __float2bfloat16(v.x - __bfloat162float(h0));
            bf16 l1 = __float2bfloat16(v.y - __bfloat162float(h1));
            bf16 l2 = __float2bfloat16(v.z - __bfloat162float(h2));
            bf16 l3 = __float2bfloat16(v.w - __bfloat162float(h3));
            *reinterpret_cast<uint2*>(bufc + GSM_AHI + off) = make_uint2(bfpack(h0, h1), bfpack(h2, h3));
            *reinterpret_cast<uint2*>(bufc + GSM_ALO + off) = make_uint2(bfpack(l0, l1), bfpack(l2, l3));
        }
#pragma unroll
        for (int p = 0; p < 2; p++) {
            uint32_t off = ASWZ((uint32_t)bRow * 64u + (uint32_t)(bC0 + p) * 16u);
            *reinterpret_cast<uint4*>(bufc + GSM_BHI + off) = bhv[p];
            *reinterpret_cast<uint4*>(bufc + GSM_BLO + off) = blv[p];
        }
    }
    __syncthreads();

    for (int kc = 0; kc < nk; kc++) {
        const uint32_t bufo = (uint32_t)(kc & 1) * GSM_BUF;
        // prefetch next chunk
        if (kc + 1 < nk) {
            const float* Ab = A + (size_t)(m0 + aRow) * K + (kc + 1) * 32;
#pragma unroll
            for (int p = 0; p < 4; p++)
                av[p] = *reinterpret_cast<const float4*>(Ab + (aQ0 + p) * 4);
            const bf16* Bh = Bhi + (size_t)(n0 + bRow) * K + (kc + 1) * 32;
            const bf16* Bl = Blo + (size_t)(n0 + bRow) * K + (kc + 1) * 32;
#pragma unroll
            for (int p = 0; p < 2; p++) {
                bhv[p] = *reinterpret_cast<const uint4*>(Bh + (bC0 + p) * 8);
                blv[p] = *reinterpret_cast<const uint4*>(Bl + (bC0 + p) * 8);
            }
        }
        // compute current chunk: two k16 steps
#pragma unroll
        for (int kk = 0; kk < 2; kk++) {
            const uint32_t kb = (uint32_t)kk * 32u;   // bytes within 64B row
            // swizzle applied AFTER adding kb (no carry: lane koff 0/16 + kb 0/32 < 64);
            // mi*1024 / ni*512 touch bits >=9 only -> commute with the xor
            const uint32_t aSw = ASWZ(aBase + kb);
            const uint32_t bSw = ASWZ(bBase + kb);
            uint32_t ah[4][4], al[4][4], bh[4][2], bl[4][2];
#pragma unroll
            for (int mi = 0; mi < 4; mi++) {
                uint32_t a_addr = sb + bufo + GSM_AHI + aSw + (uint32_t)(mi * 1024);
                LDMX4(ah[mi], a_addr);
                LDMX4(al[mi], a_addr + (GSM_ALO - GSM_AHI));
            }
#pragma unroll
            for (int ni = 0; ni < 4; ni++) {
                uint32_t b_addr = sb + bufo + GSM_BHI + bSw + (uint32_t)(ni * 512);
                LDMX2(bh[ni], b_addr);
                LDMX2(bl[ni], b_addr + (GSM_BLO - GSM_BHI));
            }
#pragma unroll
            for (int mi = 0; mi < 4; mi++)
#pragma unroll
                for (int ni = 0; ni < 4; ni++) {
                    MMA16816(acc[mi][ni], ah[mi], bh[ni]);
                    MMA16816(acc[mi][ni], ah[mi], bl[ni]);
                    MMA16816(acc[mi][ni], al[mi], bh[ni]);
                }
        }
        // store next chunk
        if (kc + 1 < nk) {
            char* bufc = smem + ((kc + 1) & 1) * GSM_BUF;
#pragma unroll
            for (int p = 0; p < 4; p++) {
                uint32_t off = ASWZ((uint32_t)aRow * 64u + (uint32_t)(aQ0 + p) * 8u);
                float4 v = av[p];
                bf16 h0 = __float2bfloat16(v.x), h1 = __float2bfloat16(v.y);
                bf16 h2 = __float2bfloat16(v.z), h3 = __float2bfloat16(v.w);
                bf16 l0 = __float2bfloat16(v.x - __bfloat162float(h0));
                bf16 l1 = __float2bfloat16(v.y - __bfloat162float(h1));
                bf16 l2 = __float2bfloat16(v.z - __bfloat162float(h2));
                bf16 l3 = __float2bfloat16(v.w - __bfloat162float(h3));
                *reinterpret_cast<uint2*>(bufc + GSM_AHI + off) = make_uint2(bfpack(h0, h1), bfpack(h2, h3));
                *reinterpret_cast<uint2*>(bufc + GSM_ALO + off) = make_uint2(bfpack(l0, l1), bfpack(l2, l3));
            }
#pragma unroll
            for (int p = 0; p < 2; p++) {
                uint32_t off = ASWZ((uint32_t)bRow * 64u + (uint32_t)(bC0 + p) * 16u);
                *reinterpret_cast<uint4*>(bufc + GSM_BHI + off) = bhv[p];
                *reinterpret_cast<uint4*>(bufc + GSM_BLO + off) = blv[p];
            }
        }
        __syncthreads();
    }

    // epilogue: stage accum in smem (stride 132), then coalesced gmem store
    float* stg = reinterpret_cast<float*>(smem);
#pragma unroll
    for (int mi = 0; mi < 4; mi++) {
#pragma unroll
        for (int ni = 0; ni < 4; ni++) {
            int r = wm * 64 + mi * 16 + (lane >> 2);
            int c = wn * 32 + ni * 8 + (lane & 3) * 2;
            stg[r * 132 + c]           = acc[mi][ni][0];
            stg[r * 132 + c + 1]       = acc[mi][ni][1];
            stg[(r + 8) * 132 + c]     = acc[mi][ni][2];
            stg[(r + 8) * 132 + c + 1] = acc[mi][ni][3];
        }
    }
    __syncthreads();
#pragma unroll 4
    for (int it = 0; it < 64; it++) {
        int idx = it * 256 + tid;
        int r = idx >> 7, c = idx & 127;
        float v = stg[r * 132 + c];
        int gn = n0 + c;
        size_t gr = (size_t)(m0 + r);
        if (bias) v += bias[gn];
        if (res)  v += res[gr * N + gn];
        if (act)  v = 0.5f * v * (1.0f + erff(v * 0.70710678118654752f));
        C[gr * N + gn] = v;
    }
}

// ---------------- fallback f32 SGEMM (classifier only) ----------------
__global__ void __launch_bounds__(256, 2)
sgemm_kernel(const float* __restrict__ A, const float* __restrict__ B,
             float* __restrict__ C, int M, int N, int K,
             const float* __restrict__ bias)
{
    __shared__ float As[8][128];
    __shared__ float Bs[8][128];
    const int tid = threadIdx.x;
    const int row0 = blockIdx.y * 128, col0 = blockIdx.x * 128;
    const int tx = tid & 15, ty = tid >> 4;
    const int arow = tid >> 1, acol = (tid & 1) * 4;
    const int brow = tid >> 5, bcol = (tid & 31) * 4;
    float acc[8][8];
#pragma unroll
    for (int i = 0; i < 8; i++)
#pragma unroll
        for (int j = 0; j < 8; j++) acc[i][j] = 0.f;
    const int gar = row0 + arow, gbc = col0 + bcol;
    const bool aok = (gar < M), bok = (gbc < N);
    for (int k0 = 0; k0 < K; k0 += 8) {
        float4 avv = make_float4(0, 0, 0, 0);
        if (aok) avv = *reinterpret_cast<const float4*>(&A[(size_t)gar * K + k0 + acol]);
        As[acol + 0][arow] = avv.x; As[acol + 1][arow] = avv.y;
        As[acol + 2][arow] = avv.z; As[acol + 3][arow] = avv.w;
        float4 bv = make_float4(0, 0, 0, 0);
        if (bok) bv = *reinterpret_cast<const float4*>(&B[(size_t)(k0 + brow) * N + gbc]);
        *reinterpret_cast<float4*>(&Bs[brow][bcol]) = bv;
        __syncthreads();
#pragma unroll
        for (int kk = 0; kk < 8; kk++) {
            float4 ra0 = *reinterpret_cast<const float4*>(&As[kk][ty * 8 + 0]);
            float4 ra1 = *reinterpret_cast<const float4*>(&As[kk][ty * 8 + 4]);
            float4 rb0 = *reinterpret_cast<const float4*>(&Bs[kk][tx * 8 + 0]);
            float4 rb1 = *reinterpret_cast<const float4*>(&Bs[kk][tx * 8 + 4]);
            float ra[8] = {ra0.x, ra0.y, ra0.z, ra0.w, ra1.x, ra1.y, ra1.z, ra1.w};
            float rb[8] = {rb0.x, rb0.y, rb0.z, rb0.w, rb1.x, rb1.y, rb1.z, rb1.w};
#pragma unroll
            for (int i = 0; i < 8; i++)
#pragma unroll
                for (int j = 0; j < 8; j++) acc[i][j] = fmaf(ra[i], rb[j], acc[i][j]);
        }
        __syncthreads();
    }
#pragma unroll
    for (int i = 0; i < 8; i++) {
        const int r = row0 + ty * 8 + i;
        if (r >= M) continue;
#pragma unroll
        for (int j = 0; j < 8; j++) {
            const int c = col0 + tx * 8 + j;
            if (c >= N) continue;
            float v = acc[i][j];
            if (bias) v += bias[c];
            C[(size_t)r * N + c] = v;
        }
    }
}

// ---------------- weight transpose + split ----------------
__global__ void tsplit_kernel(const float* __restrict__ W, bf16* __restrict__ hi,
                              bf16* __restrict__ lo, int K, int N)
{
    __shared__ float t[32][33];
    int k0 = blockIdx.y * 32, n0 = blockIdx.x * 32;
    int tx = threadIdx.x, ty = threadIdx.y;
#pragma unroll
    for (int r = 0; r < 4; r++) {
        int k = k0 + ty + r * 8;
        t[ty + r * 8][tx] = (k < K && n0 + tx < N) ? W[(size_t)k * N + n0 + tx] : 0.f;
    }
    __syncthreads();
#pragma unroll
    for (int r = 0; r < 4; r++) {
        int n = n0 + ty + r * 8, k = k0 + tx;
        if (n < N && k < K) {
            float v = t[tx][ty + r * 8];
            bf16 h = __float2bfloat16(v);
            hi[(size_t)n * K + k] = h;
            lo[(size_t)n * K + k] = __float2bfloat16(v - __bfloat162float(h));
        }
    }
}

__global__ void assemble_conv_wT(const float* __restrict__ w1, const float* __restrict__ w2,
                                 const float* __restrict__ w4, const float* __restrict__ b1,
                                 const float* __restrict__ b2, const float* __restrict__ b4,
                                 bf16* __restrict__ hi, bf16* __restrict__ lo,
                                 float* __restrict__ cb)
{
    int idx = blockIdx.x * blockDim.x + threadIdx.x;
    if (idx < EE) cb[idx] = (idx < 256) ? b1[idx] : (idx < 512 ? b2[idx - 256] : b4[idx - 512]);
    if (idx >= 768 * 1024) return;
    int n = idx / 1024, k = idx % 1024;
    int i = k % 256, d = k / 256;
    float v = 0.f;
    if (n < 256)      { if (d == 1) v = w1[n * 256 + i]; }
    else if (n < 512) { int oo = n - 256; int j = d - 1; if (j == 0 || j == 1) v = w2[oo * 512 + i * 2 + j]; }
    else              { int oo = n - 512; v = w4[oo * 1024 + i * 4 + d]; }
    bf16 h = __float2bfloat16(v);
    hi[idx] = h;
    lo[idx] = __float2bfloat16(v - __bfloat162float(h));
}

__global__ void assemble_ssm_wT(const float* __restrict__ w, bf16* __restrict__ hi,
                                bf16* __restrict__ lo)
{
    int idx = blockIdx.x * blockDim.x + threadIdx.x;
    if (idx >= 768 * 2304) return;
    int n = idx / 2304, k = idx % 2304;
    int i = k % 768, j = k / 768;
    float v = w[(size_t)n * 2304 + i * 3 + j];
    bf16 h = __float2bfloat16(v);
    hi[idx] = h;
    lo[idx] = __float2bfloat16(v - __bfloat162float(h));
}

// ---------------- small kernels ----------------
__global__ void init_c48_kernel(float* __restrict__ C48) {
    for (int i = threadIdx.x; i < FF * TP; i += blockDim.x) {
        int k = i / TP, t = i % TP;
        int m = (k * t) % TP;
        C48[i] = cospif(2.0f * (float)m / (float)TP);
    }
}

__global__ void pe_diff_kernel(const float* __restrict__ h1, const float* __restrict__ pe,
                               float* __restrict__ hpe, float* __restrict__ sf)
{
    size_t idx = (size_t)blockIdx.x * blockDim.x + threadIdx.x;
    const size_t total = N_BT * HH;
    if (idx >= total) return;
    int c = (int)(idx % HH);
    size_t r = idx / HH;
    int t = (int)(r % TT);
    float cur = h1[idx] + pe[(size_t)t * HH + c];
    hpe[idx] = cur;
    float prev = (t == 0) ? cur : (h1[idx - HH] + pe[(size_t)(t - 1) * HH + c]);
    sf[idx] = cur - prev;
}

__global__ void __launch_bounds__(256) dft48_kernel(const float* __restrict__ hp,
                                                    float* __restrict__ out,
                                                    const float* __restrict__ C48)
{
    __shared__ float sC[FF * TP];
    int b = blockIdx.x;
    for (int i = threadIdx.x; i < FF * TP; i += 256) sC[i] = C48[i];
    float r[TP];
    const float* base = hp + (size_t)b * TP * HH + threadIdx.x;
#pragma unroll
    for (int t = 0; t < TP; t++) r[t] = base[(size_t)t * HH];
    __syncthreads();
    float* ob = out + (size_t)b * FF * HH + threadIdx.x;
    for (int k = 0; k < FF; k++) {
        float acc = 0.f;
#pragma unroll
        for (int t = 0; t < TP; t++) acc = fmaf(r[t], sC[k * TP + t], acc);
        ob[(size_t)k * HH] = acc;
    }
}

__global__ void im2col_conv(const float* __restrict__ f, float* __restrict__ col) {
    size_t idx = (size_t)blockIdx.x * blockDim.x + threadIdx.x;
    const size_t total = N_BF * 1024;
    if (idx >= total) return;
    int kk = (int)(idx % 1024);
    size_t row = idx / 1024;
    int i = kk % 256, d = kk / 256;
    int fq = (int)(row % FF);
    size_t b = row / FF;
    int src = fq + d - 1;
    col[idx] = (src >= 0 && src < FF) ? f[((size_t)b * FF + src) * HH + i] : 0.f;
}

__global__ void im2col_ssm(const float* __restrict__ h, float* __restrict__ col) {
    size_t idx = (size_t)blockIdx.x * blockDim.x + threadIdx.x;
    const size_t total = N_BF * 2304;
    if (idx >= total) return;
    int kk = (int)(idx % 2304);
    size_t row = idx / 2304;
    int i = kk % EE, j = kk / EE;
    int fq = (int)(row % FF);
    size_t b = row / FF;
    int src = fq + j - 1;
    col[idx] = (src >= 0 && src < FF) ? h[((size_t)b * FF + src) * EE + i] : 0.f;
}

__global__ void __launch_bounds__(256) ln_kernel(const float* __restrict__ x,
                                                 const float* __restrict__ add,
                                                 const float* __restrict__ g,
                                                 const float* __restrict__ bta,
                                                 float* __restrict__ y, int C)
{
    int row = blockIdx.x;
    const float* xr = x + (size_t)row * C;
    const float* ar = add ? add + (size_t)row * C : nullptr;
    float s = 0.f, q = 0.f;
    for (int c = threadIdx.x; c < C; c += 256) {
        float v = xr[c] + (ar ? ar[c] : 0.f);
        s += v; q += v * v;
    }
#pragma unroll
    for (int o = 16; o; o >>= 1) {
        s += __shfl_xor_sync(~0u, s, o);
        q += __shfl_xor_sync(~0u, q, o);
    }
    __shared__ float ss[8], sq[8];
    int w = threadIdx.x >> 5, l = threadIdx.x & 31;
    if (l == 0) { ss[w] = s; sq[w] = q; }
    __syncthreads();
    if (threadIdx.x == 0) {
        float ts = 0.f, tq = 0.f;
        for (int i = 0; i < 8; i++) { ts += ss[i]; tq += sq[i]; }
        ss[0] = ts; sq[0] = tq;
    }
    __syncthreads();
    float mean = ss[0] / C;
    float var = sq[0] / C - mean * mean;
    float inv = rsqrtf(var + 1e-5f);
    for (int c = threadIdx.x; c < C; c += 256) {
        float v = xr[c] + (ar ? ar[c] : 0.f);
        y[(size_t)row * C + c] = (v - mean) * inv * g[c] + bta[c];
    }
}

__global__ void __launch_bounds__(256) attn_kernel(const float* __restrict__ qkv,
                                                   float* __restrict__ out)
{
    __shared__ float sq_[FF][DHH], sk_[FF][DHH], sv_[FF][DHH];
    __shared__ float G[FF][FF];
    __shared__ float ctab[FF];
    __shared__ float sa[NF2];
    __shared__ float kt[FF];
    int bh = blockIdx.x;
    int b = bh >> 3, hh = bh & 7;
    int tid = threadIdx.x;
    const float* base = qkv + ((size_t)b * FF) * (3 * EE) + hh * DHH;
    for (int idx = tid; idx < FF * DHH; idx += 256) {
        int t = idx / DHH, d = idx % DHH;
        size_t off = (size_t)t * (3 * EE) + d;
        sq_[t][d] = base[off];
        sk_[t][d] = base[off + EE];
        sv_[t][d] = base[off + 2 * EE];
    }
    if (tid < FF) ctab[tid] = cospif(2.0f * (float)tid / 25.0f);
    __syncthreads();
    for (int e = tid; e < FF * FF; e += 256) {
        int t = e / FF, s2 = e % FF;
        float acc = 0.f;
#pragma unroll 8
        for (int d = 0; d < DHH; d++) acc = fmaf(sq_[t][d], sk_[s2][d], acc);
        G[t][s2] = acc;
    }
    __syncthreads();
    if (tid < NF2) {
        float acc = 0.f;
        for (int t = 0; t < FF; t++)
            for (int s2 = 0; s2 < FF; s2++)
                acc = fmaf(G[t][s2], ctab[(tid * (t - s2 + FF)) % FF], acc);
        sa[tid] = acc * 0.10206207261596575f;
    }
    __syncthreads();
    if (tid == 0) {
        float mx = sa[0];
        for (int f = 1; f < NF2; f++) mx = fmaxf(mx, sa[f]);
        float e_[NF2], sum = 0.f;
        for (int f = 0; f < NF2; f++) { e_[f] = expf(sa[f] - mx); sum += e_[f]; }
        float inv = 1.0f / sum;
        for (int f = 0; f < NF2; f++) sa[f] = e_[f] * inv;
    }
    __syncthreads();
    if (tid < FF) {
        float acc = sa[0];
        for (int f = 1; f < NF2; f++) acc = fmaf(2.0f * sa[f], ctab[(f * tid) % FF], acc);
        kt[tid] = acc * 0.04f;
    }
    __syncthreads();
    float* obase = out + ((size_t)b * FF) * EE + hh * DHH;
    for (int idx = tid; idx < FF * DHH; idx += 256) {
        int t = idx / DHH, d = idx % DHH;
        float acc = 0.f;
#pragma unroll
        for (int s2 = 0; s2 < FF; s2++)
            acc = fmaf(kt[(t - s2 + FF) % FF], sv_[s2][d], acc);
        obase[(size_t)t * EE + d] = acc;
    }
}

__global__ void mean_kernel(const float* __restrict__ h, float* __restrict__ hm) {
    int b = blockIdx.x;
    int c = threadIdx.x;
    float acc = 0.f;
#pragma unroll
    for (int f = 0; f < FF; f++) acc += h[((size_t)b * FF + f) * EE + c];
    hm[(size_t)b * EE + c] = acc * 0.04f;
}

// ---------------- host helpers ----------------
static inline void gemm_tc(const float* A, const bf16* bh, const bf16* bl, float* C,
                           int M, int N, int K, const float* bias, const float* res, int act)
{
    dim3 grid(N / 128, M / 128);
    gemm_mma_kernel<<<grid, 256, GSM_TOTAL>>>(A, bh, bl, C, M, N, K, bias, res, act);
}
static inline void tsplit(const float* W, bf16* hi, bf16* lo, int K, int N) {
    dim3 grid((N + 31) / 32, (K + 31) / 32);
    tsplit_kernel<<<grid, dim3(32, 8)>>>(W, hi, lo, K, N);
}

extern "C" void kernel_launch(void* const* d_in, const int* in_sizes, int n_in,
                              void* d_out, int out_size)
{
    const float* x       = (const float*)d_in[0];
    const float* W_in    = (const float*)d_in[1];
    const float* b_in    = (const float*)d_in[2];
    const float* pe      = (const float*)d_in[3];
    const float* W_shape = (const float*)d_in[4];
    const float* b_shape = (const float*)d_in[5];
    const float* W_patch = (const float*)d_in[6];
    const float* b_patch = (const float*)d_in[7];
    const float* cw1     = (const float*)d_in[8];
    const float* cb1     = (const float*)d_in[9];
    const float* cw2     = (const float*)d_in[10];
    const float* cb2     = (const float*)d_in[11];
    const float* cw4     = (const float*)d_in[12];
    const float* cb4     = (const float*)d_in[13];
    const float* ln1g    = (const float*)d_in[14];
    const float* ln1b    = (const float*)d_in[15];
    const float* Wqkv    = (const float*)d_in[16];
    const float* Wo      = (const float*)d_in[17];
    const float* bo      = (const float*)d_in[18];
    const float* ln2g    = (const float*)d_in[19];
    const float* ln2b    = (const float*)d_in[20];
    const float* Wf1     = (const float*)d_in[21];
    const float* bf1     = (const float*)d_in[22];
    const float* Wf2     = (const float*)d_in[23];
    const float* bf2     = (const float*)d_in[24];
    const float* ssmw    = (const float*)d_in[25];
    const float* ssmb    = (const float*)d_in[26];
    const float* ssmg    = (const float*)d_in[27];
    const float* ssmbn   = (const float*)d_in[28];
    const float* W_out   = (const float*)d_in[29];
    const float* b_out   = (const float*)d_in[30];
    float* out = (float*)d_out;

    cudaFuncSetAttribute(gemm_mma_kernel, cudaFuncAttributeMaxDynamicSharedMemorySize, GSM_TOTAL);

    float *h1, *hpe, *sf, *h2, *hp, *fr, *C48, *cb, *col, *h, *y, *qkv, *att, *mid, *s, *hm;
    cudaGetSymbolAddress((void**)&h1,  g_h1);
    cudaGetSymbolAddress((void**)&hpe, g_hpe);
    cudaGetSymbolAddress((void**)&sf,  g_sf);
    cudaGetSymbolAddress((void**)&h2,  g_h2);
    cudaGetSymbolAddress((void**)&hp,  g_hp);
    cudaGetSymbolAddress((void**)&fr,  g_fr);
    cudaGetSymbolAddress((void**)&C48, g_C48);
    cudaGetSymbolAddress((void**)&cb,  g_cb);
    cudaGetSymbolAddress((void**)&col, g_col);
    cudaGetSymbolAddress((void**)&h,   g_h);
    cudaGetSymbolAddress((void**)&y,   g_y);
    cudaGetSymbolAddress((void**)&qkv, g_qkv);
    cudaGetSymbolAddress((void**)&att, g_att);
    cudaGetSymbolAddress((void**)&mid, g_mid);
    cudaGetSymbolAddress((void**)&s,   g_s);
    cudaGetSymbolAddress((void**)&hm,  g_hm);

    bf16 *tWin_h, *tWin_l, *tWsh_h, *tWsh_l, *tWpa_h, *tWpa_l, *tWc_h, *tWc_l;
    bf16 *tWqkv_h, *tWqkv_l, *tWo_h, *tWo_l, *tWf1_h, *tWf1_l, *tWf2_h, *tWf2_l, *tWc2_h, *tWc2_l;
    cudaGetSymbolAddress((void**)&tWin_h,  g_tWin_h);  cudaGetSymbolAddress((void**)&tWin_l,  g_tWin_l);
    cudaGetSymbolAddress((void**)&tWsh_h,  g_tWsh_h);  cudaGetSymbolAddress((void**)&tWsh_l,  g_tWsh_l);
    cudaGetSymbolAddress((void**)&tWpa_h,  g_tWpa_h);  cudaGetSymbolAddress((void**)&tWpa_l,  g_tWpa_l);
    cudaGetSymbolAddress((void**)&tWc_h,   g_tWc_h);   cudaGetSymbolAddress((void**)&tWc_l,   g_tWc_l);
    cudaGetSymbolAddress((void**)&tWqkv_h, g_tWqkv_h); cudaGetSymbolAddress((void**)&tWqkv_l, g_tWqkv_l);
    cudaGetSymbolAddress((void**)&tWo_h,   g_tWo_h);   cudaGetSymbolAddress((void**)&tWo_l,   g_tWo_l);
    cudaGetSymbolAddress((void**)&tWf1_h,  g_tWf1_h);  cudaGetSymbolAddress((void**)&tWf1_l,  g_tWf1_l);
    cudaGetSymbolAddress((void**)&tWf2_h,  g_tWf2_h);  cudaGetSymbolAddress((void**)&tWf2_l,  g_tWf2_l);
    cudaGetSymbolAddress((void**)&tWc2_h,  g_tWc2_h);  cudaGetSymbolAddress((void**)&tWc2_l,  g_tWc2_l);

    // tables + weight prep
    init_c48_kernel<<<1, 256>>>(C48);
    tsplit(W_in,    tWin_h, tWin_l,  64, 256);
    tsplit(W_shape, tWsh_h, tWsh_l, 256, 256);
    tsplit(W_patch, tWpa_h, tWpa_l, 512, 256);
    assemble_conv_wT<<<(768 * 1024 + 255) / 256, 256>>>(cw1, cw2, cw4, cb1, cb2, cb4, tWc_h, tWc_l, cb);
    for (int i = 0; i < LL; i++) {
        tsplit(Wqkv + (size_t)i * EE * 3 * EE, tWqkv_h + (size_t)i * 3 * EE * EE, tWqkv_l + (size_t)i * 3 * EE * EE, EE, 3 * EE);
        tsplit(Wo   + (size_t)i * EE * EE,     tWo_h   + (size_t)i * EE * EE,     tWo_l   + (size_t)i * EE * EE,     EE, EE);
        tsplit(Wf1  + (size_t)i * EE * 4 * EE, tWf1_h  + (size_t)i * 4 * EE * EE, tWf1_l  + (size_t)i * 4 * EE * EE, EE, 4 * EE);
        tsplit(Wf2  + (size_t)i * 4 * EE * EE, tWf2_h  + (size_t)i * EE * 4 * EE, tWf2_l  + (size_t)i * EE * 4 * EE, 4 * EE, EE);
    }
    assemble_ssm_wT<<<(768 * 2304 + 255) / 256, 256>>>(ssmw, tWc2_h, tWc2_l);

    // embedding chain
    gemm_tc(x, tWin_h, tWin_l, h1, BB * TT, HH, DIN, b_in, nullptr, 0);
    {
        size_t tot = N_BT * HH;
        pe_diff_kernel<<<(unsigned)((tot + 255) / 256), 256>>>(h1, pe, hpe, sf);
    }
    gemm_tc(sf, tWsh_h, tWsh_l, h2, BB * TT, HH, HH, b_shape, hpe, 0);
    gemm_tc(h2, tWpa_h, tWpa_l, hp, BB * TP, HH, 2 * HH, b_patch, nullptr, 0);

    dft48_kernel<<<BB, 256>>>(hp, fr, C48);

    {
        size_t tot = N_BF * 1024;
        im2col_conv<<<(unsigned)((tot + 255) / 256), 256>>>(fr, col);
    }
    gemm_tc(col, tWc_h, tWc_l, h, (int)N_BF, EE, 1024, cb, nullptr, 0);

    // transformer layers
    for (int i = 0; i < LL; i++) {
        ln_kernel<<<(unsigned)N_BF, 256>>>(h, nullptr, ln1g + (size_t)i * EE, ln1b + (size_t)i * EE, y, EE);
        gemm_tc(y, tWqkv_h + (size_t)i * 3 * EE * EE, tWqkv_l + (size_t)i * 3 * EE * EE,
                qkv, (int)N_BF, 3 * EE, EE, nullptr, nullptr, 0);
        attn_kernel<<<BB * NHEADS, 256>>>(qkv, att);
        gemm_tc(att, tWo_h + (size_t)i * EE * EE, tWo_l + (size_t)i * EE * EE,
                h, (int)N_BF, EE, EE, bo + (size_t)i * EE, h, 0);
        ln_kernel<<<(unsigned)N_BF, 256>>>(h, nullptr, ln2g + (size_t)i * EE, ln2b + (size_t)i * EE, y, EE);
        gemm_tc(y, tWf1_h + (size_t)i * 4 * EE * EE, tWf1_l + (size_t)i * 4 * EE * EE,
                mid, (int)N_BF, 4 * EE, EE, bf1 + (size_t)i * 4 * EE, nullptr, 1);
        gemm_tc(mid, tWf2_h + (size_t)i * EE * 4 * EE, tWf2_l + (size_t)i * EE * 4 * EE,
                h, (int)N_BF, EE, 4 * EE, bf2 + (size_t)i * EE, h, 0);
    }

    // SSM conv + LN
    {
        size_t tot = N_BF * 2304;
        im2col_ssm<<<(unsigned)((tot + 255) / 256), 256>>>(h, col);
    }
    gemm_tc(col, tWc2_h, tWc2_l, s, (int)N_BF, EE, 3 * EE, ssmb, nullptr, 0);
    ln_kernel<<<(unsigned)N_BF, 256>>>(h, s, ssmg, ssmbn, h, EE);

    // mean + classifier (small, f32 path)
    mean_kernel<<<BB, EE>>>(h, hm);
    {
        dim3 grid((NCC + 127) / 128, (BB + 127) / 128);
        sgemm_kernel<<<grid, 256>>>(hm, W_out, out, BB, NCC, EE, b_out);
    }
}

// round 5
// speedup vs baseline: 1.7191x; 1.0726x over previous
#include <cuda_runtime.h>
#include <cuda_bf16.h>
#include <math.h>
#include <stdint.h>

// ---------------- problem constants ----------------
#define BB    512
#define TT    96
#define DIN   64
#define HH    256
#define LL    4
#define EE    768
#define NCC   100
#define TP    48
#define FF    25
#define NF2   13
#define DHH   96
#define NHEADS 8

#define N_BT  ((size_t)BB * TT)   // 49152
#define N_BF  ((size_t)BB * FF)   // 12800

typedef __nv_bfloat16 bf16;

// ---------------- scratch buffers ----------------
__device__ __align__(16) float g_h1 [N_BT * HH];
__device__ __align__(16) float g_hpe[N_BT * HH];
__device__ __align__(16) float g_sf [N_BT * HH];
__device__ __align__(16) float g_h2 [N_BT * HH];
__device__ __align__(16) float g_hp [(size_t)BB * TP * HH];
__device__ __align__(16) float g_fr [N_BF * HH];
__device__ __align__(16) float g_C48[FF * TP];
__device__ __align__(16) float g_cb [EE];
__device__ __align__(16) float g_col[N_BF * 2304];
__device__ __align__(16) float g_h  [N_BF * EE];
__device__ __align__(16) float g_y  [N_BF * EE];
__device__ __align__(16) float g_qkv[N_BF * 3 * EE];
__device__ __align__(16) float g_att[N_BF * EE];
__device__ __align__(16) float g_mid[N_BF * 4 * EE];
__device__ __align__(16) float g_s  [N_BF * EE];
__device__ __align__(16) float g_hm [(size_t)BB * EE];

// transposed + split weights: [N][K] bf16 hi/lo
__device__ __align__(16) bf16 g_tWin_h [256 * 64],       g_tWin_l [256 * 64];
__device__ __align__(16) bf16 g_tWsh_h [256 * 256],      g_tWsh_l [256 * 256];
__device__ __align__(16) bf16 g_tWpa_h [256 * 512],      g_tWpa_l [256 * 512];
__device__ __align__(16) bf16 g_tWc_h  [768 * 1024],     g_tWc_l  [768 * 1024];
__device__ __align__(16) bf16 g_tWqkv_h[LL * 2304 * 768],g_tWqkv_l[LL * 2304 * 768];
__device__ __align__(16) bf16 g_tWo_h  [LL * 768 * 768], g_tWo_l  [LL * 768 * 768];
__device__ __align__(16) bf16 g_tWf1_h [LL * 3072 * 768],g_tWf1_l [LL * 3072 * 768];
__device__ __align__(16) bf16 g_tWf2_h [LL * 768 * 3072],g_tWf2_l [LL * 768 * 3072];
__device__ __align__(16) bf16 g_tWc2_h [768 * 2304],     g_tWc2_l [768 * 2304];

// ---------------- helpers ----------------
__device__ __forceinline__ uint32_t smem_u32(const void* p) {
    uint32_t a;
    asm("{ .reg .u64 t; cvta.to.shared.u64 t, %1; cvt.u32.u64 %0, t; }" : "=r"(a) : "l"(p));
    return a;
}
__device__ __forceinline__ uint32_t bfpack(bf16 a, bf16 b) {
    __nv_bfloat162 t; t.x = a; t.y = b;
    return *reinterpret_cast<uint32_t*>(&t);
}

// SW128: 128B rows, xor 16B-chunk bits [4:6] with row%8 (addr bits [7:9])
#define SWZ128(x) ((x) ^ (((x) >> 3) & 0x70))

#define LDMX4(r, a) \
    asm volatile("ldmatrix.sync.aligned.m8n8.x4.shared.b16 {%0,%1,%2,%3}, [%4];" \
        : "=r"((r)[0]), "=r"((r)[1]), "=r"((r)[2]), "=r"((r)[3]) : "r"(a))
#define MMA16816(d, A, Bf) \
    asm volatile("mma.sync.aligned.m16n8k16.row.col.f32.bf16.bf16.f32 " \
        "{%0,%1,%2,%3}, {%4,%5,%6,%7}, {%8,%9}, {%0,%1,%2,%3};" \
        : "+f"((d)[0]), "+f"((d)[1]), "+f"((d)[2]), "+f"((d)[3]) \
        : "r"((A)[0]), "r"((A)[1]), "r"((A)[2]), "r"((A)[3]), "r"((Bf)[0]), "r"((Bf)[1]))

__device__ __forceinline__ void split4(float4 v, uint2& hv, uint2& lv) {
    bf16 h0 = __float2bfloat16(v.x), h1 = __float2bfloat16(v.y);
    bf16 h2 = __float2bfloat16(v.z), h3 = __float2bfloat16(v.w);
    bf16 l0 = __float2bfloat16(v.x - __bfloat162float(h0));
    bf16 l1 = __float2bfloat16(v.y - __bfloat162float(h1));
    bf16 l2 = __float2bfloat16(v.z - __bfloat162float(h2));
    bf16 l3 = __float2bfloat16(v.w - __bfloat162float(h3));
    hv = make_uint2(bfpack(h0, h1), bfpack(h2, h3));
    lv = make_uint2(bfpack(l0, l1), bfpack(l2, l3));
}

// ---------------- HMMA GEMM: C[M,N] = act(A f32 @ B^T(split bf16) + bias + res)
// M%128==0, N%128==0, K%64==0
// smem: 2 buffers x {Ahi,Alo,Bhi,Blo} each 128x128B SW128 tiles (16KB) = 128KB
#define G2_AHI   0
#define G2_ALO   16384
#define G2_BHI   32768
#define G2_BLO   49152
#define G2_BUF   65536
#define G2_TOTAL 131072

__global__ void __launch_bounds__(256, 1)
gemm_mma_kernel(const float* __restrict__ A,
                const bf16* __restrict__ Bhi, const bf16* __restrict__ Blo,
                float* __restrict__ C, int M, int N, int K,
                const float* __restrict__ bias, const float* __restrict__ res, int act)
{
    extern __shared__ char smem[];
    const uint32_t sb = smem_u32(smem);
    const int tid  = threadIdx.x;
    const int lane = tid & 31;
    const int wid  = tid >> 5;
    const int wm   = wid & 1;       // 2 warp-rows (64 rows)
    const int wn   = wid >> 1;      // 4 warp-cols (32 cols)
    const int m0 = blockIdx.y * 128;
    const int n0 = blockIdx.x * 128;

    // loaders: 2 threads per 128B row
    const int ldRow = tid >> 1;
    const int ldHalf = tid & 1;

    float acc[4][4][4];
#pragma unroll
    for (int i = 0; i < 4; i++)
#pragma unroll
        for (int j = 0; j < 4; j++)
#pragma unroll
            for (int e = 0; e < 4; e++) acc[i][j][e] = 0.f;

    const int nk = K >> 6;

    // unswizzled per-lane fragment bases (swizzle applied after adding kb; tile
    // offsets mi*2048 / ni2*2048 touch bits >=11 and commute with the xor)
    const uint32_t aBase = (uint32_t)(wm * 64 + (lane & 15)) * 128u + (uint32_t)(lane >> 4) * 16u;
    const uint32_t bBase = (uint32_t)(wn * 32 + (lane >> 4) * 8 + (lane & 7)) * 128u
                         + (uint32_t)((lane >> 3) & 1) * 16u;

    uint2 ahv[8], alv[8];      // A prefetch, already split
    uint4 bhv[4], blv[4];      // B prefetch

    // prologue: load + convert chunk 0
    {
        const float* Ab = A + (size_t)(m0 + ldRow) * K;
#pragma unroll
        for (int p = 0; p < 8; p++) {
            float4 v = *reinterpret_cast<const float4*>(Ab + (ldHalf * 8 + p) * 4);
            split4(v, ahv[p], alv[p]);
        }
        const bf16* Bh = Bhi + (size_t)(n0 + ldRow) * K;
        const bf16* Bl = Blo + (size_t)(n0 + ldRow) * K;
#pragma unroll
        for (int p = 0; p < 4; p++) {
            bhv[p] = *reinterpret_cast<const uint4*>(Bh + (ldHalf * 4 + p) * 8);
            blv[p] = *reinterpret_cast<const uint4*>(Bl + (ldHalf * 4 + p) * 8);
        }
    }
    // STS chunk 0 into buf 0
    {
        char* bufc = smem;
#pragma unroll
        for (int p = 0; p < 8; p++) {
            uint32_t off = SWZ128((uint32_t)ldRow * 128u + (uint32_t)(ldHalf * 8 + p) * 8u);
            *reinterpret_cast<uint2*>(bufc + G2_AHI + off) = ahv[p];
            *reinterpret_cast<uint2*>(bufc + G2_ALO + off) = alv[p];
        }
#pragma unroll
        for (int p = 0; p < 4; p++) {
            uint32_t off = SWZ128((uint32_t)ldRow * 128u + (uint32_t)(ldHalf * 4 + p) * 16u);
            *reinterpret_cast<uint4*>(bufc + G2_BHI + off) = bhv[p];
            *reinterpret_cast<uint4*>(bufc + G2_BLO + off) = blv[p];
        }
    }
    __syncthreads();

    for (int kc = 0; kc < nk; kc++) {
        const uint32_t bufo = (uint32_t)(kc & 1) * G2_BUF;
        // prefetch next chunk
        if (kc + 1 < nk) {
            const float* Ab = A + (size_t)(m0 + ldRow) * K + (kc + 1) * 64;
#pragma unroll
            for (int p = 0; p < 8; p++) {
                float4 v = *reinterpret_cast<const float4*>(Ab + (ldHalf * 8 + p) * 4);
                split4(v, ahv[p], alv[p]);
            }
            const bf16* Bh = Bhi + (size_t)(n0 + ldRow) * K + (kc + 1) * 64;
            const bf16* Bl = Blo + (size_t)(n0 + ldRow) * K + (kc + 1) * 64;
#pragma unroll
            for (int p = 0; p < 4; p++) {
                bhv[p] = *reinterpret_cast<const uint4*>(Bh + (ldHalf * 4 + p) * 8);
                blv[p] = *reinterpret_cast<const uint4*>(Bl + (ldHalf * 4 + p) * 8);
            }
        }
        // compute current chunk: four k16 steps
#pragma unroll
        for (int kk = 0; kk < 4; kk++) {
            const uint32_t kb = (uint32_t)kk * 32u;     // 16 bf16 = 32B
            const uint32_t aSw = SWZ128(aBase + kb);    // lane koff(0/16)+kb(<=96) < 128: no carry
            const uint32_t bSw = SWZ128(bBase + kb);
            uint32_t ah[4][4], al[4][4], bh4[2][4], bl4[2][4];
#pragma unroll
            for (int mi = 0; mi < 4; mi++) {
                uint32_t a_addr = sb + bufo + G2_AHI + aSw + (uint32_t)(mi * 2048);
                LDMX4(ah[mi], a_addr);
                LDMX4(al[mi], a_addr + (G2_ALO - G2_AHI));
            }
#pragma unroll
            for (int ni2 = 0; ni2 < 2; ni2++) {
                uint32_t b_addr = sb + bufo + G2_BHI + bSw + (uint32_t)(ni2 * 2048);
                LDMX4(bh4[ni2], b_addr);
                LDMX4(bl4[ni2], b_addr + (G2_BLO - G2_BHI));
            }
#pragma unroll
            for (int mi = 0; mi < 4; mi++)
#pragma unroll
                for (int ni = 0; ni < 4; ni++) {
                    const uint32_t* Bh_ = &bh4[ni >> 1][(ni & 1) * 2];
                    const uint32_t* Bl_ = &bl4[ni >> 1][(ni & 1) * 2];
                    MMA16816(acc[mi][ni], ah[mi], Bh_);
                    MMA16816(acc[mi][ni], ah[mi], Bl_);
                    MMA16816(acc[mi][ni], al[mi], Bh_);
                }
        }
        // store next chunk
        if (kc + 1 < nk) {
            char* bufc = smem + ((kc + 1) & 1) * G2_BUF;
#pragma unroll
            for (int p = 0; p < 8; p++) {
                uint32_t off = SWZ128((uint32_t)ldRow * 128u + (uint32_t)(ldHalf * 8 + p) * 8u);
                *reinterpret_cast<uint2*>(bufc + G2_AHI + off) = ahv[p];
                *reinterpret_cast<uint2*>(bufc + G2_ALO + off) = alv[p];
            }
#pragma unroll
            for (int p = 0; p < 4; p++) {
                uint32_t off = SWZ128((uint32_t)ldRow * 128u + (uint32_t)(ldHalf * 4 + p) * 16u);
                *reinterpret_cast<uint4*>(bufc + G2_BHI + off) = bhv[p];
                *reinterpret_cast<uint4*>(bufc + G2_BLO + off) = blv[p];
            }
        }
        __syncthreads();
    }

    // epilogue: stage accum in smem (stride 132), then coalesced gmem store
    float* stg = reinterpret_cast<float*>(smem);
#pragma unroll
    for (int mi = 0; mi < 4; mi++) {
#pragma unroll
        for (int ni = 0; ni < 4; ni++) {
            int r = wm * 64 + mi * 16 + (lane >> 2);
            int c = wn * 32 + ni * 8 + (lane & 3) * 2;
            stg[r * 132 + c]           = acc[mi][ni][0];
            stg[r * 132 + c + 1]       = acc[mi][ni][1];
            stg[(r + 8) * 132 + c]     = acc[mi][ni][2];
            stg[(r + 8) * 132 + c + 1] = acc[mi][ni][3];
        }
    }
    __syncthreads();
#pragma unroll 4
    for (int it = 0; it < 64; it++) {
        int idx = it * 256 + tid;
        int r = idx >> 7, c = idx & 127;
        float v = stg[r * 132 + c];
        int gn = n0 + c;
        size_t gr = (size_t)(m0 + r);
        if (bias) v += bias[gn];
        if (res)  v += res[gr * N + gn];
        if (act)  v = 0.5f * v * (1.0f + erff(v * 0.70710678118654752f));
        C[gr * N + gn] = v;
    }
}

// ---------------- fallback f32 SGEMM (classifier only) ----------------
__global__ void __launch_bounds__(256, 2)
sgemm_kernel(const float* __restrict__ A, const float* __restrict__ B,
             float* __restrict__ C, int M, int N, int K,
             const float* __restrict__ bias)
{
    __shared__ float As[8][128];
    __shared__ float Bs[8][128];
    const int tid = threadIdx.x;
    const int row0 = blockIdx.y * 128, col0 = blockIdx.x * 128;
    const int tx = tid & 15, ty = tid >> 4;
    const int arow = tid >> 1, acol = (tid & 1) * 4;
    const int brow = tid >> 5, bcol = (tid & 31) * 4;
    float acc[8][8];
#pragma unroll
    for (int i = 0; i < 8; i++)
#pragma unroll
        for (int j = 0; j < 8; j++) acc[i][j] = 0.f;
    const int gar = row0 + arow, gbc = col0 + bcol;
    const bool aok = (gar < M), bok = (gbc < N);
    for (int k0 = 0; k0 < K; k0 += 8) {
        float4 avv = make_float4(0, 0, 0, 0);
        if (aok) avv = *reinterpret_cast<const float4*>(&A[(size_t)gar * K + k0 + acol]);
        As[acol + 0][arow] = avv.x; As[acol + 1][arow] = avv.y;
        As[acol + 2][arow] = avv.z; As[acol + 3][arow] = avv.w;
        float4 bv = make_float4(0, 0, 0, 0);
        if (bok) bv = *reinterpret_cast<const float4*>(&B[(size_t)(k0 + brow) * N + gbc]);
        *reinterpret_cast<float4*>(&Bs[brow][bcol]) = bv;
        __syncthreads();
#pragma unroll
        for (int kk = 0; kk < 8; kk++) {
            float4 ra0 = *reinterpret_cast<const float4*>(&As[kk][ty * 8 + 0]);
            float4 ra1 = *reinterpret_cast<const float4*>(&As[kk][ty * 8 + 4]);
            float4 rb0 = *reinterpret_cast<const float4*>(&Bs[kk][tx * 8 + 0]);
            float4 rb1 = *reinterpret_cast<const float4*>(&Bs[kk][tx * 8 + 4]);
            float ra[8] = {ra0.x, ra0.y, ra0.z, ra0.w, ra1.x, ra1.y, ra1.z, ra1.w};
            float rb[8] = {rb0.x, rb0.y, rb0.z, rb0.w, rb1.x, rb1.y, rb1.z, rb1.w};
#pragma unroll
            for (int i = 0; i < 8; i++)
#pragma unroll
                for (int j = 0; j < 8; j++) acc[i][j] = fmaf(ra[i], rb[j], acc[i][j]);
        }
        __syncthreads();
    }
#pragma unroll
    for (int i = 0; i < 8; i++) {
        const int r = row0 + ty * 8 + i;
        if (r >= M) continue;
#pragma unroll
        for (int j = 0; j < 8; j++) {
            const int c = col0 + tx * 8 + j;
            if (c >= N) continue;
            float v = acc[i][j];
            if (bias) v += bias[c];
            C[(size_t)r * N + c] = v;
        }
    }
}

// ---------------- weight transpose + split ----------------
__global__ void tsplit_kernel(const float* __restrict__ W, bf16* __restrict__ hi,
                              bf16* __restrict__ lo, int K, int N)
{
    __shared__ float t[32][33];
    int k0 = blockIdx.y * 32, n0 = blockIdx.x * 32;
    int tx = threadIdx.x, ty = threadIdx.y;
#pragma unroll
    for (int r = 0; r < 4; r++) {
        int k = k0 + ty + r * 8;
        t[ty + r * 8][tx] = (k < K && n0 + tx < N) ? W[(size_t)k * N + n0 + tx] : 0.f;
    }
    __syncthreads();
#pragma unroll
    for (int r = 0; r < 4; r++) {
        int n = n0 + ty + r * 8, k = k0 + tx;
        if (n < N && k < K) {
            float v = t[tx][ty + r * 8];
            bf16 h = __float2bfloat16(v);
            hi[(size_t)n * K + k] = h;
            lo[(size_t)n * K + k] = __float2bfloat16(v - __bfloat162float(h));
        }
    }
}

__global__ void assemble_conv_wT(const float* __restrict__ w1, const float* __restrict__ w2,
                                 const float* __restrict__ w4, const float* __restrict__ b1,
                                 const float* __restrict__ b2, const float* __restrict__ b4,
                                 bf16* __restrict__ hi, bf16* __restrict__ lo,
                                 float* __restrict__ cb)
{
    int idx = blockIdx.x * blockDim.x + threadIdx.x;
    if (idx < EE) cb[idx] = (idx < 256) ? b1[idx] : (idx < 512 ? b2[idx - 256] : b4[idx - 512]);
    if (idx >= 768 * 1024) return;
    int n = idx / 1024, k = idx % 1024;
    int i = k % 256, d = k / 256;
    float v = 0.f;
    if (n < 256)      { if (d == 1) v = w1[n * 256 + i]; }
    else if (n < 512) { int oo = n - 256; int j = d - 1; if (j == 0 || j == 1) v = w2[oo * 512 + i * 2 + j]; }
    else              { int oo = n - 512; v = w4[oo * 1024 + i * 4 + d]; }
    bf16 h = __float2bfloat16(v);
    hi[idx] = h;
    lo[idx] = __float2bfloat16(v - __bfloat162float(h));
}

__global__ void assemble_ssm_wT(const float* __restrict__ w, bf16* __restrict__ hi,
                                bf16* __restrict__ lo)
{
    int idx = blockIdx.x * blockDim.x + threadIdx.x;
    if (idx >= 768 * 2304) return;
    int n = idx / 2304, k = idx % 2304;
    int i = k % 768, j = k / 768;
    float v = w[(size_t)n * 2304 + i * 3 + j];
    bf16 h = __float2bfloat16(v);
    hi[idx] = h;
    lo[idx] = __float2bfloat16(v - __bfloat162float(h));
}

// ---------------- small kernels ----------------
__global__ void init_c48_kernel(float* __restrict__ C48) {
    for (int i = threadIdx.x; i < FF * TP; i += blockDim.x) {
        int k = i / TP, t = i % TP;
        int m = (k * t) % TP;
        C48[i] = cospif(2.0f * (float)m / (float)TP);
    }
}

__global__ void pe_diff_kernel(const float* __restrict__ h1, const float* __restrict__ pe,
                               float* __restrict__ hpe, float* __restrict__ sf)
{
    size_t idx = (size_t)blockIdx.x * blockDim.x + threadIdx.x;
    const size_t total = N_BT * HH;
    if (idx >= total) return;
    int c = (int)(idx % HH);
    size_t r = idx / HH;
    int t = (int)(r % TT);
    float cur = h1[idx] + pe[(size_t)t * HH + c];
    hpe[idx] = cur;
    float prev = (t == 0) ? cur : (h1[idx - HH] + pe[(size_t)(t - 1) * HH + c]);
    sf[idx] = cur - prev;
}

__global__ void __launch_bounds__(256) dft48_kernel(const float* __restrict__ hp,
                                                    float* __restrict__ out,
                                                    const float* __restrict__ C48)
{
    __shared__ float sC[FF * TP];
    int b = blockIdx.x;
    for (int i = threadIdx.x; i < FF * TP; i += 256) sC[i] = C48[i];
    float r[TP];
    const float* base = hp + (size_t)b * TP * HH + threadIdx.x;
#pragma unroll
    for (int t = 0; t < TP; t++) r[t] = base[(size_t)t * HH];
    __syncthreads();
    float* ob = out + (size_t)b * FF * HH + threadIdx.x;
    for (int k = 0; k < FF; k++) {
        float acc = 0.f;
#pragma unroll
        for (int t = 0; t < TP; t++) acc = fmaf(r[t], sC[k * TP + t], acc);
        ob[(size_t)k * HH] = acc;
    }
}

__global__ void im2col_conv(const float* __restrict__ f, float* __restrict__ col) {
    size_t idx = (size_t)blockIdx.x * blockDim.x + threadIdx.x;
    const size_t total = N_BF * 1024;
    if (idx >= total) return;
    int kk = (int)(idx % 1024);
    size_t row = idx / 1024;
    int i = kk % 256, d = kk / 256;
    int fq = (int)(row % FF);
    size_t b = row / FF;
    int src = fq + d - 1;
    col[idx] = (src >= 0 && src < FF) ? f[((size_t)b * FF + src) * HH + i] : 0.f;
}

__global__ void im2col_ssm(const float* __restrict__ h, float* __restrict__ col) {
    size_t idx = (size_t)blockIdx.x * blockDim.x + threadIdx.x;
    const size_t total = N_BF * 2304;
    if (idx >= total) return;
    int kk = (int)(idx % 2304);
    size_t row = idx / 2304;
    int i = kk % EE, j = kk / EE;
    int fq = (int)(row % FF);
    size_t b = row / FF;
    int src = fq + j - 1;
    col[idx] = (src >= 0 && src < FF) ? h[((size_t)b * FF + src) * EE + i] : 0.f;
}

__global__ void __launch_bounds__(256) ln_kernel(const float* __restrict__ x,
                                                 const float* __restrict__ add,
                                                 const float* __restrict__ g,
                                                 const float* __restrict__ bta,
                                                 float* __restrict__ y, int C)
{
    int row = blockIdx.x;
    const float* xr = x + (size_t)row * C;
    const float* ar = add ? add + (size_t)row * C : nullptr;
    float s = 0.f, q = 0.f;
    for (int c = threadIdx.x; c < C; c += 256) {
        float v = xr[c] + (ar ? ar[c] : 0.f);
        s += v; q += v * v;
    }
#pragma unroll
    for (int o = 16; o; o >>= 1) {
        s += __shfl_xor_sync(~0u, s, o);
        q += __shfl_xor_sync(~0u, q, o);
    }
    __shared__ float ss[8], sq[8];
    int w = threadIdx.x >> 5, l = threadIdx.x & 31;
    if (l == 0) { ss[w] = s; sq[w] = q; }
    __syncthreads();
    if (threadIdx.x == 0) {
        float ts = 0.f, tq = 0.f;
        for (int i = 0; i < 8; i++) { ts += ss[i]; tq += sq[i]; }
        ss[0] = ts; sq[0] = tq;
    }
    __syncthreads();
    float mean = ss[0] / C;
    float var = sq[0] / C - mean * mean;
    float inv = rsqrtf(var + 1e-5f);
    for (int c = threadIdx.x; c < C; c += 256) {
        float v = xr[c] + (ar ? ar[c] : 0.f);
        y[(size_t)row * C + c] = (v - mean) * inv * g[c] + bta[c];
    }
}

__global__ void __launch_bounds__(256) attn_kernel(const float* __restrict__ qkv,
                                                   float* __restrict__ out)
{
    __shared__ float sq_[FF][DHH], sk_[FF][DHH], sv_[FF][DHH];
    __shared__ float G[FF][FF];
    __shared__ float ctab[FF];
    __shared__ float sa[NF2];
    __shared__ float kt[FF];
    int bh = blockIdx.x;
    int b = bh >> 3, hh = bh & 7;
    int tid = threadIdx.x;
    const float* base = qkv + ((size_t)b * FF) * (3 * EE) + hh * DHH;
    for (int idx = tid; idx < FF * DHH; idx += 256) {
        int t = idx / DHH, d = idx % DHH;
        size_t off = (size_t)t * (3 * EE) + d;
        sq_[t][d] = base[off];
        sk_[t][d] = base[off + EE];
        sv_[t][d] = base[off + 2 * EE];
    }
    if (tid < FF) ctab[tid] = cospif(2.0f * (float)tid / 25.0f);
    __syncthreads();
    for (int e = tid; e < FF * FF; e += 256) {
        int t = e / FF, s2 = e % FF;
        float acc = 0.f;
#pragma unroll 8
        for (int d = 0; d < DHH; d++) acc = fmaf(sq_[t][d], sk_[s2][d], acc);
        G[t][s2] = acc;
    }
    __syncthreads();
    if (tid < NF2) {
        float acc = 0.f;
        for (int t = 0; t < FF; t++)
            for (int s2 = 0; s2 < FF; s2++)
                acc = fmaf(G[t][s2], ctab[(tid * (t - s2 + FF)) % FF], acc);
        sa[tid] = acc * 0.10206207261596575f;
    }
    __syncthreads();
    if (tid == 0) {
        float mx = sa[0];
        for (int f = 1; f < NF2; f++) mx = fmaxf(mx, sa[f]);
        float e_[NF2], sum = 0.f;
        for (int f = 0; f < NF2; f++) { e_[f] = expf(sa[f] - mx); sum += e_[f]; }
        float inv = 1.0f / sum;
        for (int f = 0; f < NF2; f++) sa[f] = e_[f] * inv;
    }
    __syncthreads();
    if (tid < FF) {
        float acc = sa[0];
        for (int f = 1; f < NF2; f++) acc = fmaf(2.0f * sa[f], ctab[(f * tid) % FF], acc);
        kt[tid] = acc * 0.04f;
    }
    __syncthreads();
    float* obase = out + ((size_t)b * FF) * EE + hh * DHH;
    for (int idx = tid; idx < FF * DHH; idx += 256) {
        int t = idx / DHH, d = idx % DHH;
        float acc = 0.f;
#pragma unroll
        for (int s2 = 0; s2 < FF; s2++)
            acc = fmaf(kt[(t - s2 + FF) % FF], sv_[s2][d], acc);
        obase[(size_t)t * EE + d] = acc;
    }
}

__global__ void mean_kernel(const float* __restrict__ h, float* __restrict__ hm) {
    int b = blockIdx.x;
    int c = threadIdx.x;
    float acc = 0.f;
#pragma unroll
    for (int f = 0; f < FF; f++) acc += h[((size_t)b * FF + f) * EE + c];
    hm[(size_t)b * EE + c] = acc * 0.04f;
}

// ---------------- host helpers ----------------
static inline void gemm_tc(const float* A, const bf16* bh, const bf16* bl, float* C,
                           int M, int N, int K, const float* bias, const float* res, int act)
{
    dim3 grid(N / 128, M / 128);
    gemm_mma_kernel<<<grid, 256, G2_TOTAL>>>(A, bh, bl, C, M, N, K, bias, res, act);
}
static inline void tsplit(const float* W, bf16* hi, bf16* lo, int K, int N) {
    dim3 grid((N + 31) / 32, (K + 31) / 32);
    tsplit_kernel<<<grid, dim3(32, 8)>>>(W, hi, lo, K, N);
}

extern "C" void kernel_launch(void* const* d_in, const int* in_sizes, int n_in,
                              void* d_out, int out_size)
{
    const float* x       = (const float*)d_in[0];
    const float* W_in    = (const float*)d_in[1];
    const float* b_in    = (const float*)d_in[2];
    const float* pe      = (const float*)d_in[3];
    const float* W_shape = (const float*)d_in[4];
    const float* b_shape = (const float*)d_in[5];
    const float* W_patch = (const float*)d_in[6];
    const float* b_patch = (const float*)d_in[7];
    const float* cw1     = (const float*)d_in[8];
    const float* cb1     = (const float*)d_in[9];
    const float* cw2     = (const float*)d_in[10];
    const float* cb2     = (const float*)d_in[11];
    const float* cw4     = (const float*)d_in[12];
    const float* cb4     = (const float*)d_in[13];
    const float* ln1g    = (const float*)d_in[14];
    const float* ln1b    = (const float*)d_in[15];
    const float* Wqkv    = (const float*)d_in[16];
    const float* Wo      = (const float*)d_in[17];
    const float* bo      = (const float*)d_in[18];
    const float* ln2g    = (const float*)d_in[19];
    const float* ln2b    = (const float*)d_in[20];
    const float* Wf1     = (const float*)d_in[21];
    const float* bf1     = (const float*)d_in[22];
    const float* Wf2     = (const float*)d_in[23];
    const float* bf2     = (const float*)d_in[24];
    const float* ssmw    = (const float*)d_in[25];
    const float* ssmb    = (const float*)d_in[26];
    const float* ssmg    = (const float*)d_in[27];
    const float* ssmbn   = (const float*)d_in[28];
    const float* W_out   = (const float*)d_in[29];
    const float* b_out   = (const float*)d_in[30];
    float* out = (float*)d_out;

    cudaFuncSetAttribute(gemm_mma_kernel, cudaFuncAttributeMaxDynamicSharedMemorySize, G2_TOTAL);

    float *h1, *hpe, *sf, *h2, *hp, *fr, *C48, *cb, *col, *h, *y, *qkv, *att, *mid, *s, *hm;
    cudaGetSymbolAddress((void**)&h1,  g_h1);
    cudaGetSymbolAddress((void**)&hpe, g_hpe);
    cudaGetSymbolAddress((void**)&sf,  g_sf);
    cudaGetSymbolAddress((void**)&h2,  g_h2);
    cudaGetSymbolAddress((void**)&hp,  g_hp);
    cudaGetSymbolAddress((void**)&fr,  g_fr);
    cudaGetSymbolAddress((void**)&C48, g_C48);
    cudaGetSymbolAddress((void**)&cb,  g_cb);
    cudaGetSymbolAddress((void**)&col, g_col);
    cudaGetSymbolAddress((void**)&h,   g_h);
    cudaGetSymbolAddress((void**)&y,   g_y);
    cudaGetSymbolAddress((void**)&qkv, g_qkv);
    cudaGetSymbolAddress((void**)&att, g_att);
    cudaGetSymbolAddress((void**)&mid, g_mid);
    cudaGetSymbolAddress((void**)&s,   g_s);
    cudaGetSymbolAddress((void**)&hm,  g_hm);

    bf16 *tWin_h, *tWin_l, *tWsh_h, *tWsh_l, *tWpa_h, *tWpa_l, *tWc_h, *tWc_l;
    bf16 *tWqkv_h, *tWqkv_l, *tWo_h, *tWo_l, *tWf1_h, *tWf1_l, *tWf2_h, *tWf2_l, *tWc2_h, *tWc2_l;
    cudaGetSymbolAddress((void**)&tWin_h,  g_tWin_h);  cudaGetSymbolAddress((void**)&tWin_l,  g_tWin_l);
    cudaGetSymbolAddress((void**)&tWsh_h,  g_tWsh_h);  cudaGetSymbolAddress((void**)&tWsh_l,  g_tWsh_l);
    cudaGetSymbolAddress((void**)&tWpa_h,  g_tWpa_h);  cudaGetSymbolAddress((void**)&tWpa_l,  g_tWpa_l);
    cudaGetSymbolAddress((void**)&tWc_h,   g_tWc_h);   cudaGetSymbolAddress((void**)&tWc_l,   g_tWc_l);
    cudaGetSymbolAddress((void**)&tWqkv_h, g_tWqkv_h); cudaGetSymbolAddress((void**)&tWqkv_l, g_tWqkv_l);
    cudaGetSymbolAddress((void**)&tWo_h,   g_tWo_h);   cudaGetSymbolAddress((void**)&tWo_l,   g_tWo_l);
    cudaGetSymbolAddress((void**)&tWf1_h,  g_tWf1_h);  cudaGetSymbolAddress((void**)&tWf1_l,  g_tWf1_l);
    cudaGetSymbolAddress((void**)&tWf2_h,  g_tWf2_h);  cudaGetSymbolAddress((void**)&tWf2_l,  g_tWf2_l);
    cudaGetSymbolAddress((void**)&tWc2_h,  g_tWc2_h);  cudaGetSymbolAddress((void**)&tWc2_l,  g_tWc2_l);

    // tables + weight prep
    init_c48_kernel<<<1, 256>>>(C48);
    tsplit(W_in,    tWin_h, tWin_l,  64, 256);
    tsplit(W_shape, tWsh_h, tWsh_l, 256, 256);
    tsplit(W_patch, tWpa_h, tWpa_l, 512, 256);
    assemble_conv_wT<<<(768 * 1024 + 255) / 256, 256>>>(cw1, cw2, cw4, cb1, cb2, cb4, tWc_h, tWc_l, cb);
    for (int i = 0; i < LL; i++) {
        tsplit(Wqkv + (size_t)i * EE * 3 * EE, tWqkv_h + (size_t)i * 3 * EE * EE, tWqkv_l + (size_t)i * 3 * EE * EE, EE, 3 * EE);
        tsplit(Wo   + (size_t)i * EE * EE,     tWo_h   + (size_t)i * EE * EE,     tWo_l   + (size_t)i * EE * EE,     EE, EE);
        tsplit(Wf1  + (size_t)i * EE * 4 * EE, tWf1_h  + (size_t)i * 4 * EE * EE, tWf1_l  + (size_t)i * 4 * EE * EE, EE, 4 * EE);
        tsplit(Wf2  + (size_t)i * 4 * EE * EE, tWf2_h  + (size_t)i * EE * 4 * EE, tWf2_l  + (size_t)i * EE * 4 * EE, 4 * EE, EE);
    }
    assemble_ssm_wT<<<(768 * 2304 + 255) / 256, 256>>>(ssmw, tWc2_h, tWc2_l);

    // embedding chain
    gemm_tc(x, tWin_h, tWin_l, h1, BB * TT, HH, DIN, b_in, nullptr, 0);
    {
        size_t tot = N_BT * HH;
        pe_diff_kernel<<<(unsigned)((tot + 255) / 256), 256>>>(h1, pe, hpe, sf);
    }
    gemm_tc(sf, tWsh_h, tWsh_l, h2, BB * TT, HH, HH, b_shape, hpe, 0);
    gemm_tc(h2, tWpa_h, tWpa_l, hp, BB * TP, HH, 2 * HH, b_patch, nullptr, 0);

    dft48_kernel<<<BB, 256>>>(hp, fr, C48);

    {
        size_t tot = N_BF * 1024;
        im2col_conv<<<(unsigned)((tot + 255) / 256), 256>>>(fr, col);
    }
    gemm_tc(col, tWc_h, tWc_l, h, (int)N_BF, EE, 1024, cb, nullptr, 0);

    // transformer layers
    for (int i = 0; i < LL; i++) {
        ln_kernel<<<(unsigned)N_BF, 256>>>(h, nullptr, ln1g + (size_t)i * EE, ln1b + (size_t)i * EE, y, EE);
        gemm_tc(y, tWqkv_h + (size_t)i * 3 * EE * EE, tWqkv_l + (size_t)i * 3 * EE * EE,
                qkv, (int)N_BF, 3 * EE, EE, nullptr, nullptr, 0);
        attn_kernel<<<BB * NHEADS, 256>>>(qkv, att);
        gemm_tc(att, tWo_h + (size_t)i * EE * EE, tWo_l + (size_t)i * EE * EE,
                h, (int)N_BF, EE, EE, bo + (size_t)i * EE, h, 0);
        ln_kernel<<<(unsigned)N_BF, 256>>>(h, nullptr, ln2g + (size_t)i * EE, ln2b + (size_t)i * EE, y, EE);
        gemm_tc(y, tWf1_h + (size_t)i * 4 * EE * EE, tWf1_l + (size_t)i * 4 * EE * EE,
                mid, (int)N_BF, 4 * EE, EE, bf1 + (size_t)i * 4 * EE, nullptr, 1);
        gemm_tc(mid, tWf2_h + (size_t)i * EE * 4 * EE, tWf2_l + (size_t)i * EE * 4 * EE,
                h, (int)N_BF, EE, 4 * EE, bf2 + (size_t)i * EE, h, 0);
    }

    // SSM conv + LN
    {
        size_t tot = N_BF * 2304;
        im2col_ssm<<<(unsigned)((tot + 255) / 256), 256>>>(h, col);
    }
    gemm_tc(col, tWc2_h, tWc2_l, s, (int)N_BF, EE, 3 * EE, ssmb, nullptr, 0);
    ln_kernel<<<(unsigned)N_BF, 256>>>(h, s, ssmg, ssmbn, h, EE);

    // mean + classifier (small, f32 path)
    mean_kernel<<<BB, EE>>>(h, hm);
    {
        dim3 grid((NCC + 127) / 128, (BB + 127) / 128);
        sgemm_kernel<<<grid, 256>>>(hm, W_out, out, BB, NCC, EE, b_out);
    }
}

// round 6
// speedup vs baseline: 2.2739x; 1.3227x over previous
#include <cuda_runtime.h>
#include <cuda_bf16.h>
#include <math.h>
#include <stdint.h>

// ---------------- problem constants ----------------
#define BB    512
#define TT    96
#define DIN   64
#define HH    256
#define LL    4
#define EE    768
#define NCC   100
#define TP    48
#define FF    25
#define NF2   13
#define DHH   96
#define NHEADS 8

#define N_BT  ((size_t)BB * TT)   // 49152
#define N_BF  ((size_t)BB * FF)   // 12800

typedef __nv_bfloat16 bf16;

// ---------------- scratch buffers ----------------
__device__ __align__(16) float g_h1 [N_BT * HH];
__device__ __align__(16) float g_hpe[N_BT * HH];
__device__ __align__(16) float g_sf [N_BT * HH];
__device__ __align__(16) float g_h2 [N_BT * HH];
__device__ __align__(16) float g_hp [(size_t)BB * TP * HH];
__device__ __align__(16) float g_fr [N_BF * HH];
__device__ __align__(16) float g_C48[FF * TP];
__device__ __align__(16) float g_cb [EE];
__device__ __align__(16) float g_col[N_BF * 2304];
__device__ __align__(16) float g_h  [N_BF * EE];
__device__ __align__(16) float g_y  [N_BF * EE];
__device__ __align__(16) float g_qkv[N_BF * 3 * EE];
__device__ __align__(16) float g_att[N_BF * EE];
__device__ __align__(16) float g_mid[N_BF * 4 * EE];
__device__ __align__(16) float g_s  [N_BF * EE];
__device__ __align__(16) float g_hm [(size_t)BB * EE];

// transposed + split weights: [N][K] bf16 hi/lo
__device__ __align__(16) bf16 g_tWin_h [256 * 64],       g_tWin_l [256 * 64];
__device__ __align__(16) bf16 g_tWsh_h [256 * 256],      g_tWsh_l [256 * 256];
__device__ __align__(16) bf16 g_tWpa_h [256 * 512],      g_tWpa_l [256 * 512];
__device__ __align__(16) bf16 g_tWc_h  [768 * 1024],     g_tWc_l  [768 * 1024];
__device__ __align__(16) bf16 g_tWqkv_h[LL * 2304 * 768],g_tWqkv_l[LL * 2304 * 768];
__device__ __align__(16) bf16 g_tWo_h  [LL * 768 * 768], g_tWo_l  [LL * 768 * 768];
__device__ __align__(16) bf16 g_tWf1_h [LL * 3072 * 768],g_tWf1_l [LL * 3072 * 768];
__device__ __align__(16) bf16 g_tWf2_h [LL * 768 * 3072],g_tWf2_l [LL * 768 * 3072];
__device__ __align__(16) bf16 g_tWc2_h [768 * 2304],     g_tWc2_l [768 * 2304];

// ---------------- helpers ----------------
__device__ __forceinline__ uint32_t smem_u32(const void* p) {
    uint32_t a;
    asm("{ .reg .u64 t; cvta.to.shared.u64 t, %1; cvt.u32.u64 %0, t; }" : "=r"(a) : "l"(p));
    return a;
}
__device__ __forceinline__ uint32_t bfpack(bf16 a, bf16 b) {
    __nv_bfloat162 t; t.x = a; t.y = b;
    return *reinterpret_cast<uint32_t*>(&t);
}

// SW128: 128B rows, xor 16B-chunk bits [4:6] with row%8 (addr bits [7:9])
#define SWZ128(x) ((x) ^ (((x) >> 3) & 0x70))

#define LDMX4(r, a) \
    asm volatile("ldmatrix.sync.aligned.m8n8.x4.shared.b16 {%0,%1,%2,%3}, [%4];" \
        : "=r"((r)[0]), "=r"((r)[1]), "=r"((r)[2]), "=r"((r)[3]) : "r"(a))
#define MMA16816(d, A, Bf) \
    asm volatile("mma.sync.aligned.m16n8k16.row.col.f32.bf16.bf16.f32 " \
        "{%0,%1,%2,%3}, {%4,%5,%6,%7}, {%8,%9}, {%0,%1,%2,%3};" \
        : "+f"((d)[0]), "+f"((d)[1]), "+f"((d)[2]), "+f"((d)[3]) \
        : "r"((A)[0]), "r"((A)[1]), "r"((A)[2]), "r"((A)[3]), "r"((Bf)[0]), "r"((Bf)[1]))

#define CP_ASYNC16(dst, src) \
    asm volatile("cp.async.cg.shared.global [%0], [%1], 16;" :: "r"(dst), "l"(src))
#define CP_COMMIT()  asm volatile("cp.async.commit_group;" ::: "memory")
#define CP_WAIT0()   asm volatile("cp.async.wait_group 0;" ::: "memory")

__device__ __forceinline__ void split4(float4 v, uint2& hv, uint2& lv) {
    bf16 h0 = __float2bfloat16(v.x), h1 = __float2bfloat16(v.y);
    bf16 h2 = __float2bfloat16(v.z), h3 = __float2bfloat16(v.w);
    bf16 l0 = __float2bfloat16(v.x - __bfloat162float(h0));
    bf16 l1 = __float2bfloat16(v.y - __bfloat162float(h1));
    bf16 l2 = __float2bfloat16(v.z - __bfloat162float(h2));
    bf16 l3 = __float2bfloat16(v.w - __bfloat162float(h3));
    hv = make_uint2(bfpack(h0, h1), bfpack(h2, h3));
    lv = make_uint2(bfpack(l0, l1), bfpack(l2, l3));
}

// ---------------- HMMA GEMM: C[M,N] = act(A f32 @ B^T(split bf16) + bias + res)
// M%128==0, N%128==0, K%32==0
// Per buffer: A tile 128 rows x [hi 64B | lo 64B] = 16KB, B tile same. 2 buffers = 64KB.
#define G3_A     0
#define G3_B     16384
#define G3_BUF   32768
#define G3_TOTAL 65536

__global__ void __launch_bounds__(256, 2)
gemm_mma_kernel(const float* __restrict__ A,
                const bf16* __restrict__ Bhi, const bf16* __restrict__ Blo,
                float* __restrict__ C, int M, int N, int K,
                const float* __restrict__ bias, const float* __restrict__ res, int act)
{
    extern __shared__ char smem[];
    const uint32_t sb = smem_u32(smem);
    const int tid  = threadIdx.x;
    const int lane = tid & 31;
    const int wid  = tid >> 5;
    const int wm   = wid & 1;       // 2 warp-rows (64 rows)
    const int wn   = wid >> 1;      // 4 warp-cols (32 cols)
    const int m0 = blockIdx.y * 128;
    const int n0 = blockIdx.x * 128;

    const int ldRow  = tid >> 1;    // 0..127
    const int ldHalf = tid & 1;

    float acc[4][4][4];
#pragma unroll
    for (int i = 0; i < 4; i++)
#pragma unroll
        for (int j = 0; j < 4; j++)
#pragma unroll
            for (int e = 0; e < 4; e++) acc[i][j][e] = 0.f;

    const int nk = K >> 5;

    // unswizzled per-lane fragment bases; +kk*32 (+64 for lo) added BEFORE swizzle
    const uint32_t aBase = (uint32_t)(wm * 64 + (lane & 15)) * 128u + (uint32_t)(lane >> 4) * 16u;
    const uint32_t bBase = (uint32_t)(wn * 32 + (lane >> 4) * 8 + (lane & 7)) * 128u
                         + (uint32_t)((lane >> 3) & 1) * 16u;

    uint2 ahv[4], alv[4];   // A prefetch (split)

    // ---- helpers (lambdas keep register scope tight) ----
    auto cpasyncB = [&](int kc, uint32_t bufb) {
        const bf16* Bh = Bhi + (size_t)(n0 + ldRow) * K + kc * 32;
        const bf16* Bl = Blo + (size_t)(n0 + ldRow) * K + kc * 32;
#pragma unroll
        for (int j = 0; j < 2; j++) {
            int c = ldHalf * 2 + j;
            uint32_t dh = sb + bufb + G3_B + SWZ128((uint32_t)ldRow * 128u + (uint32_t)c * 16u);
            CP_ASYNC16(dh, Bh + c * 8);
            uint32_t dl = sb + bufb + G3_B + SWZ128((uint32_t)ldRow * 128u + 64u + (uint32_t)c * 16u);
            CP_ASYNC16(dl, Bl + c * 8);
        }
    };
    auto prefA = [&](int kc) {
        const float* Ab = A + (size_t)(m0 + ldRow) * K + kc * 32 + ldHalf * 16;
#pragma unroll
        for (int p = 0; p < 4; p++) {
            float4 v = *reinterpret_cast<const float4*>(Ab + p * 4);
            split4(v, ahv[p], alv[p]);
        }
    };
    auto stsA = [&](uint32_t bufb) {
        char* base = smem + bufb + G3_A;
#pragma unroll
        for (int p = 0; p < 4; p++) {
            uint32_t oh = SWZ128((uint32_t)ldRow * 128u + (uint32_t)(ldHalf * 32 + p * 8));
            uint32_t ol = SWZ128((uint32_t)ldRow * 128u + 64u + (uint32_t)(ldHalf * 32 + p * 8));
            *reinterpret_cast<uint2*>(base + oh) = ahv[p];
            *reinterpret_cast<uint2*>(base + ol) = alv[p];
        }
    };

    // ---- prologue ----
    cpasyncB(0, 0);
    CP_COMMIT();
    prefA(0);
    stsA(0);
    CP_WAIT0();
    __syncthreads();

    for (int kc = 0; kc < nk; kc++) {
        const uint32_t bufo = (uint32_t)(kc & 1) * G3_BUF;
        const uint32_t nbuf = (uint32_t)((kc + 1) & 1) * G3_BUF;
        if (kc + 1 < nk) {
            prefA(kc + 1);
            cpasyncB(kc + 1, nbuf);
            CP_COMMIT();
        }
        // compute current chunk: two k16 steps
#pragma unroll
        for (int kk = 0; kk < 2; kk++) {
            const uint32_t kb = (uint32_t)kk * 32u;
            const uint32_t aHiSw = SWZ128(aBase + kb);
            const uint32_t aLoSw = SWZ128(aBase + kb + 64u);
            const uint32_t bHiSw = SWZ128(bBase + kb);
            const uint32_t bLoSw = SWZ128(bBase + kb + 64u);
            uint32_t bh4[2][4], bl4[2][4];
#pragma unroll
            for (int ni2 = 0; ni2 < 2; ni2++) {
                uint32_t b_addr = sb + bufo + G3_B + (uint32_t)(ni2 * 2048);
                LDMX4(bh4[ni2], b_addr + bHiSw);
                LDMX4(bl4[ni2], b_addr + bLoSw);
            }
#pragma unroll
            for (int mi = 0; mi < 4; mi++) {
                uint32_t ah[4], al[4];
                uint32_t a_addr = sb + bufo + G3_A + (uint32_t)(mi * 2048);
                LDMX4(ah, a_addr + aHiSw);
                LDMX4(al, a_addr + aLoSw);
#pragma unroll
                for (int ni = 0; ni < 4; ni++) {
                    const uint32_t* Bh_ = &bh4[ni >> 1][(ni & 1) * 2];
                    const uint32_t* Bl_ = &bl4[ni >> 1][(ni & 1) * 2];
                    MMA16816(acc[mi][ni], ah, Bh_);
                    MMA16816(acc[mi][ni], ah, Bl_);
                    MMA16816(acc[mi][ni], al, Bh_);
                }
            }
        }
        if (kc + 1 < nk) stsA(nbuf);
        CP_WAIT0();
        __syncthreads();
    }

    // epilogue: stage 64 rows at a time (stride 132), coalesced gmem store
    float* stg = reinterpret_cast<float*>(smem);
#pragma unroll
    for (int half = 0; half < 2; half++) {
        __syncthreads();
        if (wm == half) {
#pragma unroll
            for (int mi = 0; mi < 4; mi++) {
#pragma unroll
                for (int ni = 0; ni < 4; ni++) {
                    int r = mi * 16 + (lane >> 2);
                    int c = wn * 32 + ni * 8 + (lane & 3) * 2;
                    stg[r * 132 + c]           = acc[mi][ni][0];
                    stg[r * 132 + c + 1]       = acc[mi][ni][1];
                    stg[(r + 8) * 132 + c]     = acc[mi][ni][2];
                    stg[(r + 8) * 132 + c + 1] = acc[mi][ni][3];
                }
            }
        }
        __syncthreads();
#pragma unroll 4
        for (int it = 0; it < 32; it++) {
            int idx = it * 256 + tid;
            int r = idx >> 7, c = idx & 127;
            float v = stg[r * 132 + c];
            int gn = n0 + c;
            size_t gr = (size_t)(m0 + half * 64 + r);
            if (bias) v += bias[gn];
            if (res)  v += res[gr * N + gn];
            if (act)  v = 0.5f * v * (1.0f + erff(v * 0.70710678118654752f));
            C[gr * N + gn] = v;
        }
    }
}

// ---------------- fallback f32 SGEMM (classifier only) ----------------
__global__ void __launch_bounds__(256, 2)
sgemm_kernel(const float* __restrict__ A, const float* __restrict__ B,
             float* __restrict__ C, int M, int N, int K,
             const float* __restrict__ bias)
{
    __shared__ float As[8][128];
    __shared__ float Bs[8][128];
    const int tid = threadIdx.x;
    const int row0 = blockIdx.y * 128, col0 = blockIdx.x * 128;
    const int tx = tid & 15, ty = tid >> 4;
    const int arow = tid >> 1, acol = (tid & 1) * 4;
    const int brow = tid >> 5, bcol = (tid & 31) * 4;
    float acc[8][8];
#pragma unroll
    for (int i = 0; i < 8; i++)
#pragma unroll
        for (int j = 0; j < 8; j++) acc[i][j] = 0.f;
    const int gar = row0 + arow, gbc = col0 + bcol;
    const bool aok = (gar < M), bok = (gbc < N);
    for (int k0 = 0; k0 < K; k0 += 8) {
        float4 avv = make_float4(0, 0, 0, 0);
        if (aok) avv = *reinterpret_cast<const float4*>(&A[(size_t)gar * K + k0 + acol]);
        As[acol + 0][arow] = avv.x; As[acol + 1][arow] = avv.y;
        As[acol + 2][arow] = avv.z; As[acol + 3][arow] = avv.w;
        float4 bv = make_float4(0, 0, 0, 0);
        if (bok) bv = *reinterpret_cast<const float4*>(&B[(size_t)(k0 + brow) * N + gbc]);
        *reinterpret_cast<float4*>(&Bs[brow][bcol]) = bv;
        __syncthreads();
#pragma unroll
        for (int kk = 0; kk < 8; kk++) {
            float4 ra0 = *reinterpret_cast<const float4*>(&As[kk][ty * 8 + 0]);
            float4 ra1 = *reinterpret_cast<const float4*>(&As[kk][ty * 8 + 4]);
            float4 rb0 = *reinterpret_cast<const float4*>(&Bs[kk][tx * 8 + 0]);
            float4 rb1 = *reinterpret_cast<const float4*>(&Bs[kk][tx * 8 + 4]);
            float ra[8] = {ra0.x, ra0.y, ra0.z, ra0.w, ra1.x, ra1.y, ra1.z, ra1.w};
            float rb[8] = {rb0.x, rb0.y, rb0.z, rb0.w, rb1.x, rb1.y, rb1.z, rb1.w};
#pragma unroll
            for (int i = 0; i < 8; i++)
#pragma unroll
                for (int j = 0; j < 8; j++) acc[i][j] = fmaf(ra[i], rb[j], acc[i][j]);
        }
        __syncthreads();
    }
#pragma unroll
    for (int i = 0; i < 8; i++) {
        const int r = row0 + ty * 8 + i;
        if (r >= M) continue;
#pragma unroll
        for (int j = 0; j < 8; j++) {
            const int c = col0 + tx * 8 + j;
            if (c >= N) continue;
            float v = acc[i][j];
            if (bias) v += bias[c];
            C[(size_t)r * N + c] = v;
        }
    }
}

// ---------------- weight transpose + split ----------------
__global__ void tsplit_kernel(const float* __restrict__ W, bf16* __restrict__ hi,
                              bf16* __restrict__ lo, int K, int N)
{
    __shared__ float t[32][33];
    int k0 = blockIdx.y * 32, n0 = blockIdx.x * 32;
    int tx = threadIdx.x, ty = threadIdx.y;
#pragma unroll
    for (int r = 0; r < 4; r++) {
        int k = k0 + ty + r * 8;
        t[ty + r * 8][tx] = (k < K && n0 + tx < N) ? W[(size_t)k * N + n0 + tx] : 0.f;
    }
    __syncthreads();
#pragma unroll
    for (int r = 0; r < 4; r++) {
        int n = n0 + ty + r * 8, k = k0 + tx;
        if (n < N && k < K) {
            float v = t[tx][ty + r * 8];
            bf16 h = __float2bfloat16(v);
            hi[(size_t)n * K + k] = h;
            lo[(size_t)n * K + k] = __float2bfloat16(v - __bfloat162float(h));
        }
    }
}

__global__ void assemble_conv_wT(const float* __restrict__ w1, const float* __restrict__ w2,
                                 const float* __restrict__ w4, const float* __restrict__ b1,
                                 const float* __restrict__ b2, const float* __restrict__ b4,
                                 bf16* __restrict__ hi, bf16* __restrict__ lo,
                                 float* __restrict__ cb)
{
    int idx = blockIdx.x * blockDim.x + threadIdx.x;
    if (idx < EE) cb[idx] = (idx < 256) ? b1[idx] : (idx < 512 ? b2[idx - 256] : b4[idx - 512]);
    if (idx >= 768 * 1024) return;
    int n = idx / 1024, k = idx % 1024;
    int i = k % 256, d = k / 256;
    float v = 0.f;
    if (n < 256)      { if (d == 1) v = w1[n * 256 + i]; }
    else if (n < 512) { int oo = n - 256; int j = d - 1; if (j == 0 || j == 1) v = w2[oo * 512 + i * 2 + j]; }
    else              { int oo = n - 512; v = w4[oo * 1024 + i * 4 + d]; }
    bf16 h = __float2bfloat16(v);
    hi[idx] = h;
    lo[idx] = __float2bfloat16(v - __bfloat162float(h));
}

__global__ void assemble_ssm_wT(const float* __restrict__ w, bf16* __restrict__ hi,
                                bf16* __restrict__ lo)
{
    int idx = blockIdx.x * blockDim.x + threadIdx.x;
    if (idx >= 768 * 2304) return;
    int n = idx / 2304, k = idx % 2304;
    int i = k % 768, j = k / 768;
    float v = w[(size_t)n * 2304 + i * 3 + j];
    bf16 h = __float2bfloat16(v);
    hi[idx] = h;
    lo[idx] = __float2bfloat16(v - __bfloat162float(h));
}

// ---------------- small kernels ----------------
__global__ void init_c48_kernel(float* __restrict__ C48) {
    for (int i = threadIdx.x; i < FF * TP; i += blockDim.x) {
        int k = i / TP, t = i % TP;
        int m = (k * t) % TP;
        C48[i] = cospif(2.0f * (float)m / (float)TP);
    }
}

__global__ void pe_diff_kernel(const float* __restrict__ h1, const float* __restrict__ pe,
                               float* __restrict__ hpe, float* __restrict__ sf)
{
    size_t idx = (size_t)blockIdx.x * blockDim.x + threadIdx.x;
    const size_t total = N_BT * HH;
    if (idx >= total) return;
    int c = (int)(idx % HH);
    size_t r = idx / HH;
    int t = (int)(r % TT);
    float cur = h1[idx] + pe[(size_t)t * HH + c];
    hpe[idx] = cur;
    float prev = (t == 0) ? cur : (h1[idx - HH] + pe[(size_t)(t - 1) * HH + c]);
    sf[idx] = cur - prev;
}

__global__ void __launch_bounds__(256) dft48_kernel(const float* __restrict__ hp,
                                                    float* __restrict__ out,
                                                    const float* __restrict__ C48)
{
    __shared__ float sC[FF * TP];
    int b = blockIdx.x;
    for (int i = threadIdx.x; i < FF * TP; i += 256) sC[i] = C48[i];
    float r[TP];
    const float* base = hp + (size_t)b * TP * HH + threadIdx.x;
#pragma unroll
    for (int t = 0; t < TP; t++) r[t] = base[(size_t)t * HH];
    __syncthreads();
    float* ob = out + (size_t)b * FF * HH + threadIdx.x;
    for (int k = 0; k < FF; k++) {
        float acc = 0.f;
#pragma unroll
        for (int t = 0; t < TP; t++) acc = fmaf(r[t], sC[k * TP + t], acc);
        ob[(size_t)k * HH] = acc;
    }
}

__global__ void im2col_conv(const float* __restrict__ f, float* __restrict__ col) {
    size_t idx = (size_t)blockIdx.x * blockDim.x + threadIdx.x;
    const size_t total = N_BF * 1024;
    if (idx >= total) return;
    int kk = (int)(idx % 1024);
    size_t row = idx / 1024;
    int i = kk % 256, d = kk / 256;
    int fq = (int)(row % FF);
    size_t b = row / FF;
    int src = fq + d - 1;
    col[idx] = (src >= 0 && src < FF) ? f[((size_t)b * FF + src) * HH + i] : 0.f;
}

__global__ void im2col_ssm(const float* __restrict__ h, float* __restrict__ col) {
    size_t idx = (size_t)blockIdx.x * blockDim.x + threadIdx.x;
    const size_t total = N_BF * 2304;
    if (idx >= total) return;
    int kk = (int)(idx % 2304);
    size_t row = idx / 2304;
    int i = kk % EE, j = kk / EE;
    int fq = (int)(row % FF);
    size_t b = row / FF;
    int src = fq + j - 1;
    col[idx] = (src >= 0 && src < FF) ? h[((size_t)b * FF + src) * EE + i] : 0.f;
}

__global__ void __launch_bounds__(256) ln_kernel(const float* __restrict__ x,
                                                 const float* __restrict__ add,
                                                 const float* __restrict__ g,
                                                 const float* __restrict__ bta,
                                                 float* __restrict__ y, int C)
{
    int row = blockIdx.x;
    const float* xr = x + (size_t)row * C;
    const float* ar = add ? add + (size_t)row * C : nullptr;
    float s = 0.f, q = 0.f;
    for (int c = threadIdx.x; c < C; c += 256) {
        float v = xr[c] + (ar ? ar[c] : 0.f);
        s += v; q += v * v;
    }
#pragma unroll
    for (int o = 16; o; o >>= 1) {
        s += __shfl_xor_sync(~0u, s, o);
        q += __shfl_xor_sync(~0u, q, o);
    }
    __shared__ float ss[8], sq[8];
    int w = threadIdx.x >> 5, l = threadIdx.x & 31;
    if (l == 0) { ss[w] = s; sq[w] = q; }
    __syncthreads();
    if (threadIdx.x == 0) {
        float ts = 0.f, tq = 0.f;
        for (int i = 0; i < 8; i++) { ts += ss[i]; tq += sq[i]; }
        ss[0] = ts; sq[0] = tq;
    }
    __syncthreads();
    float mean = ss[0] / C;
    float var = sq[0] / C - mean * mean;
    float inv = rsqrtf(var + 1e-5f);
    for (int c = threadIdx.x; c < C; c += 256) {
        float v = xr[c] + (ar ? ar[c] : 0.f);
        y[(size_t)row * C + c] = (v - mean) * inv * g[c] + bta[c];
    }
}

__global__ void __launch_bounds__(256) attn_kernel(const float* __restrict__ qkv,
                                                   float* __restrict__ out)
{
    __shared__ float sq_[FF][DHH], sk_[FF][DHH], sv_[FF][DHH];
    __shared__ float G[FF][FF];
    __shared__ float ctab[FF];
    __shared__ float sa[NF2];
    __shared__ float kt[FF];
    int bh = blockIdx.x;
    int b = bh >> 3, hh = bh & 7;
    int tid = threadIdx.x;
    const float* base = qkv + ((size_t)b * FF) * (3 * EE) + hh * DHH;
    for (int idx = tid; idx < FF * DHH; idx += 256) {
        int t = idx / DHH, d = idx % DHH;
        size_t off = (size_t)t * (3 * EE) + d;
        sq_[t][d] = base[off];
        sk_[t][d] = base[off + EE];
        sv_[t][d] = base[off + 2 * EE];
    }
    if (tid < FF) ctab[tid] = cospif(2.0f * (float)tid / 25.0f);
    __syncthreads();
    for (int e = tid; e < FF * FF; e += 256) {
        int t = e / FF, s2 = e % FF;
        float acc = 0.f;
#pragma unroll 8
        for (int d = 0; d < DHH; d++) acc = fmaf(sq_[t][d], sk_[s2][d], acc);
        G[t][s2] = acc;
    }
    __syncthreads();
    if (tid < NF2) {
        float acc = 0.f;
        for (int t = 0; t < FF; t++)
            for (int s2 = 0; s2 < FF; s2++)
                acc = fmaf(G[t][s2], ctab[(tid * (t - s2 + FF)) % FF], acc);
        sa[tid] = acc * 0.10206207261596575f;
    }
    __syncthreads();
    if (tid == 0) {
        float mx = sa[0];
        for (int f = 1; f < NF2; f++) mx = fmaxf(mx, sa[f]);
        float e_[NF2], sum = 0.f;
        for (int f = 0; f < NF2; f++) { e_[f] = expf(sa[f] - mx); sum += e_[f]; }
        float inv = 1.0f / sum;
        for (int f = 0; f < NF2; f++) sa[f] = e_[f] * inv;
    }
    __syncthreads();
    if (tid < FF) {
        float acc = sa[0];
        for (int f = 1; f < NF2; f++) acc = fmaf(2.0f * sa[f], ctab[(f * tid) % FF], acc);
        kt[tid] = acc * 0.04f;
    }
    __syncthreads();
    float* obase = out + ((size_t)b * FF) * EE + hh * DHH;
    for (int idx = tid; idx < FF * DHH; idx += 256) {
        int t = idx / DHH, d = idx % DHH;
        float acc = 0.f;
#pragma unroll
        for (int s2 = 0; s2 < FF; s2++)
            acc = fmaf(kt[(t - s2 + FF) % FF], sv_[s2][d], acc);
        obase[(size_t)t * EE + d] = acc;
    }
}

__global__ void mean_kernel(const float* __restrict__ h, float* __restrict__ hm) {
    int b = blockIdx.x;
    int c = threadIdx.x;
    float acc = 0.f;
#pragma unroll
    for (int f = 0; f < FF; f++) acc += h[((size_t)b * FF + f) * EE + c];
    hm[(size_t)b * EE + c] = acc * 0.04f;
}

// ---------------- host helpers ----------------
static inline void gemm_tc(const float* A, const bf16* bh, const bf16* bl, float* C,
                           int M, int N, int K, const float* bias, const float* res, int act)
{
    dim3 grid(N / 128, M / 128);
    gemm_mma_kernel<<<grid, 256, G3_TOTAL>>>(A, bh, bl, C, M, N, K, bias, res, act);
}
static inline void tsplit(const float* W, bf16* hi, bf16* lo, int K, int N) {
    dim3 grid((N + 31) / 32, (K + 31) / 32);
    tsplit_kernel<<<grid, dim3(32, 8)>>>(W, hi, lo, K, N);
}

extern "C" void kernel_launch(void* const* d_in, const int* in_sizes, int n_in,
                              void* d_out, int out_size)
{
    const float* x       = (const float*)d_in[0];
    const float* W_in    = (const float*)d_in[1];
    const float* b_in    = (const float*)d_in[2];
    const float* pe      = (const float*)d_in[3];
    const float* W_shape = (const float*)d_in[4];
    const float* b_shape = (const float*)d_in[5];
    const float* W_patch = (const float*)d_in[6];
    const float* b_patch = (const float*)d_in[7];
    const float* cw1     = (const float*)d_in[8];
    const float* cb1     = (const float*)d_in[9];
    const float* cw2     = (const float*)d_in[10];
    const float* cb2     = (const float*)d_in[11];
    const float* cw4     = (const float*)d_in[12];
    const float* cb4     = (const float*)d_in[13];
    const float* ln1g    = (const float*)d_in[14];
    const float* ln1b    = (const float*)d_in[15];
    const float* Wqkv    = (const float*)d_in[16];
    const float* Wo      = (const float*)d_in[17];
    const float* bo      = (const float*)d_in[18];
    const float* ln2g    = (const float*)d_in[19];
    const float* ln2b    = (const float*)d_in[20];
    const float* Wf1     = (const float*)d_in[21];
    const float* bf1     = (const float*)d_in[22];
    const float* Wf2     = (const float*)d_in[23];
    const float* bf2     = (const float*)d_in[24];
    const float* ssmw    = (const float*)d_in[25];
    const float* ssmb    = (const float*)d_in[26];
    const float* ssmg    = (const float*)d_in[27];
    const float* ssmbn   = (const float*)d_in[28];
    const float* W_out   = (const float*)d_in[29];
    const float* b_out   = (const float*)d_in[30];
    float* out = (float*)d_out;

    cudaFuncSetAttribute(gemm_mma_kernel, cudaFuncAttributeMaxDynamicSharedMemorySize, G3_TOTAL);

    float *h1, *hpe, *sf, *h2, *hp, *fr, *C48, *cb, *col, *h, *y, *qkv, *att, *mid, *s, *hm;
    cudaGetSymbolAddress((void**)&h1,  g_h1);
    cudaGetSymbolAddress((void**)&hpe, g_hpe);
    cudaGetSymbolAddress((void**)&sf,  g_sf);
    cudaGetSymbolAddress((void**)&h2,  g_h2);
    cudaGetSymbolAddress((void**)&hp,  g_hp);
    cudaGetSymbolAddress((void**)&fr,  g_fr);
    cudaGetSymbolAddress((void**)&C48, g_C48);
    cudaGetSymbolAddress((void**)&cb,  g_cb);
    cudaGetSymbolAddress((void**)&col, g_col);
    cudaGetSymbolAddress((void**)&h,   g_h);
    cudaGetSymbolAddress((void**)&y,   g_y);
    cudaGetSymbolAddress((void**)&qkv, g_qkv);
    cudaGetSymbolAddress((void**)&att, g_att);
    cudaGetSymbolAddress((void**)&mid, g_mid);
    cudaGetSymbolAddress((void**)&s,   g_s);
    cudaGetSymbolAddress((void**)&hm,  g_hm);

    bf16 *tWin_h, *tWin_l, *tWsh_h, *tWsh_l, *tWpa_h, *tWpa_l, *tWc_h, *tWc_l;
    bf16 *tWqkv_h, *tWqkv_l, *tWo_h, *tWo_l, *tWf1_h, *tWf1_l, *tWf2_h, *tWf2_l, *tWc2_h, *tWc2_l;
    cudaGetSymbolAddress((void**)&tWin_h,  g_tWin_h);  cudaGetSymbolAddress((void**)&tWin_l,  g_tWin_l);
    cudaGetSymbolAddress((void**)&tWsh_h,  g_tWsh_h);  cudaGetSymbolAddress((void**)&tWsh_l,  g_tWsh_l);
    cudaGetSymbolAddress((void**)&tWpa_h,  g_tWpa_h);  cudaGetSymbolAddress((void**)&tWpa_l,  g_tWpa_l);
    cudaGetSymbolAddress((void**)&tWc_h,   g_tWc_h);   cudaGetSymbolAddress((void**)&tWc_l,   g_tWc_l);
    cudaGetSymbolAddress((void**)&tWqkv_h, g_tWqkv_h); cudaGetSymbolAddress((void**)&tWqkv_l, g_tWqkv_l);
    cudaGetSymbolAddress((void**)&tWo_h,   g_tWo_h);   cudaGetSymbolAddress((void**)&tWo_l,   g_tWo_l);
    cudaGetSymbolAddress((void**)&tWf1_h,  g_tWf1_h);  cudaGetSymbolAddress((void**)&tWf1_l,  g_tWf1_l);
    cudaGetSymbolAddress((void**)&tWf2_h,  g_tWf2_h);  cudaGetSymbolAddress((void**)&tWf2_l,  g_tWf2_l);
    cudaGetSymbolAddress((void**)&tWc2_h,  g_tWc2_h);  cudaGetSymbolAddress((void**)&tWc2_l,  g_tWc2_l);

    // tables + weight prep
    init_c48_kernel<<<1, 256>>>(C48);
    tsplit(W_in,    tWin_h, tWin_l,  64, 256);
    tsplit(W_shape, tWsh_h, tWsh_l, 256, 256);
    tsplit(W_patch, tWpa_h, tWpa_l, 512, 256);
    assemble_conv_wT<<<(768 * 1024 + 255) / 256, 256>>>(cw1, cw2, cw4, cb1, cb2, cb4, tWc_h, tWc_l, cb);
    for (int i = 0; i < LL; i++) {
        tsplit(Wqkv + (size_t)i * EE * 3 * EE, tWqkv_h + (size_t)i * 3 * EE * EE, tWqkv_l + (size_t)i * 3 * EE * EE, EE, 3 * EE);
        tsplit(Wo   + (size_t)i * EE * EE,     tWo_h   + (size_t)i * EE * EE,     tWo_l   + (size_t)i * EE * EE,     EE, EE);
        tsplit(Wf1  + (size_t)i * EE * 4 * EE, tWf1_h  + (size_t)i * 4 * EE * EE, tWf1_l  + (size_t)i * 4 * EE * EE, EE, 4 * EE);
        tsplit(Wf2  + (size_t)i * 4 * EE * EE, tWf2_h  + (size_t)i * EE * 4 * EE, tWf2_l  + (size_t)i * EE * 4 * EE, 4 * EE, EE);
    }
    assemble_ssm_wT<<<(768 * 2304 + 255) / 256, 256>>>(ssmw, tWc2_h, tWc2_l);

    // embedding chain
    gemm_tc(x, tWin_h, tWin_l, h1, BB * TT, HH, DIN, b_in, nullptr, 0);
    {
        size_t tot = N_BT * HH;
        pe_diff_kernel<<<(unsigned)((tot + 255) / 256), 256>>>(h1, pe, hpe, sf);
    }
    gemm_tc(sf, tWsh_h, tWsh_l, h2, BB * TT, HH, HH, b_shape, hpe, 0);
    gemm_tc(h2, tWpa_h, tWpa_l, hp, BB * TP, HH, 2 * HH, b_patch, nullptr, 0);

    dft48_kernel<<<BB, 256>>>(hp, fr, C48);

    {
        size_t tot = N_BF * 1024;
        im2col_conv<<<(unsigned)((tot + 255) / 256), 256>>>(fr, col);
    }
    gemm_tc(col, tWc_h, tWc_l, h, (int)N_BF, EE, 1024, cb, nullptr, 0);

    // transformer layers
    for (int i = 0; i < LL; i++) {
        ln_kernel<<<(unsigned)N_BF, 256>>>(h, nullptr, ln1g + (size_t)i * EE, ln1b + (size_t)i * EE, y, EE);
        gemm_tc(y, tWqkv_h + (size_t)i * 3 * EE * EE, tWqkv_l + (size_t)i * 3 * EE * EE,
                qkv, (int)N_BF, 3 * EE, EE, nullptr, nullptr, 0);
        attn_kernel<<<BB * NHEADS, 256>>>(qkv, att);
        gemm_tc(att, tWo_h + (size_t)i * EE * EE, tWo_l + (size_t)i * EE * EE,
                h, (int)N_BF, EE, EE, bo + (size_t)i * EE, h, 0);
        ln_kernel<<<(unsigned)N_BF, 256>>>(h, nullptr, ln2g + (size_t)i * EE, ln2b + (size_t)i * EE, y, EE);
        gemm_tc(y, tWf1_h + (size_t)i * 4 * EE * EE, tWf1_l + (size_t)i * 4 * EE * EE,
                mid, (int)N_BF, 4 * EE, EE, bf1 + (size_t)i * 4 * EE, nullptr, 1);
        gemm_tc(mid, tWf2_h + (size_t)i * EE * 4 * EE, tWf2_l + (size_t)i * EE * 4 * EE,
                h, (int)N_BF, EE, 4 * EE, bf2 + (size_t)i * EE, h, 0);
    }

    // SSM conv + LN
    {
        size_t tot = N_BF * 2304;
        im2col_ssm<<<(unsigned)((tot + 255) / 256), 256>>>(h, col);
    }
    gemm_tc(col, tWc2_h, tWc2_l, s, (int)N_BF, EE, 3 * EE, ssmb, nullptr, 0);
    ln_kernel<<<(unsigned)N_BF, 256>>>(h, s, ssmg, ssmbn, h, EE);

    // mean + classifier (small, f32 path)
    mean_kernel<<<BB, EE>>>(h, hm);
    {
        dim3 grid((NCC + 127) / 128, (BB + 127) / 128);
        sgemm_kernel<<<grid, 256>>>(hm, W_out, out, BB, NCC, EE, b_out);
    }
}

// round 8
// speedup vs baseline: 2.4770x; 1.0893x over previous
#include <cuda_runtime.h>
#include <cuda_fp16.h>
#include <math.h>
#include <stdint.h>

// ---------------- problem constants ----------------
#define BB    512
#define TT    96
#define DIN   64
#define HH    256
#define LL    4
#define EE    768
#define NCC   100
#define TP    48
#define FF    25
#define NF2   13
#define DHH   96
#define NHEADS 8

#define N_BT  ((size_t)BB * TT)   // 49152
#define N_BF  ((size_t)BB * FF)   // 12800

// merged-residual split constant c = 1/64; final scale 64/65
#define SPLIT_C63_64  0.984375f
#define FINAL_SCALE   0.9846153846153846f

// ---------------- scratch buffers ----------------
__device__ __align__(16) float g_h1 [N_BT * HH];
__device__ __align__(16) float g_hpe[N_BT * HH];
__device__ __align__(16) float g_sf [N_BT * HH];
__device__ __align__(16) float g_h2 [N_BT * HH];
__device__ __align__(16) float g_hp [(size_t)BB * TP * HH];
__device__ __align__(16) float g_fr [N_BF * HH];
__device__ __align__(16) float g_C48[FF * TP];
__device__ __align__(16) float g_cb [EE];
__device__ __align__(16) float g_col[N_BF * 2304];
__device__ __align__(16) float g_h  [N_BF * EE];
__device__ __align__(16) float g_y  [N_BF * EE];
__device__ __align__(16) float g_qkv[N_BF * 3 * EE];
__device__ __align__(16) float g_att[N_BF * EE];
__device__ __align__(16) float g_mid[N_BF * 4 * EE];
__device__ __align__(16) float g_s  [N_BF * EE];
__device__ __align__(16) float g_hm [(size_t)BB * EE];

// transposed fp16 weights [N][K]: _h = RN(W), _2 = RN(Wh + 64*(W - Wh))
__device__ __align__(16) __half g_tWin_h [256 * 64],       g_tWin_2 [256 * 64];
__device__ __align__(16) __half g_tWsh_h [256 * 256],      g_tWsh_2 [256 * 256];
__device__ __align__(16) __half g_tWpa_h [256 * 512],      g_tWpa_2 [256 * 512];
__device__ __align__(16) __half g_tWc_h  [768 * 1024],     g_tWc_2  [768 * 1024];
__device__ __align__(16) __half g_tWqkv_h[LL * 2304 * 768],g_tWqkv_2[LL * 2304 * 768];
__device__ __align__(16) __half g_tWo_h  [LL * 768 * 768], g_tWo_2  [LL * 768 * 768];
__device__ __align__(16) __half g_tWf1_h [LL * 3072 * 768],g_tWf1_2 [LL * 3072 * 768];
__device__ __align__(16) __half g_tWf2_h [LL * 768 * 3072],g_tWf2_2 [LL * 768 * 3072];
__device__ __align__(16) __half g_tWc2_h [768 * 2304],     g_tWc2_2 [768 * 2304];

// ---------------- helpers ----------------
__device__ __forceinline__ uint32_t smem_u32(const void* p) {
    uint32_t a;
    asm("{ .reg .u64 t; cvta.to.shared.u64 t, %1; cvt.u32.u64 %0, t; }" : "=r"(a) : "l"(p));
    return a;
}
__device__ __forceinline__ uint32_t hpack(__half a, __half b) {
    __half2 t; t.x = a; t.y = b;
    return *reinterpret_cast<uint32_t*>(&t);
}

// SW128: 128B rows, xor 16B-chunk bits [4:6] with row%8 (addr bits [7:9])
#define SWZ128(x) ((x) ^ (((x) >> 3) & 0x70))

#define LDMX4(r, a) \
    asm volatile("ldmatrix.sync.aligned.m8n8.x4.shared.b16 {%0,%1,%2,%3}, [%4];" \
        : "=r"((r)[0]), "=r"((r)[1]), "=r"((r)[2]), "=r"((r)[3]) : "r"(a))
#define MMA16816(d, A, Bf) \
    asm volatile("mma.sync.aligned.m16n8k16.row.col.f32.f16.f16.f32 " \
        "{%0,%1,%2,%3}, {%4,%5,%6,%7}, {%8,%9}, {%0,%1,%2,%3};" \
        : "+f"((d)[0]), "+f"((d)[1]), "+f"((d)[2]), "+f"((d)[3]) \
        : "r"((A)[0]), "r"((A)[1]), "r"((A)[2]), "r"((A)[3]), "r"((Bf)[0]), "r"((Bf)[1]))

#define CP_ASYNC16(dst, src) \
    asm volatile("cp.async.cg.shared.global [%0], [%1], 16;" :: "r"(dst), "l"(src))
#define CP_COMMIT()  asm volatile("cp.async.commit_group;" ::: "memory")
#define CP_WAIT0()   asm volatile("cp.async.wait_group 0;" ::: "memory")

// A split: x1 = RN(a), x2 = RN(a - (63/64)*float(x1)) = Alo + Ahi/64
__device__ __forceinline__ void splitA(float4 v, uint2& x1v, uint2& x2v) {
    __half h0 = __float2half_rn(v.x), h1 = __float2half_rn(v.y);
    __half h2 = __float2half_rn(v.z), h3 = __float2half_rn(v.w);
    __half r0 = __float2half_rn(fmaf(-SPLIT_C63_64, __half2float(h0), v.x));
    __half r1 = __float2half_rn(fmaf(-SPLIT_C63_64, __half2float(h1), v.y));
    __half r2 = __float2half_rn(fmaf(-SPLIT_C63_64, __half2float(h2), v.z));
    __half r3 = __float2half_rn(fmaf(-SPLIT_C63_64, __half2float(h3), v.w));
    x1v = make_uint2(hpack(h0, h1), hpack(h2, h3));
    x2v = make_uint2(hpack(r0, r1), hpack(r2, r3));
}
// B split (weight prep): b1 = RN(w), b2 = RN(b1f + 64*(w - b1f))
__device__ __forceinline__ void splitB(float w, __half& b1, __half& b2) {
    b1 = __float2half_rn(w);
    float b1f = __half2float(b1);
    b2 = __float2half_rn(fmaf(64.f, w - b1f, b1f));
}

// ---------------- HMMA GEMM: C[M,N] = act(scale*(X1·B1 + X2·B2) + bias + res)
// K32 chunks; 128B smem rows = [tile1 64B | tile2 64B]; 2 buffers = 64KB -> 2 CTAs/SM
#define G5_A     0
#define G5_B     16384
#define G5_BUF   32768
#define G5_TOTAL 65536

__global__ void __launch_bounds__(256, 2)
gemm_mma_kernel(const float* __restrict__ A,
                const __half* __restrict__ B1g, const __half* __restrict__ B2g,
                float* __restrict__ C, int M, int N, int K,
                const float* __restrict__ bias, const float* __restrict__ res, int act)
{
    extern __shared__ char smem[];
    const uint32_t sb = smem_u32(smem);
    const int tid  = threadIdx.x;
    const int lane = tid & 31;
    const int wid  = tid >> 5;
    const int wm   = wid & 1;       // 2 warp-rows (64 rows)
    const int wn   = wid >> 1;      // 4 warp-cols (32 cols)
    const int m0 = blockIdx.y * 128;
    const int n0 = blockIdx.x * 128;

    const int ldRow  = tid >> 1;    // 0..127
    const int ldHalf = tid & 1;

    float acc[4][4][4];
#pragma unroll
    for (int i = 0; i < 4; i++)
#pragma unroll
        for (int j = 0; j < 4; j++)
#pragma unroll
            for (int e = 0; e < 4; e++) acc[i][j][e] = 0.f;

    const int nk = K >> 5;

    // unswizzled fragment bases; +kb (0/32) and +64 (tile2) added BEFORE swizzle
    // (low-bit sums: koff<=16 + kb<=32 + 64 = 112 < 128: no carry into row bits)
    const uint32_t aBase = (uint32_t)(wm * 64 + (lane & 15)) * 128u + (uint32_t)(lane >> 4) * 16u;
    const uint32_t bBase = (uint32_t)(wn * 32 + (lane >> 4) * 8 + (lane & 7)) * 128u
                         + (uint32_t)((lane >> 3) & 1) * 16u;

    uint2 x1v[4], x2v[4];   // A prefetch (split)

    auto cpasyncB = [&](int kc, uint32_t bufb) {
        const __half* B1p = B1g + (size_t)(n0 + ldRow) * K + kc * 32;
        const __half* B2p = B2g + (size_t)(n0 + ldRow) * K + kc * 32;
#pragma unroll
        for (int j = 0; j < 2; j++) {
            int c = ldHalf * 2 + j;
            uint32_t d1 = sb + bufb + G5_B + SWZ128((uint32_t)ldRow * 128u + (uint32_t)c * 16u);
            CP_ASYNC16(d1, B1p + c * 8);
            uint32_t d2 = sb + bufb + G5_B + SWZ128((uint32_t)ldRow * 128u + 64u + (uint32_t)c * 16u);
            CP_ASYNC16(d2, B2p + c * 8);
        }
    };
    auto prefA = [&](int kc) {
        const float* Ab = A + (size_t)(m0 + ldRow) * K + kc * 32 + ldHalf * 16;
#pragma unroll
        for (int p = 0; p < 4; p++) {
            float4 v = *reinterpret_cast<const float4*>(Ab + p * 4);
            splitA(v, x1v[p], x2v[p]);
        }
    };
    auto stsA = [&](uint32_t bufb) {
        char* base = smem + bufb + G5_A;
#pragma unroll
        for (int p = 0; p < 4; p++) {
            uint32_t o1 = SWZ128((uint32_t)ldRow * 128u + (uint32_t)(ldHalf * 32 + p * 8));
            uint32_t o2 = SWZ128((uint32_t)ldRow * 128u + 64u + (uint32_t)(ldHalf * 32 + p * 8));
            *reinterpret_cast<uint2*>(base + o1) = x1v[p];
            *reinterpret_cast<uint2*>(base + o2) = x2v[p];
        }
    };

    // ---- prologue ----
    cpasyncB(0, 0);
    CP_COMMIT();
    prefA(0);
    stsA(0);
    CP_WAIT0();
    __syncthreads();

    for (int kc = 0; kc < nk; kc++) {
        const uint32_t bufo = (uint32_t)(kc & 1) * G5_BUF;
        const uint32_t nbuf = (uint32_t)((kc + 1) & 1) * G5_BUF;
        if (kc + 1 < nk) {
            prefA(kc + 1);
            cpasyncB(kc + 1, nbuf);
            CP_COMMIT();
        }
        // compute current chunk: two k16 steps
#pragma unroll
        for (int kk = 0; kk < 2; kk++) {
            const uint32_t kb = (uint32_t)kk * 32u;
            const uint32_t a1Sw = SWZ128(aBase + kb);
            const uint32_t a2Sw = SWZ128(aBase + kb + 64u);
            const uint32_t b1Sw = SWZ128(bBase + kb);
            const uint32_t b2Sw = SWZ128(bBase + kb + 64u);
            uint32_t b1f[2][4], b2f[2][4];
#pragma unroll
            for (int ni2 = 0; ni2 < 2; ni2++) {
                uint32_t b_addr = sb + bufo + G5_B + (uint32_t)(ni2 * 2048);
                LDMX4(b1f[ni2], b_addr + b1Sw);
                LDMX4(b2f[ni2], b_addr + b2Sw);
            }
#pragma unroll
            for (int mi = 0; mi < 4; mi++) {
                uint32_t x1f[4], x2f[4];
                uint32_t a_addr = sb + bufo + G5_A + (uint32_t)(mi * 2048);
                LDMX4(x1f, a_addr + a1Sw);
                LDMX4(x2f, a_addr + a2Sw);
#pragma unroll
                for (int ni = 0; ni < 4; ni++) {
                    MMA16816(acc[mi][ni], x1f, &b1f[ni >> 1][(ni & 1) * 2]);
                    MMA16816(acc[mi][ni], x2f, &b2f[ni >> 1][(ni & 1) * 2]);
                }
            }
        }
        if (kc + 1 < nk) stsA(nbuf);
        CP_WAIT0();
        __syncthreads();
    }

    // epilogue: stage 64 rows at a time (stride 132), coalesced gmem store
    float* stg = reinterpret_cast<float*>(smem);
#pragma unroll
    for (int half = 0; half < 2; half++) {
        __syncthreads();
        if (wm == half) {
#pragma unroll
            for (int mi = 0; mi < 4; mi++) {
#pragma unroll
                for (int ni = 0; ni < 4; ni++) {
                    int r = mi * 16 + (lane >> 2);
                    int c = wn * 32 + ni * 8 + (lane & 3) * 2;
                    stg[r * 132 + c]           = acc[mi][ni][0];
                    stg[r * 132 + c + 1]       = acc[mi][ni][1];
                    stg[(r + 8) * 132 + c]     = acc[mi][ni][2];
                    stg[(r + 8) * 132 + c + 1] = acc[mi][ni][3];
                }
            }
        }
        __syncthreads();
#pragma unroll 4
        for (int it = 0; it < 32; it++) {
            int idx = it * 256 + tid;
            int r = idx >> 7, c = idx & 127;
            float v = stg[r * 132 + c] * FINAL_SCALE;
            int gn = n0 + c;
            size_t gr = (size_t)(m0 + half * 64 + r);
            if (bias) v += bias[gn];
            if (res)  v += res[gr * N + gn];
            if (act)  v = 0.5f * v * (1.0f + erff(v * 0.70710678118654752f));
            C[gr * N + gn] = v;
        }
    }
}

// ---------------- fallback f32 SGEMM (classifier only) ----------------
__global__ void __launch_bounds__(256, 2)
sgemm_kernel(const float* __restrict__ A, const float* __restrict__ B,
             float* __restrict__ C, int M, int N, int K,
             const float* __restrict__ bias)
{
    __shared__ float As[8][128];
    __shared__ float Bs[8][128];
    const int tid = threadIdx.x;
    const int row0 = blockIdx.y * 128, col0 = blockIdx.x * 128;
    const int tx = tid & 15, ty = tid >> 4;
    const int arow = tid >> 1, acol = (tid & 1) * 4;
    const int brow = tid >> 5, bcol = (tid & 31) * 4;
    float acc[8][8];
#pragma unroll
    for (int i = 0; i < 8; i++)
#pragma unroll
        for (int j = 0; j < 8; j++) acc[i][j] = 0.f;
    const int gar = row0 + arow, gbc = col0 + bcol;
    const bool aok = (gar < M), bok = (gbc < N);
    for (int k0 = 0; k0 < K; k0 += 8) {
        float4 avv = make_float4(0, 0, 0, 0);
        if (aok) avv = *reinterpret_cast<const float4*>(&A[(size_t)gar * K + k0 + acol]);
        As[acol + 0][arow] = avv.x; As[acol + 1][arow] = avv.y;
        As[acol + 2][arow] = avv.z; As[acol + 3][arow] = avv.w;
        float4 bv = make_float4(0, 0, 0, 0);
        if (bok) bv = *reinterpret_cast<const float4*>(&B[(size_t)(k0 + brow) * N + gbc]);
        *reinterpret_cast<float4*>(&Bs[brow][bcol]) = bv;
        __syncthreads();
#pragma unroll
        for (int kk = 0; kk < 8; kk++) {
            float4 ra0 = *reinterpret_cast<const float4*>(&As[kk][ty * 8 + 0]);
            float4 ra1 = *reinterpret_cast<const float4*>(&As[kk][ty * 8 + 4]);
            float4 rb0 = *reinterpret_cast<const float4*>(&Bs[kk][tx * 8 + 0]);
            float4 rb1 = *reinterpret_cast<const float4*>(&Bs[kk][tx * 8 + 4]);
            float ra[8] = {ra0.x, ra0.y, ra0.z, ra0.w, ra1.x, ra1.y, ra1.z, ra1.w};
            float rb[8] = {rb0.x, rb0.y, rb0.z, rb0.w, rb1.x, rb1.y, rb1.z, rb1.w};
#pragma unroll
            for (int i = 0; i < 8; i++)
#pragma unroll
                for (int j = 0; j < 8; j++) acc[i][j] = fmaf(ra[i], rb[j], acc[i][j]);
        }
        __syncthreads();
    }
#pragma unroll
    for (int i = 0; i < 8; i++) {
        const int r = row0 + ty * 8 + i;
        if (r >= M) continue;
#pragma unroll
        for (int j = 0; j < 8; j++) {
            const int c = col0 + tx * 8 + j;
            if (c >= N) continue;
            float v = acc[i][j];
            if (bias) v += bias[c];
            C[(size_t)r * N + c] = v;
        }
    }
}

// ---------------- weight transpose + merged-residual split ----------------
__global__ void tsplit_kernel(const float* __restrict__ W, __half* __restrict__ b1,
                              __half* __restrict__ b2, int K, int N)
{
    __shared__ float t[32][33];
    int k0 = blockIdx.y * 32, n0 = blockIdx.x * 32;
    int tx = threadIdx.x, ty = threadIdx.y;
#pragma unroll
    for (int r = 0; r < 4; r++) {
        int k = k0 + ty + r * 8;
        t[ty + r * 8][tx] = (k < K && n0 + tx < N) ? W[(size_t)k * N + n0 + tx] : 0.f;
    }
    __syncthreads();
#pragma unroll
    for (int r = 0; r < 4; r++) {
        int n = n0 + ty + r * 8, k = k0 + tx;
        if (n < N && k < K) {
            __half h1, h2;
            splitB(t[tx][ty + r * 8], h1, h2);
            b1[(size_t)n * K + k] = h1;
            b2[(size_t)n * K + k] = h2;
        }
    }
}

__global__ void assemble_conv_wT(const float* __restrict__ w1, const float* __restrict__ w2,
                                 const float* __restrict__ w4, const float* __restrict__ b1c,
                                 const float* __restrict__ b2c, const float* __restrict__ b4c,
                                 __half* __restrict__ o1, __half* __restrict__ o2,
                                 float* __restrict__ cb)
{
    int idx = blockIdx.x * blockDim.x + threadIdx.x;
    if (idx < EE) cb[idx] = (idx < 256) ? b1c[idx] : (idx < 512 ? b2c[idx - 256] : b4c[idx - 512]);
    if (idx >= 768 * 1024) return;
    int n = idx / 1024, k = idx % 1024;
    int i = k % 256, d = k / 256;
    float v = 0.f;
    if (n < 256)      { if (d == 1) v = w1[n * 256 + i]; }
    else if (n < 512) { int oo = n - 256; int j = d - 1; if (j == 0 || j == 1) v = w2[oo * 512 + i * 2 + j]; }
    else              { int oo = n - 512; v = w4[oo * 1024 + i * 4 + d]; }
    __half h1, h2;
    splitB(v, h1, h2);
    o1[idx] = h1;
    o2[idx] = h2;
}

__global__ void assemble_ssm_wT(const float* __restrict__ w, __half* __restrict__ o1,
                                __half* __restrict__ o2)
{
    int idx = blockIdx.x * blockDim.x + threadIdx.x;
    if (idx >= 768 * 2304) return;
    int n = idx / 2304, k = idx % 2304;
    int i = k % 768, j = k / 768;
    __half h1, h2;
    splitB(w[(size_t)n * 2304 + i * 3 + j], h1, h2);
    o1[idx] = h1;
    o2[idx] = h2;
}

// ---------------- small kernels ----------------
__global__ void init_c48_kernel(float* __restrict__ C48) {
    for (int i = threadIdx.x; i < FF * TP; i += blockDim.x) {
        int k = i / TP, t = i % TP;
        int m = (k * t) % TP;
        C48[i] = cospif(2.0f * (float)m / (float)TP);
    }
}

__global__ void pe_diff_kernel(const float* __restrict__ h1, const float* __restrict__ pe,
                               float* __restrict__ hpe, float* __restrict__ sf)
{
    size_t idx = (size_t)blockIdx.x * blockDim.x + threadIdx.x;
    const size_t total = N_BT * HH;
    if (idx >= total) return;
    int c = (int)(idx % HH);
    size_t r = idx / HH;
    int t = (int)(r % TT);
    float cur = h1[idx] + pe[(size_t)t * HH + c];
    hpe[idx] = cur;
    float prev = (t == 0) ? cur : (h1[idx - HH] + pe[(size_t)(t - 1) * HH + c]);
    sf[idx] = cur - prev;
}

__global__ void __launch_bounds__(256) dft48_kernel(const float* __restrict__ hp,
                                                    float* __restrict__ out,
                                                    const float* __restrict__ C48)
{
    __shared__ float sC[FF * TP];
    int b = blockIdx.x;
    for (int i = threadIdx.x; i < FF * TP; i += 256) sC[i] = C48[i];
    float r[TP];
    const float* base = hp + (size_t)b * TP * HH + threadIdx.x;
#pragma unroll
    for (int t = 0; t < TP; t++) r[t] = base[(size_t)t * HH];
    __syncthreads();
    float* ob = out + (size_t)b * FF * HH + threadIdx.x;
    for (int k = 0; k < FF; k++) {
        float acc = 0.f;
#pragma unroll
        for (int t = 0; t < TP; t++) acc = fmaf(r[t], sC[k * TP + t], acc);
        ob[(size_t)k * HH] = acc;
    }
}

__global__ void im2col_conv(const float* __restrict__ f, float* __restrict__ col) {
    size_t idx = (size_t)blockIdx.x * blockDim.x + threadIdx.x;
    const size_t total = N_BF * 1024;
    if (idx >= total) return;
    int kk = (int)(idx % 1024);
    size_t row = idx / 1024;
    int i = kk % 256, d = kk / 256;
    int fq = (int)(row % FF);
    size_t b = row / FF;
    int src = fq + d - 1;
    col[idx] = (src >= 0 && src < FF) ? f[((size_t)b * FF + src) * HH + i] : 0.f;
}

__global__ void im2col_ssm(const float* __restrict__ h, float* __restrict__ col) {
    size_t idx = (size_t)blockIdx.x * blockDim.x + threadIdx.x;
    const size_t total = N_BF * 2304;
    if (idx >= total) return;
    int kk = (int)(idx % 2304);
    size_t row = idx / 2304;
    int i = kk % EE, j = kk / EE;
    int fq = (int)(row % FF);
    size_t b = row / FF;
    int src = fq + j - 1;
    col[idx] = (src >= 0 && src < FF) ? h[((size_t)b * FF + src) * EE + i] : 0.f;
}

__global__ void __launch_bounds__(256) ln_kernel(const float* __restrict__ x,
                                                 const float* __restrict__ add,
                                                 const float* __restrict__ g,
                                                 const float* __restrict__ bta,
                                                 float* __restrict__ y, int C)
{
    int row = blockIdx.x;
    const float* xr = x + (size_t)row * C;
    const float* ar = add ? add + (size_t)row * C : nullptr;
    float s = 0.f, q = 0.f;
    for (int c = threadIdx.x; c < C; c += 256) {
        float v = xr[c] + (ar ? ar[c] : 0.f);
        s += v; q += v * v;
    }
#pragma unroll
    for (int o = 16; o; o >>= 1) {
        s += __shfl_xor_sync(~0u, s, o);
        q += __shfl_xor_sync(~0u, q, o);
    }
    __shared__ float ss[8], sq[8];
    int w = threadIdx.x >> 5, l = threadIdx.x & 31;
    if (l == 0) { ss[w] = s; sq[w] = q; }
    __syncthreads();
    if (threadIdx.x == 0) {
        float ts = 0.f, tq = 0.f;
        for (int i = 0; i < 8; i++) { ts += ss[i]; tq += sq[i]; }
        ss[0] = ts; sq[0] = tq;
    }
    __syncthreads();
    float mean = ss[0] / C;
    float var = sq[0] / C - mean * mean;
    float inv = rsqrtf(var + 1e-5f);
    for (int c = threadIdx.x; c < C; c += 256) {
        float v = xr[c] + (ar ? ar[c] : 0.f);
        y[(size_t)row * C + c] = (v - mean) * inv * g[c] + bta[c];
    }
}

__global__ void __launch_bounds__(256) attn_kernel(const float* __restrict__ qkv,
                                                   float* __restrict__ out)
{
    __shared__ float sq_[FF][DHH], sk_[FF][DHH], sv_[FF][DHH];
    __shared__ float G[FF][FF];
    __shared__ float ctab[FF];
    __shared__ float sa[NF2];
    __shared__ float kt[FF];
    int bh = blockIdx.x;
    int b = bh >> 3, hh = bh & 7;
    int tid = threadIdx.x;
    const float* base = qkv + ((size_t)b * FF) * (3 * EE) + hh * DHH;
    for (int idx = tid; idx < FF * DHH; idx += 256) {
        int t = idx / DHH, d = idx % DHH;
        size_t off = (size_t)t * (3 * EE) + d;
        sq_[t][d] = base[off];
        sk_[t][d] = base[off + EE];
        sv_[t][d] = base[off + 2 * EE];
    }
    if (tid < FF) ctab[tid] = cospif(2.0f * (float)tid / 25.0f);
    __syncthreads();
    for (int e = tid; e < FF * FF; e += 256) {
        int t = e / FF, s2 = e % FF;
        float acc = 0.f;
#pragma unroll 8
        for (int d = 0; d < DHH; d++) acc = fmaf(sq_[t][d], sk_[s2][d], acc);
        G[t][s2] = acc;
    }
    __syncthreads();
    if (tid < NF2) {
        float acc = 0.f;
        for (int t = 0; t < FF; t++)
            for (int s2 = 0; s2 < FF; s2++)
                acc = fmaf(G[t][s2], ctab[(tid * (t - s2 + FF)) % FF], acc);
        sa[tid] = acc * 0.10206207261596575f;
    }
    __syncthreads();
    if (tid == 0) {
        float mx = sa[0];
        for (int f = 1; f < NF2; f++) mx = fmaxf(mx, sa[f]);
        float e_[NF2], sum = 0.f;
        for (int f = 0; f < NF2; f++) { e_[f] = expf(sa[f] - mx); sum += e_[f]; }
        float inv = 1.0f / sum;
        for (int f = 0; f < NF2; f++) sa[f] = e_[f] * inv;
    }
    __syncthreads();
    if (tid < FF) {
        float acc = sa[0];
        for (int f = 1; f < NF2; f++) acc = fmaf(2.0f * sa[f], ctab[(f * tid) % FF], acc);
        kt[tid] = acc * 0.04f;
    }
    __syncthreads();
    float* obase = out + ((size_t)b * FF) * EE + hh * DHH;
    for (int idx = tid; idx < FF * DHH; idx += 256) {
        int t = idx / DHH, d = idx % DHH;
        float acc = 0.f;
#pragma unroll
        for (int s2 = 0; s2 < FF; s2++)
            acc = fmaf(kt[(t - s2 + FF) % FF], sv_[s2][d], acc);
        obase[(size_t)t * EE + d] = acc;
    }
}

__global__ void mean_kernel(const float* __restrict__ h, float* __restrict__ hm) {
    int b = blockIdx.x;
    int c = threadIdx.x;
    float acc = 0.f;
#pragma unroll
    for (int f = 0; f < FF; f++) acc += h[((size_t)b * FF + f) * EE + c];
    hm[(size_t)b * EE + c] = acc * 0.04f;
}

// ---------------- host helpers ----------------
static inline void gemm_tc(const float* A, const __half* b1, const __half* b2, float* C,
                           int M, int N, int K, const float* bias, const float* res, int act)
{
    dim3 grid(N / 128, M / 128);
    gemm_mma_kernel<<<grid, 256, G5_TOTAL>>>(A, b1, b2, C, M, N, K, bias, res, act);
}
static inline void tsplit(const float* W, __half* b1, __half* b2, int K, int N) {
    dim3 grid((N + 31) / 32, (K + 31) / 32);
    tsplit_kernel<<<grid, dim3(32, 8)>>>(W, b1, b2, K, N);
}

extern "C" void kernel_launch(void* const* d_in, const int* in_sizes, int n_in,
                              void* d_out, int out_size)
{
    const float* x       = (const float*)d_in[0];
    const float* W_in    = (const float*)d_in[1];
    const float* b_in    = (const float*)d_in[2];
    const float* pe      = (const float*)d_in[3];
    const float* W_shape = (const float*)d_in[4];
    const float* b_shape = (const float*)d_in[5];
    const float* W_patch = (const float*)d_in[6];
    const float* b_patch = (const float*)d_in[7];
    const float* cw1     = (const float*)d_in[8];
    const float* cb1     = (const float*)d_in[9];
    const float* cw2     = (const float*)d_in[10];
    const float* cb2     = (const float*)d_in[11];
    const float* cw4     = (const float*)d_in[12];
    const float* cb4     = (const float*)d_in[13];
    const float* ln1g    = (const float*)d_in[14];
    const float* ln1b    = (const float*)d_in[15];
    const float* Wqkv    = (const float*)d_in[16];
    const float* Wo      = (const float*)d_in[17];
    const float* bo      = (const float*)d_in[18];
    const float* ln2g    = (const float*)d_in[19];
    const float* ln2b    = (const float*)d_in[20];
    const float* Wf1     = (const float*)d_in[21];
    const float* bf1     = (const float*)d_in[22];
    const float* Wf2     = (const float*)d_in[23];
    const float* bf2     = (const float*)d_in[24];
    const float* ssmw    = (const float*)d_in[25];
    const float* ssmb    = (const float*)d_in[26];
    const float* ssmg    = (const float*)d_in[27];
    const float* ssmbn   = (const float*)d_in[28];
    const float* W_out   = (const float*)d_in[29];
    const float* b_out   = (const float*)d_in[30];
    float* out = (float*)d_out;

    cudaFuncSetAttribute(gemm_mma_kernel, cudaFuncAttributeMaxDynamicSharedMemorySize, G5_TOTAL);

    float *h1, *hpe, *sf, *h2, *hp, *fr, *C48, *cb, *col, *h, *y, *qkv, *att, *mid, *s, *hm;
    cudaGetSymbolAddress((void**)&h1,  g_h1);
    cudaGetSymbolAddress((void**)&hpe, g_hpe);
    cudaGetSymbolAddress((void**)&sf,  g_sf);
    cudaGetSymbolAddress((void**)&h2,  g_h2);
    cudaGetSymbolAddress((void**)&hp,  g_hp);
    cudaGetSymbolAddress((void**)&fr,  g_fr);
    cudaGetSymbolAddress((void**)&C48, g_C48);
    cudaGetSymbolAddress((void**)&cb,  g_cb);
    cudaGetSymbolAddress((void**)&col, g_col);
    cudaGetSymbolAddress((void**)&h,   g_h);
    cudaGetSymbolAddress((void**)&y,   g_y);
    cudaGetSymbolAddress((void**)&qkv, g_qkv);
    cudaGetSymbolAddress((void**)&att, g_att);
    cudaGetSymbolAddress((void**)&mid, g_mid);
    cudaGetSymbolAddress((void**)&s,   g_s);
    cudaGetSymbolAddress((void**)&hm,  g_hm);

    __half *tWin_h, *tWin_2, *tWsh_h, *tWsh_2, *tWpa_h, *tWpa_2, *tWc_h, *tWc_2;
    __half *tWqkv_h, *tWqkv_2, *tWo_h, *tWo_2, *tWf1_h, *tWf1_2, *tWf2_h, *tWf2_2, *tWc2_h, *tWc2_2;
    cudaGetSymbolAddress((void**)&tWin_h,  g_tWin_h);  cudaGetSymbolAddress((void**)&tWin_2,  g_tWin_2);
    cudaGetSymbolAddress((void**)&tWsh_h,  g_tWsh_h);  cudaGetSymbolAddress((void**)&tWsh_2,  g_tWsh_2);
    cudaGetSymbolAddress((void**)&tWpa_h,  g_tWpa_h);  cudaGetSymbolAddress((void**)&tWpa_2,  g_tWpa_2);
    cudaGetSymbolAddress((void**)&tWc_h,   g_tWc_h);   cudaGetSymbolAddress((void**)&tWc_2,   g_tWc_2);
    cudaGetSymbolAddress((void**)&tWqkv_h, g_tWqkv_h); cudaGetSymbolAddress((void**)&tWqkv_2, g_tWqkv_2);
    cudaGetSymbolAddress((void**)&tWo_h,   g_tWo_h);   cudaGetSymbolAddress((void**)&tWo_2,   g_tWo_2);
    cudaGetSymbolAddress((void**)&tWf1_h,  g_tWf1_h);  cudaGetSymbolAddress((void**)&tWf1_2,  g_tWf1_2);
    cudaGetSymbolAddress((void**)&tWf2_h,  g_tWf2_h);  cudaGetSymbolAddress((void**)&tWf2_2,  g_tWf2_2);
    cudaGetSymbolAddress((void**)&tWc2_h,  g_tWc2_h);  cudaGetSymbolAddress((void**)&tWc2_2,  g_tWc2_2);

    // tables + weight prep
    init_c48_kernel<<<1, 256>>>(C48);
    tsplit(W_in,    tWin_h, tWin_2,  64, 256);
    tsplit(W_shape, tWsh_h, tWsh_2, 256, 256);
    tsplit(W_patch, tWpa_h, tWpa_2, 512, 256);
    assemble_conv_wT<<<(768 * 1024 + 255) / 256, 256>>>(cw1, cw2, cw4, cb1, cb2, cb4, tWc_h, tWc_2, cb);
    for (int i = 0; i < LL; i++) {
        tsplit(Wqkv + (size_t)i * EE * 3 * EE, tWqkv_h + (size_t)i * 3 * EE * EE, tWqkv_2 + (size_t)i * 3 * EE * EE, EE, 3 * EE);
        tsplit(Wo   + (size_t)i * EE * EE,     tWo_h   + (size_t)i * EE * EE,     tWo_2   + (size_t)i * EE * EE,     EE, EE);
        tsplit(Wf1  + (size_t)i * EE * 4 * EE, tWf1_h  + (size_t)i * 4 * EE * EE, tWf1_2  + (size_t)i * 4 * EE * EE, EE, 4 * EE);
        tsplit(Wf2  + (size_t)i * 4 * EE * EE, tWf2_h  + (size_t)i * EE * 4 * EE, tWf2_2  + (size_t)i * EE * 4 * EE, 4 * EE, EE);
    }
    assemble_ssm_wT<<<(768 * 2304 + 255) / 256, 256>>>(ssmw, tWc2_h, tWc2_2);

    // embedding chain
    gemm_tc(x, tWin_h, tWin_2, h1, BB * TT, HH, DIN, b_in, nullptr, 0);
    {
        size_t tot = N_BT * HH;
        pe_diff_kernel<<<(unsigned)((tot + 255) / 256), 256>>>(h1, pe, hpe, sf);
    }
    gemm_tc(sf, tWsh_h, tWsh_2, h2, BB * TT, HH, HH, b_shape, hpe, 0);
    gemm_tc(h2, tWpa_h, tWpa_2, hp, BB * TP, HH, 2 * HH, b_patch, nullptr, 0);

    dft48_kernel<<<BB, 256>>>(hp, fr, C48);

    {
        size_t tot = N_BF * 1024;
        im2col_conv<<<(unsigned)((tot + 255) / 256), 256>>>(fr, col);
    }
    gemm_tc(col, tWc_h, tWc_2, h, (int)N_BF, EE, 1024, cb, nullptr, 0);

    // transformer layers
    for (int i = 0; i < LL; i++) {
        ln_kernel<<<(unsigned)N_BF, 256>>>(h, nullptr, ln1g + (size_t)i * EE, ln1b + (size_t)i * EE, y, EE);
        gemm_tc(y, tWqkv_h + (size_t)i * 3 * EE * EE, tWqkv_2 + (size_t)i * 3 * EE * EE,
                qkv, (int)N_BF, 3 * EE, EE, nullptr, nullptr, 0);
        attn_kernel<<<BB * NHEADS, 256>>>(qkv, att);
        gemm_tc(att, tWo_h + (size_t)i * EE * EE, tWo_2 + (size_t)i * EE * EE,
                h, (int)N_BF, EE, EE, bo + (size_t)i * EE, h, 0);
        ln_kernel<<<(unsigned)N_BF, 256>>>(h, nullptr, ln2g + (size_t)i * EE, ln2b + (size_t)i * EE, y, EE);
        gemm_tc(y, tWf1_h + (size_t)i * 4 * EE * EE, tWf1_2 + (size_t)i * 4 * EE * EE,
                mid, (int)N_BF, 4 * EE, EE, bf1 + (size_t)i * 4 * EE, nullptr, 1);
        gemm_tc(mid, tWf2_h + (size_t)i * EE * 4 * EE, tWf2_2 + (size_t)i * EE * 4 * EE,
                h, (int)N_BF, EE, 4 * EE, bf2 + (size_t)i * EE, h, 0);
    }

    // SSM conv + LN
    {
        size_t tot = N_BF * 2304;
        im2col_ssm<<<(unsigned)((tot + 255) / 256), 256>>>(h, col);
    }
    gemm_tc(col, tWc2_h, tWc2_2, s, (int)N_BF, EE, 3 * EE, ssmb, nullptr, 0);
    ln_kernel<<<(unsigned)N_BF, 256>>>(h, s, ssmg, ssmbn, h, EE);

    // mean + classifier (small, f32 path)
    mean_kernel<<<BB, EE>>>(h, hm);
    {
        dim3 grid((NCC + 127) / 128, (BB + 127) / 128);
        sgemm_kernel<<<grid, 256>>>(hm, W_out, out, BB, NCC, EE, b_out);
    }
}

// round 9
// speedup vs baseline: 2.6553x; 1.0720x over previous
#include <cuda_runtime.h>
#include <cuda_fp16.h>
#include <math.h>
#include <stdint.h>

// ---------------- problem constants ----------------
#define BB    512
#define TT    96
#define DIN   64
#define HH    256
#define LL    4
#define EE    768
#define NCC   100
#define TP    48
#define FF    25
#define NF2   13
#define DHH   96
#define NHEADS 8

#define N_BT  ((size_t)BB * TT)   // 49152
#define N_BF  ((size_t)BB * FF)   // 12800

// merged-residual split constant c = 1/64; final scale 64/65
#define SPLIT_C63_64  0.984375f
#define FINAL_SCALE   0.9846153846153846f

// ---------------- scratch buffers ----------------
__device__ __align__(16) float g_h1 [N_BT * HH];
__device__ __align__(16) float g_hpe[N_BT * HH];
__device__ __align__(16) float g_hp [(size_t)BB * TP * HH];
__device__ __align__(16) float g_fr [N_BF * HH];
__device__ __align__(16) float g_C48[FF * TP];
__device__ __align__(16) float g_cb [EE];
__device__ __align__(16) float g_h  [N_BF * EE];
__device__ __align__(16) float g_qkv[N_BF * 3 * EE];
__device__ __align__(16) float g_s  [N_BF * EE];
__device__ __align__(16) float g_hm [(size_t)BB * EE];

// split-fp16 GEMM-A buffers (x1 = RN(a), x2 = RN(a - (63/64)*x1))
__device__ __align__(16) __half g_xs1 [N_BT * DIN],      g_xs2 [N_BT * DIN];
__device__ __align__(16) __half g_sf1 [N_BT * HH],       g_sf2 [N_BT * HH];
__device__ __align__(16) __half g_h21 [N_BT * HH],       g_h22 [N_BT * HH];
__device__ __align__(16) __half g_col1[N_BF * 2304],     g_col2[N_BF * 2304];
__device__ __align__(16) __half g_y1  [N_BF * EE],       g_y2  [N_BF * EE];
__device__ __align__(16) __half g_att1[N_BF * EE],       g_att2[N_BF * EE];
__device__ __align__(16) __half g_mid1[N_BF * 4 * EE],   g_mid2[N_BF * 4 * EE];

// transposed fp16 weights [N][K]: _h = RN(W), _2 = RN(Wh + 64*(W - Wh))
__device__ __align__(16) __half g_tWin_h [256 * 64],       g_tWin_2 [256 * 64];
__device__ __align__(16) __half g_tWsh_h [256 * 256],      g_tWsh_2 [256 * 256];
__device__ __align__(16) __half g_tWpa_h [256 * 512],      g_tWpa_2 [256 * 512];
__device__ __align__(16) __half g_tWc_h  [768 * 1024],     g_tWc_2  [768 * 1024];
__device__ __align__(16) __half g_tWqkv_h[LL * 2304 * 768],g_tWqkv_2[LL * 2304 * 768];
__device__ __align__(16) __half g_tWo_h  [LL * 768 * 768], g_tWo_2  [LL * 768 * 768];
__device__ __align__(16) __half g_tWf1_h [LL * 3072 * 768],g_tWf1_2 [LL * 3072 * 768];
__device__ __align__(16) __half g_tWf2_h [LL * 768 * 3072],g_tWf2_2 [LL * 768 * 3072];
__device__ __align__(16) __half g_tWc2_h [768 * 2304],     g_tWc2_2 [768 * 2304];

// ---------------- helpers ----------------
__device__ __forceinline__ uint32_t smem_u32(const void* p) {
    uint32_t a;
    asm("{ .reg .u64 t; cvta.to.shared.u64 t, %1; cvt.u32.u64 %0, t; }" : "=r"(a) : "l"(p));
    return a;
}

// scalar merged-residual splits
__device__ __forceinline__ void splitS(float a, __half& x1, __half& x2) {
    x1 = __float2half_rn(a);
    x2 = __float2half_rn(fmaf(-SPLIT_C63_64, __half2float(x1), a));
}
__device__ __forceinline__ void splitB(float w, __half& b1, __half& b2) {
    b1 = __float2half_rn(w);
    float b1f = __half2float(b1);
    b2 = __float2half_rn(fmaf(64.f, w - b1f, b1f));
}

// SW128: 128B rows, xor 16B-chunk bits [4:6] with row%8 (addr bits [7:9])
#define SWZ128(x) ((x) ^ (((x) >> 3) & 0x70))

#define LDMX4(r, a) \
    asm volatile("ldmatrix.sync.aligned.m8n8.x4.shared.b16 {%0,%1,%2,%3}, [%4];" \
        : "=r"((r)[0]), "=r"((r)[1]), "=r"((r)[2]), "=r"((r)[3]) : "r"(a))
#define MMA16816(d, A, Bf) \
    asm volatile("mma.sync.aligned.m16n8k16.row.col.f32.f16.f16.f32 " \
        "{%0,%1,%2,%3}, {%4,%5,%6,%7}, {%8,%9}, {%0,%1,%2,%3};" \
        : "+f"((d)[0]), "+f"((d)[1]), "+f"((d)[2]), "+f"((d)[3]) \
        : "r"((A)[0]), "r"((A)[1]), "r"((A)[2]), "r"((A)[3]), "r"((Bf)[0]), "r"((Bf)[1]))

#define CP_ASYNC16(dst, src) \
    asm volatile("cp.async.cg.shared.global [%0], [%1], 16;" :: "r"(dst), "l"(src))
#define CP_COMMIT()  asm volatile("cp.async.commit_group;" ::: "memory")
#define CP_WAIT0()   asm volatile("cp.async.wait_group 0;" ::: "memory")
#define CP_WAIT1()   asm volatile("cp.async.wait_group 1;" ::: "memory")

// ---------------- HMMA GEMM: C = act(scale*(X1·B1 + X2·B2) + bias + res)
// A pre-split fp16 (A1,A2) [M][K]; B pre-split fp16 (B1,B2) [N][K].
// K32 chunks; per stage: A 16KB ([x1 64B|x2 64B] rows) + B 16KB; 3 stages = 96KB.
#define G6_A      0
#define G6_B      16384
#define G6_STAGE  32768
#define G6_TOTAL  98304

__global__ void __launch_bounds__(256, 2)
gemm_mma_kernel(const __half* __restrict__ A1, const __half* __restrict__ A2,
                const __half* __restrict__ B1g, const __half* __restrict__ B2g,
                float* __restrict__ Cf, __half* __restrict__ C1, __half* __restrict__ C2,
                int M, int N, int K,
                const float* __restrict__ bias, const float* __restrict__ res, int act)
{
    extern __shared__ char smem[];
    const uint32_t sb = smem_u32(smem);
    const int tid  = threadIdx.x;
    const int lane = tid & 31;
    const int wid  = tid >> 5;
    const int wm   = wid & 1;       // 2 warp-rows (64 rows)
    const int wn   = wid >> 1;      // 4 warp-cols (32 cols)
    const int m0 = blockIdx.y * 128;
    const int n0 = blockIdx.x * 128;

    const int ldRow  = tid >> 1;    // 0..127
    const int ldHalf = tid & 1;

    float acc[4][4][4];
#pragma unroll
    for (int i = 0; i < 4; i++)
#pragma unroll
        for (int j = 0; j < 4; j++)
#pragma unroll
            for (int e = 0; e < 4; e++) acc[i][j][e] = 0.f;

    const int nk = K >> 5;

    // unswizzled fragment bases; +kb (0/32) and +64 (tile2) added BEFORE swizzle
    // (low-bit sums <= 112 < 128: no carry into row bits; stage/tile offsets are higher bits)
    const uint32_t aBase = (uint32_t)(wm * 64 + (lane & 15)) * 128u + (uint32_t)(lane >> 4) * 16u;
    const uint32_t bBase = (uint32_t)(wn * 32 + (lane >> 4) * 8 + (lane & 7)) * 128u
                         + (uint32_t)((lane >> 3) & 1) * 16u;

    auto issueStage = [&](int kc, uint32_t bufb) {
        const __half* A1p = A1 + (size_t)(m0 + ldRow) * K + kc * 32;
        const __half* A2p = A2 + (size_t)(m0 + ldRow) * K + kc * 32;
        const __half* B1p = B1g + (size_t)(n0 + ldRow) * K + kc * 32;
        const __half* B2p = B2g + (size_t)(n0 + ldRow) * K + kc * 32;
#pragma unroll
        for (int j = 0; j < 2; j++) {
            int c = ldHalf * 2 + j;
            uint32_t r1 = (uint32_t)ldRow * 128u + (uint32_t)c * 16u;
            CP_ASYNC16(sb + bufb + G6_A + SWZ128(r1),       A1p + c * 8);
            CP_ASYNC16(sb + bufb + G6_A + SWZ128(r1 + 64u), A2p + c * 8);
            CP_ASYNC16(sb + bufb + G6_B + SWZ128(r1),       B1p + c * 8);
            CP_ASYNC16(sb + bufb + G6_B + SWZ128(r1 + 64u), B2p + c * 8);
        }
    };

    // ---- prologue: stages 0 and 1 (group per stage; empty groups are fine) ----
    issueStage(0, 0);
    CP_COMMIT();
    if (1 < nk) issueStage(1, G6_STAGE);
    CP_COMMIT();

    int stage = 0;
    for (int kc = 0; kc < nk; kc++) {
        CP_WAIT1();          // groups 0..kc complete (one pending allowed)
        __syncthreads();
        // refill stage (kc+2)%3 == (kc-1)%3 (already consumed)
        if (kc + 2 < nk) {
            int ns = stage + 2; if (ns >= 3) ns -= 3;
            issueStage(kc + 2, (uint32_t)ns * G6_STAGE);
        }
        CP_COMMIT();
        const uint32_t bufo = (uint32_t)stage * G6_STAGE;
        // compute chunk kc: two k16 steps
#pragma unroll
        for (int kk = 0; kk < 2; kk++) {
            const uint32_t kb = (uint32_t)kk * 32u;
            const uint32_t a1Sw = SWZ128(aBase + kb);
            const uint32_t a2Sw = SWZ128(aBase + kb + 64u);
            const uint32_t b1Sw = SWZ128(bBase + kb);
            const uint32_t b2Sw = SWZ128(bBase + kb + 64u);
            uint32_t b1f[2][4], b2f[2][4];
#pragma unroll
            for (int ni2 = 0; ni2 < 2; ni2++) {
                uint32_t b_addr = sb + bufo + G6_B + (uint32_t)(ni2 * 2048);
                LDMX4(b1f[ni2], b_addr + b1Sw);
                LDMX4(b2f[ni2], b_addr + b2Sw);
            }
#pragma unroll
            for (int mi = 0; mi < 4; mi++) {
                uint32_t x1f[4], x2f[4];
                uint32_t a_addr = sb + bufo + G6_A + (uint32_t)(mi * 2048);
                LDMX4(x1f, a_addr + a1Sw);
                LDMX4(x2f, a_addr + a2Sw);
#pragma unroll
                for (int ni = 0; ni < 4; ni++) {
                    MMA16816(acc[mi][ni], x1f, &b1f[ni >> 1][(ni & 1) * 2]);
                    MMA16816(acc[mi][ni], x2f, &b2f[ni >> 1][(ni & 1) * 2]);
                }
            }
        }
        if (++stage == 3) stage = 0;
    }
    __syncthreads();

    // epilogue: stage 64 rows at a time (stride 132), coalesced store
    float* stg = reinterpret_cast<float*>(smem);
#pragma unroll
    for (int half = 0; half < 2; half++) {
        __syncthreads();
        if (wm == half) {
#pragma unroll
            for (int mi = 0; mi < 4; mi++) {
#pragma unroll
                for (int ni = 0; ni < 4; ni++) {
                    int r = mi * 16 + (lane >> 2);
                    int c = wn * 32 + ni * 8 + (lane & 3) * 2;
                    stg[r * 132 + c]           = acc[mi][ni][0];
                    stg[r * 132 + c + 1]       = acc[mi][ni][1];
                    stg[(r + 8) * 132 + c]     = acc[mi][ni][2];
                    stg[(r + 8) * 132 + c + 1] = acc[mi][ni][3];
                }
            }
        }
        __syncthreads();
#pragma unroll 4
        for (int it = 0; it < 32; it++) {
            int idx = it * 256 + tid;
            int r = idx >> 7, c = idx & 127;
            float v = stg[r * 132 + c] * FINAL_SCALE;
            int gn = n0 + c;
            size_t gr = (size_t)(m0 + half * 64 + r);
            if (bias) v += bias[gn];
            if (res)  v += res[gr * N + gn];
            if (act)  v = 0.5f * v * (1.0f + erff(v * 0.70710678118654752f));
            if (C1) {
                __half o1, o2;
                splitS(v, o1, o2);
                C1[gr * N + gn] = o1;
                C2[gr * N + gn] = o2;
            } else {
                Cf[gr * N + gn] = v;
            }
        }
    }
}

// ---------------- fallback f32 SGEMM (classifier only) ----------------
__global__ void __launch_bounds__(256, 2)
sgemm_kernel(const float* __restrict__ A, const float* __restrict__ B,
             float* __restrict__ C, int M, int N, int K,
             const float* __restrict__ bias)
{
    __shared__ float As[8][128];
    __shared__ float Bs[8][128];
    const int tid = threadIdx.x;
    const int row0 = blockIdx.y * 128, col0 = blockIdx.x * 128;
    const int tx = tid & 15, ty = tid >> 4;
    const int arow = tid >> 1, acol = (tid & 1) * 4;
    const int brow = tid >> 5, bcol = (tid & 31) * 4;
    float acc[8][8];
#pragma unroll
    for (int i = 0; i < 8; i++)
#pragma unroll
        for (int j = 0; j < 8; j++) acc[i][j] = 0.f;
    const int gar = row0 + arow, gbc = col0 + bcol;
    const bool aok = (gar < M), bok = (gbc < N);
    for (int k0 = 0; k0 < K; k0 += 8) {
        float4 avv = make_float4(0, 0, 0, 0);
        if (aok) avv = *reinterpret_cast<const float4*>(&A[(size_t)gar * K + k0 + acol]);
        As[acol + 0][arow] = avv.x; As[acol + 1][arow] = avv.y;
        As[acol + 2][arow] = avv.z; As[acol + 3][arow] = avv.w;
        float4 bv = make_float4(0, 0, 0, 0);
        if (bok) bv = *reinterpret_cast<const float4*>(&B[(size_t)(k0 + brow) * N + gbc]);
        *reinterpret_cast<float4*>(&Bs[brow][bcol]) = bv;
        __syncthreads();
#pragma unroll
        for (int kk = 0; kk < 8; kk++) {
            float4 ra0 = *reinterpret_cast<const float4*>(&As[kk][ty * 8 + 0]);
            float4 ra1 = *reinterpret_cast<const float4*>(&As[kk][ty * 8 + 4]);
            float4 rb0 = *reinterpret_cast<const float4*>(&Bs[kk][tx * 8 + 0]);
            float4 rb1 = *reinterpret_cast<const float4*>(&Bs[kk][tx * 8 + 4]);
            float ra[8] = {ra0.x, ra0.y, ra0.z, ra0.w, ra1.x, ra1.y, ra1.z, ra1.w};
            float rb[8] = {rb0.x, rb0.y, rb0.z, rb0.w, rb1.x, rb1.y, rb1.z, rb1.w};
#pragma unroll
            for (int i = 0; i < 8; i++)
#pragma unroll
                for (int j = 0; j < 8; j++) acc[i][j] = fmaf(ra[i], rb[j], acc[i][j]);
        }
        __syncthreads();
    }
#pragma unroll
    for (int i = 0; i < 8; i++) {
        const int r = row0 + ty * 8 + i;
        if (r >= M) continue;
#pragma unroll
        for (int j = 0; j < 8; j++) {
            const int c = col0 + tx * 8 + j;
            if (c >= N) continue;
            float v = acc[i][j];
            if (bias) v += bias[c];
            C[(size_t)r * N + c] = v;
        }
    }
}

// ---------------- weight transpose + merged-residual split ----------------
__global__ void tsplit_kernel(const float* __restrict__ W, __half* __restrict__ b1,
                              __half* __restrict__ b2, int K, int N)
{
    __shared__ float t[32][33];
    int k0 = blockIdx.y * 32, n0 = blockIdx.x * 32;
    int tx = threadIdx.x, ty = threadIdx.y;
#pragma unroll
    for (int r = 0; r < 4; r++) {
        int k = k0 + ty + r * 8;
        t[ty + r * 8][tx] = (k < K && n0 + tx < N) ? W[(size_t)k * N + n0 + tx] : 0.f;
    }
    __syncthreads();
#pragma unroll
    for (int r = 0; r < 4; r++) {
        int n = n0 + ty + r * 8, k = k0 + tx;
        if (n < N && k < K) {
            __half h1, h2;
            splitB(t[tx][ty + r * 8], h1, h2);
            b1[(size_t)n * K + k] = h1;
            b2[(size_t)n * K + k] = h2;
        }
    }
}

__global__ void assemble_conv_wT(const float* __restrict__ w1, const float* __restrict__ w2,
                                 const float* __restrict__ w4, const float* __restrict__ b1c,
                                 const float* __restrict__ b2c, const float* __restrict__ b4c,
                                 __half* __restrict__ o1, __half* __restrict__ o2,
                                 float* __restrict__ cb)
{
    int idx = blockIdx.x * blockDim.x + threadIdx.x;
    if (idx < EE) cb[idx] = (idx < 256) ? b1c[idx] : (idx < 512 ? b2c[idx - 256] : b4c[idx - 512]);
    if (idx >= 768 * 1024) return;
    int n = idx / 1024, k = idx % 1024;
    int i = k % 256, d = k / 256;
    float v = 0.f;
    if (n < 256)      { if (d == 1) v = w1[n * 256 + i]; }
    else if (n < 512) { int oo = n - 256; int j = d - 1; if (j == 0 || j == 1) v = w2[oo * 512 + i * 2 + j]; }
    else              { int oo = n - 512; v = w4[oo * 1024 + i * 4 + d]; }
    __half h1, h2;
    splitB(v, h1, h2);
    o1[idx] = h1;
    o2[idx] = h2;
}

__global__ void assemble_ssm_wT(const float* __restrict__ w, __half* __restrict__ o1,
                                __half* __restrict__ o2)
{
    int idx = blockIdx.x * blockDim.x + threadIdx.x;
    if (idx >= 768 * 2304) return;
    int n = idx / 2304, k = idx % 2304;
    int i = k % 768, j = k / 768;
    __half h1, h2;
    splitB(w[(size_t)n * 2304 + i * 3 + j], h1, h2);
    o1[idx] = h1;
    o2[idx] = h2;
}

// ---------------- small kernels ----------------
__global__ void init_c48_kernel(float* __restrict__ C48) {
    for (int i = threadIdx.x; i < FF * TP; i += blockDim.x) {
        int k = i / TP, t = i % TP;
        int m = (k * t) % TP;
        C48[i] = cospif(2.0f * (float)m / (float)TP);
    }
}

// split input x -> fp16 pair
__global__ void split_x_kernel(const float* __restrict__ x, __half* __restrict__ x1,
                               __half* __restrict__ x2, size_t total)
{
    size_t idx = (size_t)blockIdx.x * blockDim.x + threadIdx.x;
    if (idx >= total) return;
    __half a, b;
    splitS(x[idx], a, b);
    x1[idx] = a;
    x2[idx] = b;
}

// h1 -> hpe = h1 + pe[t] (f32), sf split fp16
__global__ void pe_diff_kernel(const float* __restrict__ h1, const float* __restrict__ pe,
                               float* __restrict__ hpe, __half* __restrict__ sf1,
                               __half* __restrict__ sf2)
{
    size_t idx = (size_t)blockIdx.x * blockDim.x + threadIdx.x;
    const size_t total = N_BT * HH;
    if (idx >= total) return;
    int c = (int)(idx % HH);
    size_t r = idx / HH;
    int t = (int)(r % TT);
    float cur = h1[idx] + pe[(size_t)t * HH + c];
    hpe[idx] = cur;
    float prev = (t == 0) ? cur : (h1[idx - HH] + pe[(size_t)(t - 1) * HH + c]);
    __half a, b;
    splitS(cur - prev, a, b);
    sf1[idx] = a;
    sf2[idx] = b;
}

__global__ void __launch_bounds__(256) dft48_kernel(const float* __restrict__ hp,
                                                    float* __restrict__ out,
                                                    const float* __restrict__ C48)
{
    __shared__ float sC[FF * TP];
    int b = blockIdx.x;
    for (int i = threadIdx.x; i < FF * TP; i += 256) sC[i] = C48[i];
    float r[TP];
    const float* base = hp + (size_t)b * TP * HH + threadIdx.x;
#pragma unroll
    for (int t = 0; t < TP; t++) r[t] = base[(size_t)t * HH];
    __syncthreads();
    float* ob = out + (size_t)b * FF * HH + threadIdx.x;
    for (int k = 0; k < FF; k++) {
        float acc = 0.f;
#pragma unroll
        for (int t = 0; t < TP; t++) acc = fmaf(r[t], sC[k * TP + t], acc);
        ob[(size_t)k * HH] = acc;
    }
}

__global__ void im2col_conv(const float* __restrict__ f, __half* __restrict__ c1,
                            __half* __restrict__ c2)
{
    size_t idx = (size_t)blockIdx.x * blockDim.x + threadIdx.x;
    const size_t total = N_BF * 1024;
    if (idx >= total) return;
    int kk = (int)(idx % 1024);
    size_t row = idx / 1024;
    int i = kk % 256, d = kk / 256;
    int fq = (int)(row % FF);
    size_t b = row / FF;
    int src = fq + d - 1;
    float v = (src >= 0 && src < FF) ? f[((size_t)b * FF + src) * HH + i] : 0.f;
    __half a, bb;
    splitS(v, a, bb);
    c1[idx] = a;
    c2[idx] = bb;
}

__global__ void im2col_ssm(const float* __restrict__ h, __half* __restrict__ c1,
                           __half* __restrict__ c2)
{
    size_t idx = (size_t)blockIdx.x * blockDim.x + threadIdx.x;
    const size_t total = N_BF * 2304;
    if (idx >= total) return;
    int kk = (int)(idx % 2304);
    size_t row = idx / 2304;
    int i = kk % EE, j = kk / EE;
    int fq = (int)(row % FF);
    size_t b = row / FF;
    int src = fq + j - 1;
    float v = (src >= 0 && src < FF) ? h[((size_t)b * FF + src) * EE + i] : 0.f;
    __half a, bb;
    splitS(v, a, bb);
    c1[idx] = a;
    c2[idx] = bb;
}

// layernorm; output written as split fp16
__global__ void __launch_bounds__(256) ln_kernel(const float* __restrict__ x,
                                                 const float* __restrict__ g,
                                                 const float* __restrict__ bta,
                                                 __half* __restrict__ y1,
                                                 __half* __restrict__ y2, int C)
{
    int row = blockIdx.x;
    const float* xr = x + (size_t)row * C;
    float s = 0.f, q = 0.f;
    for (int c = threadIdx.x; c < C; c += 256) {
        float v = xr[c];
        s += v; q += v * v;
    }
#pragma unroll
    for (int o = 16; o; o >>= 1) {
        s += __shfl_xor_sync(~0u, s, o);
        q += __shfl_xor_sync(~0u, q, o);
    }
    __shared__ float ss[8], sq[8];
    int w = threadIdx.x >> 5, l = threadIdx.x & 31;
    if (l == 0) { ss[w] = s; sq[w] = q; }
    __syncthreads();
    if (threadIdx.x == 0) {
        float ts = 0.f, tq = 0.f;
        for (int i = 0; i < 8; i++) { ts += ss[i]; tq += sq[i]; }
        ss[0] = ts; sq[0] = tq;
    }
    __syncthreads();
    float mean = ss[0] / C;
    float var = sq[0] / C - mean * mean;
    float inv = rsqrtf(var + 1e-5f);
    for (int c = threadIdx.x; c < C; c += 256) {
        float v = (xr[c] - mean) * inv * g[c] + bta[c];
        __half a, b;
        splitS(v, a, b);
        y1[(size_t)row * C + c] = a;
        y2[(size_t)row * C + c] = b;
    }
}

// final layernorm (f32 in+add -> f32 out, in-place safe)
__global__ void __launch_bounds__(256) ln_f32_kernel(const float* __restrict__ x,
                                                     const float* __restrict__ add,
                                                     const float* __restrict__ g,
                                                     const float* __restrict__ bta,
                                                     float* __restrict__ y, int C)
{
    int row = blockIdx.x;
    const float* xr = x + (size_t)row * C;
    const float* ar = add + (size_t)row * C;
    float s = 0.f, q = 0.f;
    for (int c = threadIdx.x; c < C; c += 256) {
        float v = xr[c] + ar[c];
        s += v; q += v * v;
    }
#pragma unroll
    for (int o = 16; o; o >>= 1) {
        s += __shfl_xor_sync(~0u, s, o);
        q += __shfl_xor_sync(~0u, q, o);
    }
    __shared__ float ss[8], sq[8];
    int w = threadIdx.x >> 5, l = threadIdx.x & 31;
    if (l == 0) { ss[w] = s; sq[w] = q; }
    __syncthreads();
    if (threadIdx.x == 0) {
        float ts = 0.f, tq = 0.f;
        for (int i = 0; i < 8; i++) { ts += ss[i]; tq += sq[i]; }
        ss[0] = ts; sq[0] = tq;
    }
    __syncthreads();
    float mean = ss[0] / C;
    float var = sq[0] / C - mean * mean;
    float inv = rsqrtf(var + 1e-5f);
    for (int c = threadIdx.x; c < C; c += 256) {
        float v = xr[c] + ar[c];
        y[(size_t)row * C + c] = (v - mean) * inv * g[c] + bta[c];
    }
}

__global__ void __launch_bounds__(256) attn_kernel(const float* __restrict__ qkv,
                                                   __half* __restrict__ o1,
                                                   __half* __restrict__ o2)
{
    __shared__ float sq_[FF][DHH], sk_[FF][DHH], sv_[FF][DHH];
    __shared__ float G[FF][FF];
    __shared__ float ctab[FF];
    __shared__ float sa[NF2];
    __shared__ float kt[FF];
    int bh = blockIdx.x;
    int b = bh >> 3, hh = bh & 7;
    int tid = threadIdx.x;
    const float* base = qkv + ((size_t)b * FF) * (3 * EE) + hh * DHH;
    for (int idx = tid; idx < FF * DHH; idx += 256) {
        int t = idx / DHH, d = idx % DHH;
        size_t off = (size_t)t * (3 * EE) + d;
        sq_[t][d] = base[off];
        sk_[t][d] = base[off + EE];
        sv_[t][d] = base[off + 2 * EE];
    }
    if (tid < FF) ctab[tid] = cospif(2.0f * (float)tid / 25.0f);
    __syncthreads();
    for (int e = tid; e < FF * FF; e += 256) {
        int t = e / FF, s2 = e % FF;
        float acc = 0.f;
#pragma unroll 8
        for (int d = 0; d < DHH; d++) acc = fmaf(sq_[t][d], sk_[s2][d], acc);
        G[t][s2] = acc;
    }
    __syncthreads();
    if (tid < NF2) {
        float acc = 0.f;
        for (int t = 0; t < FF; t++)
            for (int s2 = 0; s2 < FF; s2++)
                acc = fmaf(G[t][s2], ctab[(tid * (t - s2 + FF)) % FF], acc);
        sa[tid] = acc * 0.10206207261596575f;
    }
    __syncthreads();
    if (tid == 0) {
        float mx = sa[0];
        for (int f = 1; f < NF2; f++) mx = fmaxf(mx, sa[f]);
        float e_[NF2], sum = 0.f;
        for (int f = 0; f < NF2; f++) { e_[f] = expf(sa[f] - mx); sum += e_[f]; }
        float inv = 1.0f / sum;
        for (int f = 0; f < NF2; f++) sa[f] = e_[f] * inv;
    }
    __syncthreads();
    if (tid < FF) {
        float acc = sa[0];
        for (int f = 1; f < NF2; f++) acc = fmaf(2.0f * sa[f], ctab[(f * tid) % FF], acc);
        kt[tid] = acc * 0.04f;
    }
    __syncthreads();
    size_t obase = ((size_t)b * FF) * EE + hh * DHH;
    for (int idx = tid; idx < FF * DHH; idx += 256) {
        int t = idx / DHH, d = idx % DHH;
        float acc = 0.f;
#pragma unroll
        for (int s2 = 0; s2 < FF; s2++)
            acc = fmaf(kt[(t - s2 + FF) % FF], sv_[s2][d], acc);
        __half a, bb;
        splitS(acc, a, bb);
        o1[obase + (size_t)t * EE + d] = a;
        o2[obase + (size_t)t * EE + d] = bb;
    }
}

__global__ void mean_kernel(const float* __restrict__ h, float* __restrict__ hm) {
    int b = blockIdx.x;
    int c = threadIdx.x;
    float acc = 0.f;
#pragma unroll
    for (int f = 0; f < FF; f++) acc += h[((size_t)b * FF + f) * EE + c];
    hm[(size_t)b * EE + c] = acc * 0.04f;
}

// ---------------- host helpers ----------------
static inline void gemm_f32out(const __half* a1, const __half* a2,
                               const __half* b1, const __half* b2, float* C,
                               int M, int N, int K, const float* bias, const float* res, int act)
{
    dim3 grid(N / 128, M / 128);
    gemm_mma_kernel<<<grid, 256, G6_TOTAL>>>(a1, a2, b1, b2, C, nullptr, nullptr,
                                             M, N, K, bias, res, act);
}
static inline void gemm_splitout(const __half* a1, const __half* a2,
                                 const __half* b1, const __half* b2,
                                 __half* C1, __half* C2,
                                 int M, int N, int K, const float* bias, const float* res, int act)
{
    dim3 grid(N / 128, M / 128);
    gemm_mma_kernel<<<grid, 256, G6_TOTAL>>>(a1, a2, b1, b2, nullptr, C1, C2,
                                             M, N, K, bias, res, act);
}
static inline void tsplit(const float* W, __half* b1, __half* b2, int K, int N) {
    dim3 grid((N + 31) / 32, (K + 31) / 32);
    tsplit_kernel<<<grid, dim3(32, 8)>>>(W, b1, b2, K, N);
}

extern "C" void kernel_launch(void* const* d_in, const int* in_sizes, int n_in,
                              void* d_out, int out_size)
{
    const float* x       = (const float*)d_in[0];
    const float* W_in    = (const float*)d_in[1];
    const float* b_in    = (const float*)d_in[2];
    const float* pe      = (const float*)d_in[3];
    const float* W_shape = (const float*)d_in[4];
    const float* b_shape = (const float*)d_in[5];
    const float* W_patch = (const float*)d_in[6];
    const float* b_patch = (const float*)d_in[7];
    const float* cw1     = (const float*)d_in[8];
    const float* cb1     = (const float*)d_in[9];
    const float* cw2     = (const float*)d_in[10];
    const float* cb2     = (const float*)d_in[11];
    const float* cw4     = (const float*)d_in[12];
    const float* cb4     = (const float*)d_in[13];
    const float* ln1g    = (const float*)d_in[14];
    const float* ln1b    = (const float*)d_in[15];
    const float* Wqkv    = (const float*)d_in[16];
    const float* Wo      = (const float*)d_in[17];
    const float* bo      = (const float*)d_in[18];
    const float* ln2g    = (const float*)d_in[19];
    const float* ln2b    = (const float*)d_in[20];
    const float* Wf1     = (const float*)d_in[21];
    const float* bf1     = (const float*)d_in[22];
    const float* Wf2     = (const float*)d_in[23];
    const float* bf2     = (const float*)d_in[24];
    const float* ssmw    = (const float*)d_in[25];
    const float* ssmb    = (const float*)d_in[26];
    const float* ssmg    = (const float*)d_in[27];
    const float* ssmbn   = (const float*)d_in[28];
    const float* W_out   = (const float*)d_in[29];
    const float* b_out   = (const float*)d_in[30];
    float* out = (float*)d_out;

    cudaFuncSetAttribute(gemm_mma_kernel, cudaFuncAttributeMaxDynamicSharedMemorySize, G6_TOTAL);

    float *h1, *hpe, *hp, *fr, *C48, *cb, *h, *qkv, *s, *hm;
    cudaGetSymbolAddress((void**)&h1,  g_h1);
    cudaGetSymbolAddress((void**)&hpe, g_hpe);
    cudaGetSymbolAddress((void**)&hp,  g_hp);
    cudaGetSymbolAddress((void**)&fr,  g_fr);
    cudaGetSymbolAddress((void**)&C48, g_C48);
    cudaGetSymbolAddress((void**)&cb,  g_cb);
    cudaGetSymbolAddress((void**)&h,   g_h);
    cudaGetSymbolAddress((void**)&qkv, g_qkv);
    cudaGetSymbolAddress((void**)&s,   g_s);
    cudaGetSymbolAddress((void**)&hm,  g_hm);

    __half *xs1, *xs2, *sf1, *sf2, *h21, *h22, *col1, *col2, *y1, *y2, *att1, *att2, *mid1, *mid2;
    cudaGetSymbolAddress((void**)&xs1,  g_xs1);  cudaGetSymbolAddress((void**)&xs2,  g_xs2);
    cudaGetSymbolAddress((void**)&sf1,  g_sf1);  cudaGetSymbolAddress((void**)&sf2,  g_sf2);
    cudaGetSymbolAddress((void**)&h21,  g_h21);  cudaGetSymbolAddress((void**)&h22,  g_h22);
    cudaGetSymbolAddress((void**)&col1, g_col1); cudaGetSymbolAddress((void**)&col2, g_col2);
    cudaGetSymbolAddress((void**)&y1,   g_y1);   cudaGetSymbolAddress((void**)&y2,   g_y2);
    cudaGetSymbolAddress((void**)&att1, g_att1); cudaGetSymbolAddress((void**)&att2, g_att2);
    cudaGetSymbolAddress((void**)&mid1, g_mid1); cudaGetSymbolAddress((void**)&mid2, g_mid2);

    __half *tWin_h, *tWin_2, *tWsh_h, *tWsh_2, *tWpa_h, *tWpa_2, *tWc_h, *tWc_2;
    __half *tWqkv_h, *tWqkv_2, *tWo_h, *tWo_2, *tWf1_h, *tWf1_2, *tWf2_h, *tWf2_2, *tWc2_h, *tWc2_2;
    cudaGetSymbolAddress((void**)&tWin_h,  g_tWin_h);  cudaGetSymbolAddress((void**)&tWin_2,  g_tWin_2);
    cudaGetSymbolAddress((void**)&tWsh_h,  g_tWsh_h);  cudaGetSymbolAddress((void**)&tWsh_2,  g_tWsh_2);
    cudaGetSymbolAddress((void**)&tWpa_h,  g_tWpa_h);  cudaGetSymbolAddress((void**)&tWpa_2,  g_tWpa_2);
    cudaGetSymbolAddress((void**)&tWc_h,   g_tWc_h);   cudaGetSymbolAddress((void**)&tWc_2,   g_tWc_2);
    cudaGetSymbolAddress((void**)&tWqkv_h, g_tWqkv_h); cudaGetSymbolAddress((void**)&tWqkv_2, g_tWqkv_2);
    cudaGetSymbolAddress((void**)&tWo_h,   g_tWo_h);   cudaGetSymbolAddress((void**)&tWo_2,   g_tWo_2);
    cudaGetSymbolAddress((void**)&tWf1_h,  g_tWf1_h);  cudaGetSymbolAddress((void**)&tWf1_2,  g_tWf1_2);
    cudaGetSymbolAddress((void**)&tWf2_h,  g_tWf2_h);  cudaGetSymbolAddress((void**)&tWf2_2,  g_tWf2_2);
    cudaGetSymbolAddress((void**)&tWc2_h,  g_tWc2_h);  cudaGetSymbolAddress((void**)&tWc2_2,  g_tWc2_2);

    // tables + weight prep
    init_c48_kernel<<<1, 256>>>(C48);
    tsplit(W_in,    tWin_h, tWin_2,  64, 256);
    tsplit(W_shape, tWsh_h, tWsh_2, 256, 256);
    tsplit(W_patch, tWpa_h, tWpa_2, 512, 256);
    assemble_conv_wT<<<(768 * 1024 + 255) / 256, 256>>>(cw1, cw2, cw4, cb1, cb2, cb4, tWc_h, tWc_2, cb);
    for (int i = 0; i < LL; i++) {
        tsplit(Wqkv + (size_t)i * EE * 3 * EE, tWqkv_h + (size_t)i * 3 * EE * EE, tWqkv_2 + (size_t)i * 3 * EE * EE, EE, 3 * EE);
        tsplit(Wo   + (size_t)i * EE * EE,     tWo_h   + (size_t)i * EE * EE,     tWo_2   + (size_t)i * EE * EE,     EE, EE);
        tsplit(Wf1  + (size_t)i * EE * 4 * EE, tWf1_h  + (size_t)i * 4 * EE * EE, tWf1_2  + (size_t)i * 4 * EE * EE, EE, 4 * EE);
        tsplit(Wf2  + (size_t)i * 4 * EE * EE, tWf2_h  + (size_t)i * EE * 4 * EE, tWf2_2  + (size_t)i * EE * 4 * EE, 4 * EE, EE);
    }
    assemble_ssm_wT<<<(768 * 2304 + 255) / 256, 256>>>(ssmw, tWc2_h, tWc2_2);

    // embedding chain
    {
        size_t tot = N_BT * DIN;
        split_x_kernel<<<(unsigned)((tot + 255) / 256), 256>>>(x, xs1, xs2, tot);
    }
    gemm_f32out(xs1, xs2, tWin_h, tWin_2, h1, BB * TT, HH, DIN, b_in, nullptr, 0);
    {
        size_t tot = N_BT * HH;
        pe_diff_kernel<<<(unsigned)((tot + 255) / 256), 256>>>(h1, pe, hpe, sf1, sf2);
    }
    gemm_splitout(sf1, sf2, tWsh_h, tWsh_2, h21, h22, BB * TT, HH, HH, b_shape, hpe, 0);
    // patch: view h2 split as [B*48, 512]
    gemm_f32out(h21, h22, tWpa_h, tWpa_2, hp, BB * TP, HH, 2 * HH, b_patch, nullptr, 0);

    dft48_kernel<<<BB, 256>>>(hp, fr, C48);

    {
        size_t tot = N_BF * 1024;
        im2col_conv<<<(unsigned)((tot + 255) / 256), 256>>>(fr, col1, col2);
    }
    gemm_f32out(col1, col2, tWc_h, tWc_2, h, (int)N_BF, EE, 1024, cb, nullptr, 0);

    // transformer layers
    for (int i = 0; i < LL; i++) {
        ln_kernel<<<(unsigned)N_BF, 256>>>(h, ln1g + (size_t)i * EE, ln1b + (size_t)i * EE, y1, y2, EE);
        gemm_f32out(y1, y2, tWqkv_h + (size_t)i * 3 * EE * EE, tWqkv_2 + (size_t)i * 3 * EE * EE,
                    qkv, (int)N_BF, 3 * EE, EE, nullptr, nullptr, 0);
        attn_kernel<<<BB * NHEADS, 256>>>(qkv, att1, att2);
        gemm_f32out(att1, att2, tWo_h + (size_t)i * EE * EE, tWo_2 + (size_t)i * EE * EE,
                    h, (int)N_BF, EE, EE, bo + (size_t)i * EE, h, 0);
        ln_kernel<<<(unsigned)N_BF, 256>>>(h, ln2g + (size_t)i * EE, ln2b + (size_t)i * EE, y1, y2, EE);
        gemm_splitout(y1, y2, tWf1_h + (size_t)i * 4 * EE * EE, tWf1_2 + (size_t)i * 4 * EE * EE,
                      mid1, mid2, (int)N_BF, 4 * EE, EE, bf1 + (size_t)i * 4 * EE, nullptr, 1);
        gemm_f32out(mid1, mid2, tWf2_h + (size_t)i * EE * 4 * EE, tWf2_2 + (size_t)i * EE * 4 * EE,
                    h, (int)N_BF, EE, 4 * EE, bf2 + (size_t)i * EE, h, 0);
    }

    // SSM conv + LN
    {
        size_t tot = N_BF * 2304;
        im2col_ssm<<<(unsigned)((tot + 255) / 256), 256>>>(h, col1, col2);
    }
    gemm_f32out(col1, col2, tWc2_h, tWc2_2, s, (int)N_BF, EE, 3 * EE, ssmb, nullptr, 0);
    ln_f32_kernel<<<(unsigned)N_BF, 256>>>(h, s, ssmg, ssmbn, h, EE);

    // mean + classifier (small, f32 path)
    mean_kernel<<<BB, EE>>>(h, hm);
    {
        dim3 grid((NCC + 127) / 128, (BB + 127) / 128);
        sgemm_kernel<<<grid, 256>>>(hm, W_out, out, BB, NCC, EE, b_out);
    }
}